// round 8
// baseline (speedup 1.0000x reference)
#include <cuda_runtime.h>
#include <cuda_bf16.h>
#include <math.h>
#include <stdint.h>

#define BB 64
#define SS 256
#define DD 512
#define HH 8
#define DH 64
#define DFF 2048
#define VV 128
#define LL 6
#define M_TOK (BB*SS)

// ---------------------------------------------------------------------------
// Scratch
// ---------------------------------------------------------------------------
__device__ float g_x  [M_TOK*DD];
__device__ float g_sub[M_TOK*DD];
__device__ float g_mem[BB*DD];
__device__ float g_cav[LL*BB*DD];
__device__ float g_ca [LL*BB*DD];

__device__ __nv_bfloat16 g_ahi[(size_t)M_TOK*DD];
__device__ __nv_bfloat16 g_alo[(size_t)M_TOK*DD];
__device__ __nv_bfloat16 g_qhi[(size_t)M_TOK*3*DD];
__device__ __nv_bfloat16 g_qlo[(size_t)M_TOK*3*DD];
__device__ __nv_bfloat16 g_fhi[(size_t)M_TOK*DFF];
__device__ __nv_bfloat16 g_flo[(size_t)M_TOK*DFF];

#define O_SAW  0u
#define O_SAOW 4718592u
#define O_FF1  6291456u
#define O_FF2  12582912u
#define O_FC   18874368u
#define WPOOL_E 18940032u
__device__ __nv_bfloat16 g_whi[WPOOL_E];
__device__ __nv_bfloat16 g_wlo[WPOOL_E];

// ---------------------------------------------------------------------------
// Helpers
// ---------------------------------------------------------------------------
__device__ __forceinline__ uint32_t smem_u32(const void* p) {
    uint32_t a;
    asm("{ .reg .u64 t; cvta.to.shared.u64 t, %1; cvt.u32.u64 %0, t; }"
        : "=r"(a) : "l"(p));
    return a;
}
__device__ __forceinline__ void cp_async16(uint32_t dst, const void* src) {
    asm volatile("cp.async.cg.shared.global [%0], [%1], 16;"
                 :: "r"(dst), "l"(src));
}
#define CP_COMMIT() asm volatile("cp.async.commit_group;" ::: "memory")
#define CP_WAIT1()  asm volatile("cp.async.wait_group 1;" ::: "memory")
#define CP_WAIT0()  asm volatile("cp.async.wait_group 0;" ::: "memory")

__device__ __forceinline__ void ldm_x4(uint32_t* r, uint32_t addr) {
    asm volatile("ldmatrix.sync.aligned.m8n8.x4.shared.b16 {%0,%1,%2,%3}, [%4];"
                 : "=r"(r[0]), "=r"(r[1]), "=r"(r[2]), "=r"(r[3]) : "r"(addr));
}
__device__ __forceinline__ void ldm_x4t(uint32_t* r, uint32_t addr) {
    asm volatile("ldmatrix.sync.aligned.m8n8.x4.trans.shared.b16 {%0,%1,%2,%3}, [%4];"
                 : "=r"(r[0]), "=r"(r[1]), "=r"(r[2]), "=r"(r[3]) : "r"(addr));
}
__device__ __forceinline__ void mma_bf16(float* c, const uint32_t* a,
                                         const uint32_t* b) {
    asm volatile(
        "mma.sync.aligned.m16n8k16.row.col.f32.bf16.bf16.f32 "
        "{%0,%1,%2,%3}, {%4,%5,%6,%7}, {%8,%9}, {%0,%1,%2,%3};"
        : "+f"(c[0]), "+f"(c[1]), "+f"(c[2]), "+f"(c[3])
        : "r"(a[0]), "r"(a[1]), "r"(a[2]), "r"(a[3]), "r"(b[0]), "r"(b[1]));
}
__device__ __forceinline__ uint32_t pack2bf(float a, float b) {
    __nv_bfloat162 t = __floats2bfloat162_rn(a, b);
    return *(uint32_t*)&t;
}
__device__ __forceinline__ void split2(float a, float b, uint32_t& hi, uint32_t& lo) {
    __nv_bfloat16 ha = __float2bfloat16_rn(a);
    __nv_bfloat16 hb = __float2bfloat16_rn(b);
    hi = pack2bf(__bfloat162float(ha), __bfloat162float(hb));
    lo = pack2bf(a - __bfloat162float(ha), b - __bfloat162float(hb));
}

// ---------------------------------------------------------------------------
// Embedding
// ---------------------------------------------------------------------------
__global__ void embed_kernel(const int* __restrict__ tgt,
                             const float* __restrict__ emb,
                             const float* __restrict__ pos,
                             float* __restrict__ x,
                             __nv_bfloat16* __restrict__ xhi,
                             __nv_bfloat16* __restrict__ xlo) {
    int row = blockIdx.x;
    int d4  = threadIdx.x;
    int tok = tgt[row];
    int s   = row & (SS - 1);
    float4 e = ((const float4*)(emb + (size_t)tok*DD))[d4];
    float4 p = ((const float4*)(pos + (size_t)s*DD))[d4];
    float4 v = make_float4(e.x+p.x, e.y+p.y, e.z+p.z, e.w+p.w);
    ((float4*)(x + (size_t)row*DD))[d4] = v;
    uint32_t h0, l0, h1, l1;
    split2(v.x, v.y, h0, l0);
    split2(v.z, v.w, h1, l1);
    ((uint2*)(xhi + (size_t)row*DD))[d4] = make_uint2(h0, h1);
    ((uint2*)(xlo + (size_t)row*DD))[d4] = make_uint2(l0, l1);
}

// ---------------------------------------------------------------------------
// fp32 -> bf16 hi/lo (weights)
// ---------------------------------------------------------------------------
__global__ void __launch_bounds__(256)
conv_pair(const float* __restrict__ src, __nv_bfloat16* __restrict__ hi,
          __nv_bfloat16* __restrict__ lo) {
    size_t i = (size_t)blockIdx.x * 256 + threadIdx.x;
    float4 v = ((const float4*)src)[i];
    uint32_t h0, l0, h1, l1;
    split2(v.x, v.y, h0, l0);
    split2(v.z, v.w, h1, l1);
    ((uint2*)hi)[i] = make_uint2(h0, h1);
    ((uint2*)lo)[i] = make_uint2(l0, l1);
}

// ---------------------------------------------------------------------------
// HMMA bf16x3 GEMM, 256(M)x128(N) CTA tile, 512 threads (16 warps, 4x4),
// warp tile 64x32, 2-stage cp.async pipeline.
// mode 0: fp32 C. mode 1: bf16 hi/lo + opt ReLU.
// Stage: Ahi 32K | Alo 32K | Bhi 16K | Blo 16K = 96 KB.
// ---------------------------------------------------------------------------
#define G2STAGE 98304
#define G2SMEM  (2*G2STAGE)

__global__ void __launch_bounds__(512, 1)
gemm_hmma2(const __nv_bfloat16* __restrict__ Ahi,
           const __nv_bfloat16* __restrict__ Alo,
           const __nv_bfloat16* __restrict__ Bhi,
           const __nv_bfloat16* __restrict__ Blo,
           const float* __restrict__ bias, float* __restrict__ C,
           __nv_bfloat16* __restrict__ Chi, __nv_bfloat16* __restrict__ Clo,
           int N, int K, int relu, int mode) {
    extern __shared__ char smg[];
    const uint32_t sa = smem_u32(smg);
    const int tid = threadIdx.x;
    const int wid = tid >> 5, lane = tid & 31;
    const int wM = wid >> 2, wN = wid & 3;       // 4 x 4 warps
    const int bm = blockIdx.y * 256;
    const int bn = blockIdx.x * 128;
    const int kc = K >> 6;

    float acc[4][4][4];
    #pragma unroll
    for (int i = 0; i < 4; i++)
        #pragma unroll
        for (int j = 0; j < 4; j++)
            #pragma unroll
            for (int e = 0; e < 4; e++) acc[i][j][e] = 0.f;

    auto load_stage = [&](int s, int kk) {
        uint32_t stg = sa + s*G2STAGE;
        #pragma unroll
        for (int i = tid; i < 4096; i += 512) {   // A hi+lo: 256 rows x 8 cgrp
            int pool = i >> 11, r = (i >> 3) & 255, c = i & 7;
            const __nv_bfloat16* g =
                (pool ? Alo : Ahi) + (size_t)(bm + r)*K + kk*64 + c*8;
            cp_async16(stg + pool*32768 + r*128 + ((c*16) ^ ((r & 7) << 4)), g);
        }
        #pragma unroll
        for (int i = tid; i < 2048; i += 512) {   // B hi+lo: 128 rows
            int pool = i >> 10, r = (i >> 3) & 127, c = i & 7;
            const __nv_bfloat16* g =
                (pool ? Blo : Bhi) + (size_t)(bn + r)*K + kk*64 + c*8;
            cp_async16(stg + 65536 + pool*16384 + r*128 +
                       ((c*16) ^ ((r & 7) << 4)), g);
        }
    };

    load_stage(0, 0); CP_COMMIT();
    load_stage(1, 1); CP_COMMIT();

    const int laneA_row = lane & 15;
    const int laneA_b   = (lane >> 4) << 4;
    const int laneB_row = ((lane >> 4) << 3) + (lane & 7);
    const int laneB_b   = ((lane >> 3) & 1) << 4;

    for (int ch = 0; ch < kc; ch++) {
        CP_WAIT1();
        __syncthreads();
        uint32_t stg = sa + (ch & 1)*G2STAGE;

        #pragma unroll
        for (int ks = 0; ks < 4; ks++) {
            uint32_t ah[4][4], al[4][4];
            #pragma unroll
            for (int mf = 0; mf < 4; mf++) {
                int r = wM*64 + mf*16 + laneA_row;
                uint32_t off = r*128 + (((uint32_t)(ks*32 + laneA_b)) ^ ((r & 7) << 4));
                ldm_x4(ah[mf], stg + off);
                ldm_x4(al[mf], stg + 32768 + off);
            }
            #pragma unroll
            for (int nf2 = 0; nf2 < 2; nf2++) {
                uint32_t bh4[4], bl4[4];
                int r = wN*32 + nf2*16 + laneB_row;
                uint32_t off = r*128 + (((uint32_t)(ks*32 + laneB_b)) ^ ((r & 7) << 4));
                ldm_x4(bh4, stg + 65536 + off);
                ldm_x4(bl4, stg + 81920 + off);
                #pragma unroll
                for (int mf = 0; mf < 4; mf++)
                    #pragma unroll
                    for (int j = 0; j < 2; j++) {
                        float* a = acc[mf][nf2*2 + j];
                        mma_bf16(a, ah[mf], &bh4[j*2]);
                        mma_bf16(a, ah[mf], &bl4[j*2]);
                        mma_bf16(a, al[mf], &bh4[j*2]);
                    }
            }
        }
        __syncthreads();
        if (ch + 2 < kc) load_stage(ch & 1, ch + 2);
        CP_COMMIT();
    }

    const int gid = lane >> 2, tig = lane & 3;
    #pragma unroll
    for (int mf = 0; mf < 4; mf++) {
        int r0 = bm + wM*64 + mf*16 + gid;
        #pragma unroll
        for (int nf = 0; nf < 4; nf++) {
            int col = bn + wN*32 + nf*8 + tig*2;
            float bx = __ldg(bias + col), by = __ldg(bias + col + 1);
            float v0x = acc[mf][nf][0] + bx, v0y = acc[mf][nf][1] + by;
            float v1x = acc[mf][nf][2] + bx, v1y = acc[mf][nf][3] + by;
            if (relu) {
                v0x = fmaxf(v0x, 0.f); v0y = fmaxf(v0y, 0.f);
                v1x = fmaxf(v1x, 0.f); v1y = fmaxf(v1y, 0.f);
            }
            if (mode == 0) {
                *(float2*)(C + (size_t)r0*N + col)       = make_float2(v0x, v0y);
                *(float2*)(C + (size_t)(r0 + 8)*N + col) = make_float2(v1x, v1y);
            } else {
                uint32_t h, l;
                size_t i0 = (size_t)r0*N + col, i1 = (size_t)(r0 + 8)*N + col;
                split2(v0x, v0y, h, l);
                *(uint32_t*)(Chi + i0) = h; *(uint32_t*)(Clo + i0) = l;
                split2(v1x, v1y, h, l);
                *(uint32_t*)(Chi + i1) = h; *(uint32_t*)(Clo + i1) = l;
            }
        }
    }
}

// ---------------------------------------------------------------------------
// HMMA causal attention (unchanged)
// ---------------------------------------------------------------------------
#define OQH 0
#define OQL 8192
#define OKH 16384
#define OKL 49152
#define OVH 81920
#define OVL 114688
#define OPH 147456
#define OPL 180224
#define ORED 212992
#define ATT_SMEM (ORED + 1024)

__global__ void __launch_bounds__(256, 1)
attn_hmma(const __nv_bfloat16* __restrict__ qhi,
          const __nv_bfloat16* __restrict__ qlo,
          __nv_bfloat16* __restrict__ ohi,
          __nv_bfloat16* __restrict__ olo) {
    extern __shared__ char smg[];
    const uint32_t sa = smem_u32(smg);
    const int tid = threadIdx.x;
    const int wid = tid >> 5, lane = tid & 31;
    const int wM = wid >> 1, wN = wid & 1;
    const int gid = lane >> 2, tig = lane & 3;

    const int bid = blockIdx.x;
    const int qb = bid & 3;
    const int h  = (bid >> 2) & 7;
    const int b  = bid >> 5;
    const int krows = (qb + 1) * 64;

    auto load_tile = [&](const __nv_bfloat16* g, uint32_t sbase, int rows) {
        for (int i = tid; i < rows*8; i += 256) {
            int r = i >> 3, c = i & 7;
            cp_async16(sa + sbase + r*128 + ((c*16) ^ ((r & 7) << 4)),
                       g + (size_t)r*1536 + c*8);
        }
    };
    const size_t qbase = (size_t)(b*SS + qb*64)*1536 + h*DH;
    const size_t kbase = (size_t)(b*SS)*1536 + DD + h*DH;
    const size_t vbase = (size_t)(b*SS)*1536 + 2*DD + h*DH;
    load_tile(qhi + qbase, OQH, 64);
    load_tile(qlo + qbase, OQL, 64);
    load_tile(qhi + kbase, OKH, krows);
    load_tile(qlo + kbase, OKL, krows);
    CP_COMMIT();
    load_tile(qhi + vbase, OVH, krows);
    load_tile(qlo + vbase, OVL, krows);
    CP_COMMIT();
    CP_WAIT1();
    __syncthreads();

    const int laneA_row = lane & 15;
    const int laneA_b   = (lane >> 4) << 4;
    const int laneB_row = ((lane >> 4) << 3) + (lane & 7);
    const int laneB_b   = ((lane >> 3) & 1) << 4;

    float s[16][4];
    #pragma unroll
    for (int nt = 0; nt < 16; nt++)
        #pragma unroll
        for (int e = 0; e < 4; e++) s[nt][e] = 0.f;

    #pragma unroll
    for (int ks = 0; ks < 4; ks++) {
        uint32_t ah[4], al[4];
        {
            int r = wM*16 + laneA_row;
            uint32_t off = r*128 + (((uint32_t)(ks*32 + laneA_b)) ^ ((r & 7) << 4));
            ldm_x4(ah, sa + OQH + off);
            ldm_x4(al, sa + OQL + off);
        }
        #pragma unroll
        for (int ng = 0; ng < 8; ng++) {
            uint32_t bh4[4], bl4[4];
            int r = wN*128 + ng*16 + laneB_row;
            uint32_t off = r*128 + (((uint32_t)(ks*32 + laneB_b)) ^ ((r & 7) << 4));
            ldm_x4(bh4, sa + OKH + off);
            ldm_x4(bl4, sa + OKL + off);
            #pragma unroll
            for (int j = 0; j < 2; j++) {
                float* a = s[ng*2 + j];
                mma_bf16(a, ah, &bh4[j*2]);
                mma_bf16(a, ah, &bl4[j*2]);
                mma_bf16(a, al, &bh4[j*2]);
            }
        }
    }

    const int qrow0 = qb*64 + wM*16 + gid;
    const int qrow1 = qrow0 + 8;
    float m0 = -1e30f, m1 = -1e30f;
    #pragma unroll
    for (int nt = 0; nt < 16; nt++) {
        int c0 = wN*128 + nt*8 + tig*2;
        s[nt][0] = (c0     <= qrow0) ? s[nt][0]*0.125f : -1e30f;
        s[nt][1] = (c0 + 1 <= qrow0) ? s[nt][1]*0.125f : -1e30f;
        s[nt][2] = (c0     <= qrow1) ? s[nt][2]*0.125f : -1e30f;
        s[nt][3] = (c0 + 1 <= qrow1) ? s[nt][3]*0.125f : -1e30f;
        m0 = fmaxf(m0, fmaxf(s[nt][0], s[nt][1]));
        m1 = fmaxf(m1, fmaxf(s[nt][2], s[nt][3]));
    }
    #pragma unroll
    for (int o = 1; o <= 2; o <<= 1) {
        m0 = fmaxf(m0, __shfl_xor_sync(~0u, m0, o));
        m1 = fmaxf(m1, __shfl_xor_sync(~0u, m1, o));
    }
    float* redm = (float*)(smg + ORED);
    float* reds = (float*)(smg + ORED + 512);
    int r0l = wM*16 + gid;
    if (tig == 0) { redm[wN*64 + r0l] = m0; redm[wN*64 + r0l + 8] = m1; }
    __syncthreads();
    m0 = fmaxf(redm[r0l],     redm[64 + r0l]);
    m1 = fmaxf(redm[r0l + 8], redm[64 + r0l + 8]);

    float sum0 = 0.f, sum1 = 0.f;
    #pragma unroll
    for (int nt = 0; nt < 16; nt++) {
        s[nt][0] = __expf(s[nt][0] - m0);
        s[nt][1] = __expf(s[nt][1] - m0);
        s[nt][2] = __expf(s[nt][2] - m1);
        s[nt][3] = __expf(s[nt][3] - m1);
        sum0 += s[nt][0] + s[nt][1];
        sum1 += s[nt][2] + s[nt][3];
    }
    #pragma unroll
    for (int o = 1; o <= 2; o <<= 1) {
        sum0 += __shfl_xor_sync(~0u, sum0, o);
        sum1 += __shfl_xor_sync(~0u, sum1, o);
    }
    if (tig == 0) { reds[wN*64 + r0l] = sum0; reds[wN*64 + r0l + 8] = sum1; }
    __syncthreads();
    float inv0 = 1.f / (reds[r0l]     + reds[64 + r0l]);
    float inv1 = 1.f / (reds[r0l + 8] + reds[64 + r0l + 8]);

    #pragma unroll
    for (int nt = 0; nt < 16; nt++) {
        int c0 = wN*128 + nt*8 + tig*2;
        int kb = c0 >> 6, cb = c0 & 63;
        uint32_t sw0 = (uint32_t)(cb*2) ^ ((r0l & 7) << 4);
        uint32_t sw1 = (uint32_t)(cb*2) ^ (((r0l + 8) & 7) << 4);
        uint32_t off0 = kb*8192 + r0l*128 + sw0;
        uint32_t off1 = kb*8192 + (r0l + 8)*128 + sw1;
        uint32_t h, l;
        split2(s[nt][0]*inv0, s[nt][1]*inv0, h, l);
        *(uint32_t*)(smg + OPH + off0) = h;
        *(uint32_t*)(smg + OPL + off0) = l;
        split2(s[nt][2]*inv1, s[nt][3]*inv1, h, l);
        *(uint32_t*)(smg + OPH + off1) = h;
        *(uint32_t*)(smg + OPL + off1) = l;
    }
    CP_WAIT0();
    __syncthreads();

    float o[4][4];
    #pragma unroll
    for (int nt = 0; nt < 4; nt++)
        #pragma unroll
        for (int e = 0; e < 4; e++) o[nt][e] = 0.f;

    const int vlrow = lane & 15;
    const uint32_t cbyte0 = (uint32_t)(wN*64 + ((lane >> 4) << 4));
    for (int kb = 0; kb <= qb; kb++) {
        #pragma unroll
        for (int ks = 0; ks < 4; ks++) {
            uint32_t ph4[4], pl4[4];
            {
                int r = wM*16 + laneA_row;
                uint32_t off = kb*8192 + r*128 +
                               (((uint32_t)(ks*32 + laneA_b)) ^ ((r & 7) << 4));
                ldm_x4(ph4, sa + OPH + off);
                ldm_x4(pl4, sa + OPL + off);
            }
            int vr = kb*64 + ks*16 + vlrow;
            #pragma unroll
            for (int chh = 0; chh < 2; chh++) {
                uint32_t vh4[4], vl4[4];
                uint32_t voff = vr*128 + ((cbyte0 + chh*32) ^ ((vr & 7) << 4));
                ldm_x4t(vh4, sa + OVH + voff);
                ldm_x4t(vl4, sa + OVL + voff);
                #pragma unroll
                for (int j = 0; j < 2; j++) {
                    float* a = o[chh*2 + j];
                    mma_bf16(a, ph4, &vh4[j*2]);
                    mma_bf16(a, ph4, &vl4[j*2]);
                    mma_bf16(a, pl4, &vh4[j*2]);
                }
            }
        }
    }

    const int gr0 = b*SS + qb*64 + wM*16 + gid;
    #pragma unroll
    for (int nt = 0; nt < 4; nt++) {
        int col = h*DH + wN*32 + nt*8 + tig*2;
        uint32_t h0, l0, h1, l1;
        split2(o[nt][0], o[nt][1], h0, l0);
        split2(o[nt][2], o[nt][3], h1, l1);
        size_t i0 = (size_t)gr0*DD + col, i1 = (size_t)(gr0 + 8)*DD + col;
        *(uint32_t*)(ohi + i0) = h0; *(uint32_t*)(olo + i0) = l0;
        *(uint32_t*)(ohi + i1) = h1; *(uint32_t*)(olo + i1) = l1;
    }
}

// ---------------------------------------------------------------------------
// fp32 SIMT NT GEMM, z-batched
// ---------------------------------------------------------------------------
__global__ void __launch_bounds__(256)
gemm_nt_b(const float* __restrict__ A, size_t astr,
          const float* __restrict__ B, size_t bstr,
          const float* __restrict__ bias, size_t bistr,
          float* __restrict__ C, size_t cstr,
          int M, int N, int K) {
    const int zz = blockIdx.z;
    A += zz*astr; B += zz*bstr; bias += zz*bistr; C += zz*cstr;

    __shared__ float As[8][128];
    __shared__ float Bs[8][128];
    const int bm = blockIdx.y * 128;
    const int bn = blockIdx.x * 128;
    const int tid = threadIdx.x;
    const int tx = tid & 15, ty = tid >> 4;
    const int lr = tid >> 1, lc = (tid & 1) * 4;
    const int arow = min(bm + lr, M - 1);
    const int brow = bn + lr;

    float acc[8][8];
    #pragma unroll
    for (int i = 0; i < 8; i++)
        #pragma unroll
        for (int j = 0; j < 8; j++) acc[i][j] = 0.f;

    for (int kt = 0; kt < K; kt += 8) {
        {
            float4 v = *(const float4*)(A + (size_t)arow*K + kt + lc);
            As[lc+0][lr] = v.x; As[lc+1][lr] = v.y;
            As[lc+2][lr] = v.z; As[lc+3][lr] = v.w;
        }
        {
            float4 v = *(const float4*)(B + (size_t)brow*K + kt + lc);
            Bs[lc+0][lr] = v.x; Bs[lc+1][lr] = v.y;
            Bs[lc+2][lr] = v.z; Bs[lc+3][lr] = v.w;
        }
        __syncthreads();
        #pragma unroll
        for (int k = 0; k < 8; k++) {
            float a[8], b[8];
            #pragma unroll
            for (int i = 0; i < 8; i++) a[i] = As[k][ty*8 + i];
            #pragma unroll
            for (int j = 0; j < 8; j++) b[j] = Bs[k][tx*8 + j];
            #pragma unroll
            for (int i = 0; i < 8; i++)
                #pragma unroll
                for (int j = 0; j < 8; j++)
                    acc[i][j] = fmaf(a[i], b[j], acc[i][j]);
        }
        __syncthreads();
    }
    #pragma unroll
    for (int i = 0; i < 8; i++) {
        int row = bm + ty*8 + i;
        if (row >= M) continue;
        #pragma unroll
        for (int j = 0; j < 8; j++) {
            int col = bn + tx*8 + j;
            C[(size_t)row*N + col] = acc[i][j] + bias[col];
        }
    }
}

// ---------------------------------------------------------------------------
// LN body (device helper)
// ---------------------------------------------------------------------------
__device__ __forceinline__ void ln_block(float* v, const float4 gv,
                                         const float4 bv, int t,
                                         float* red, float* o) {
    float sum = v[0] + v[1] + v[2] + v[3];
    #pragma unroll
    for (int oo = 16; oo; oo >>= 1) sum += __shfl_xor_sync(~0u, sum, oo);
    if ((t & 31) == 0) red[t >> 5] = sum;
    __syncthreads();
    float mean = (red[0] + red[1] + red[2] + red[3]) * (1.f/512.f);
    float var = 0.f;
    #pragma unroll
    for (int i = 0; i < 4; i++) {
        float d = v[i] - mean;
        var = fmaf(d, d, var);
    }
    #pragma unroll
    for (int oo = 16; oo; oo >>= 1) var += __shfl_xor_sync(~0u, var, oo);
    if ((t & 31) == 0) red[4 + (t >> 5)] = var;
    __syncthreads();
    float rs = rsqrtf((red[4] + red[5] + red[6] + red[7]) * (1.f/512.f) + 1e-5f);
    o[0] = (v[0] - mean) * rs * gv.x + bv.x;
    o[1] = (v[1] - mean) * rs * gv.y + bv.y;
    o[2] = (v[2] - mean) * rs * gv.z + bv.z;
    o[3] = (v[3] - mean) * rs * gv.w + bv.w;
}

__global__ void __launch_bounds__(128)
add_ln_kernel(float* __restrict__ x, const float* __restrict__ r,
              const float* __restrict__ g, const float* __restrict__ bt,
              __nv_bfloat16* __restrict__ xhi, __nv_bfloat16* __restrict__ xlo) {
    int row = blockIdx.x;
    const float* rp = r + (size_t)row*DD;
    float* xp = x + (size_t)row*DD;
    int t = threadIdx.x;
    __shared__ float red[8];

    float4 xv = ((const float4*)xp)[t];
    float4 rv = ((const float4*)rp)[t];
    float v[4] = {xv.x+rv.x, xv.y+rv.y, xv.z+rv.z, xv.w+rv.w};
    float o[4];
    ln_block(v, ((const float4*)g)[t], ((const float4*)bt)[t], t, red, o);
    ((float4*)xp)[t] = make_float4(o[0], o[1], o[2], o[3]);
    uint32_t h0, l0, h1, l1;
    split2(o[0], o[1], h0, l0);
    split2(o[2], o[3], h1, l1);
    ((uint2*)(xhi + (size_t)row*DD))[t] = make_uint2(h0, h1);
    ((uint2*)(xlo + (size_t)row*DD))[t] = make_uint2(l0, l1);
}

__global__ void __launch_bounds__(128)
add_ln2_kernel(float* __restrict__ x, const float* __restrict__ sub,
               const float* __restrict__ ca,
               const float* __restrict__ g1, const float* __restrict__ b1,
               const float* __restrict__ g2, const float* __restrict__ b2,
               __nv_bfloat16* __restrict__ xhi, __nv_bfloat16* __restrict__ xlo) {
    int row = blockIdx.x;
    float* xp = x + (size_t)row*DD;
    const float* sp = sub + (size_t)row*DD;
    const float* cp = ca + (size_t)(row >> 8)*DD;
    int t = threadIdx.x;
    __shared__ float red[8];

    float4 xv = ((const float4*)xp)[t];
    float4 sv = ((const float4*)sp)[t];
    float v[4] = {xv.x+sv.x, xv.y+sv.y, xv.z+sv.z, xv.w+sv.w};
    float y1[4];
    ln_block(v, ((const float4*)g1)[t], ((const float4*)b1)[t], t, red, y1);
    __syncthreads();

    float4 cv = ((const float4*)cp)[t];
    float v2[4] = {y1[0]+cv.x, y1[1]+cv.y, y1[2]+cv.z, y1[3]+cv.w};
    float o[4];
    ln_block(v2, ((const float4*)g2)[t], ((const float4*)b2)[t], t, red, o);
    ((float4*)xp)[t] = make_float4(o[0], o[1], o[2], o[3]);
    uint32_t h0, l0, h1, l1;
    split2(o[0], o[1], h0, l0);
    split2(o[2], o[3], h1, l1);
    ((uint2*)(xhi + (size_t)row*DD))[t] = make_uint2(h0, h1);
    ((uint2*)(xlo + (size_t)row*DD))[t] = make_uint2(l0, l1);
}

// ---------------------------------------------------------------------------
// Launch
// ---------------------------------------------------------------------------
extern "C" void kernel_launch(void* const* d_in, const int* in_sizes, int n_in,
                              void* d_out, int out_size) {
    const float* z      = (const float*)d_in[0];
    const int*   tgt    = (const int*)  d_in[1];
    const float* emb    = (const float*)d_in[2];
    const float* pos    = (const float*)d_in[3];
    const float* proj_w = (const float*)d_in[4];
    const float* proj_b = (const float*)d_in[5];
    const float* sa_w   = (const float*)d_in[6];
    const float* sa_b   = (const float*)d_in[7];
    const float* sa_ow  = (const float*)d_in[8];
    const float* sa_ob  = (const float*)d_in[9];
    const float* ca_w   = (const float*)d_in[10];
    const float* ca_b   = (const float*)d_in[11];
    const float* ca_ow  = (const float*)d_in[12];
    const float* ca_ob  = (const float*)d_in[13];
    const float* ln1_s  = (const float*)d_in[14];
    const float* ln1_b  = (const float*)d_in[15];
    const float* ln2_s  = (const float*)d_in[16];
    const float* ln2_b  = (const float*)d_in[17];
    const float* ln3_s  = (const float*)d_in[18];
    const float* ln3_b  = (const float*)d_in[19];
    const float* ff1_w  = (const float*)d_in[20];
    const float* ff1_b  = (const float*)d_in[21];
    const float* ff2_w  = (const float*)d_in[22];
    const float* ff2_b  = (const float*)d_in[23];
    const float* fc_w   = (const float*)d_in[24];
    const float* fc_b   = (const float*)d_in[25];
    float* out = (float*)d_out;

    float *x, *sub, *mem, *cav, *ca;
    __nv_bfloat16 *ahi, *alo, *qhi, *qlo, *fhi, *flo, *whi, *wlo;
    cudaGetSymbolAddress((void**)&x,   g_x);
    cudaGetSymbolAddress((void**)&sub, g_sub);
    cudaGetSymbolAddress((void**)&mem, g_mem);
    cudaGetSymbolAddress((void**)&cav, g_cav);
    cudaGetSymbolAddress((void**)&ca,  g_ca);
    cudaGetSymbolAddress((void**)&ahi, g_ahi);
    cudaGetSymbolAddress((void**)&alo, g_alo);
    cudaGetSymbolAddress((void**)&qhi, g_qhi);
    cudaGetSymbolAddress((void**)&qlo, g_qlo);
    cudaGetSymbolAddress((void**)&fhi, g_fhi);
    cudaGetSymbolAddress((void**)&flo, g_flo);
    cudaGetSymbolAddress((void**)&whi, g_whi);
    cudaGetSymbolAddress((void**)&wlo, g_wlo);

    cudaFuncSetAttribute(gemm_hmma2,
                         cudaFuncAttributeMaxDynamicSharedMemorySize, G2SMEM);
    cudaFuncSetAttribute(attn_hmma,
                         cudaFuncAttributeMaxDynamicSharedMemorySize, ATT_SMEM);

    // ---- weight conversion ----
    conv_pair<<<6*3*DD*DD/1024, 256>>>(sa_w,  whi + O_SAW,  wlo + O_SAW);
    conv_pair<<<6*DD*DD/1024,   256>>>(sa_ow, whi + O_SAOW, wlo + O_SAOW);
    conv_pair<<<6*DFF*DD/1024,  256>>>(ff1_w, whi + O_FF1,  wlo + O_FF1);
    conv_pair<<<6*DD*DFF/1024,  256>>>(ff2_w, whi + O_FF2,  wlo + O_FF2);
    conv_pair<<<VV*DD/1024,     256>>>(fc_w,  whi + O_FC,   wlo + O_FC);

    // ---- embedding + memory projection ----
    embed_kernel<<<M_TOK, 128>>>(tgt, emb, pos, x, ahi, alo);
    gemm_nt_b<<<dim3(DD/128, 1, 1), 256>>>(z, 0, proj_w, 0, proj_b, 0,
                                           mem, 0, BB, DD, DD);

    // ---- batched cross-attention vectors (all layers) ----
    gemm_nt_b<<<dim3(DD/128, 1, LL), 256>>>(
        mem, 0,
        ca_w + (size_t)2*DD*DD, (size_t)3*DD*DD,
        ca_b + 2*DD, (size_t)3*DD,
        cav, (size_t)BB*DD, BB, DD, DD);
    gemm_nt_b<<<dim3(DD/128, 1, LL), 256>>>(
        cav, (size_t)BB*DD,
        ca_ow, (size_t)DD*DD,
        ca_ob, (size_t)DD,
        ca, (size_t)BB*DD, BB, DD, DD);

    for (int l = 0; l < LL; l++) {
        const float* sabl  = sa_b  + (size_t)l*3*DD;
        const float* saobl = sa_ob + (size_t)l*DD;
        size_t o_qkv = O_SAW  + (size_t)l*3*DD*DD;
        size_t o_ow  = O_SAOW + (size_t)l*DD*DD;
        size_t o_ff1 = O_FF1  + (size_t)l*DFF*DD;
        size_t o_ff2 = O_FF2  + (size_t)l*DD*DFF;

        // self-attention
        gemm_hmma2<<<dim3(12, 64), 512, G2SMEM>>>(ahi, alo, whi + o_qkv,
                                                  wlo + o_qkv, sabl, nullptr,
                                                  qhi, qlo, 3*DD, DD, 0, 1);
        attn_hmma<<<BB*HH*4, 256, ATT_SMEM>>>(qhi, qlo, ahi, alo);
        gemm_hmma2<<<dim3(4, 64), 512, G2SMEM>>>(ahi, alo, whi + o_ow,
                                                 wlo + o_ow, saobl, sub,
                                                 nullptr, nullptr, DD, DD, 0, 0);
        add_ln2_kernel<<<M_TOK, 128>>>(x, sub, ca + (size_t)l*BB*DD,
                                       ln1_s + l*DD, ln1_b + l*DD,
                                       ln2_s + l*DD, ln2_b + l*DD, ahi, alo);

        // feed-forward
        gemm_hmma2<<<dim3(16, 64), 512, G2SMEM>>>(ahi, alo, whi + o_ff1,
                                                  wlo + o_ff1, ff1_b + l*DFF,
                                                  nullptr, fhi, flo,
                                                  DFF, DD, 1, 1);
        gemm_hmma2<<<dim3(4, 64), 512, G2SMEM>>>(fhi, flo, whi + o_ff2,
                                                 wlo + o_ff2, ff2_b + l*DD,
                                                 sub, nullptr, nullptr,
                                                 DD, DFF, 0, 0);
        add_ln_kernel<<<M_TOK, 128>>>(x, sub, ln3_s + l*DD, ln3_b + l*DD,
                                      ahi, alo);
    }

    // final classifier
    gemm_hmma2<<<dim3(1, 64), 512, G2SMEM>>>(ahi, alo, whi + O_FC, wlo + O_FC,
                                             fc_b, out, nullptr, nullptr,
                                             VV, DD, 0, 0);
}

// round 9
// speedup vs baseline: 1.5708x; 1.5708x over previous
#include <cuda_runtime.h>
#include <cuda_bf16.h>
#include <math.h>
#include <stdint.h>

#define BB 64
#define SS 256
#define DD 512
#define HH 8
#define DH 64
#define DFF 2048
#define VV 128
#define LL 6
#define M_TOK (BB*SS)

// ---------------------------------------------------------------------------
// Scratch
// ---------------------------------------------------------------------------
__device__ float g_x  [M_TOK*DD];
__device__ float g_sub[M_TOK*DD];
__device__ float g_mem[BB*DD];
__device__ float g_cav[LL*BB*DD];
__device__ float g_ca [LL*BB*DD];

__device__ __nv_bfloat16 g_ahi[(size_t)M_TOK*DD];
__device__ __nv_bfloat16 g_alo[(size_t)M_TOK*DD];
__device__ __nv_bfloat16 g_qhi[(size_t)M_TOK*3*DD];
__device__ __nv_bfloat16 g_qlo[(size_t)M_TOK*3*DD];
__device__ __nv_bfloat16 g_fhi[(size_t)M_TOK*DFF];
__device__ __nv_bfloat16 g_flo[(size_t)M_TOK*DFF];

#define O_SAW  0u
#define O_SAOW 4718592u
#define O_FF1  6291456u
#define O_FF2  12582912u
#define O_FC   18874368u
#define WPOOL_E 18940032u
__device__ __nv_bfloat16 g_whi[WPOOL_E];
__device__ __nv_bfloat16 g_wlo[WPOOL_E];

// ---------------------------------------------------------------------------
// Helpers
// ---------------------------------------------------------------------------
__device__ __forceinline__ uint32_t smem_u32(const void* p) {
    uint32_t a;
    asm("{ .reg .u64 t; cvta.to.shared.u64 t, %1; cvt.u32.u64 %0, t; }"
        : "=r"(a) : "l"(p));
    return a;
}
__device__ __forceinline__ void cp_async16(uint32_t dst, const void* src) {
    asm volatile("cp.async.cg.shared.global [%0], [%1], 16;"
                 :: "r"(dst), "l"(src));
}
#define CP_COMMIT() asm volatile("cp.async.commit_group;" ::: "memory")
#define CP_WAIT1()  asm volatile("cp.async.wait_group 1;" ::: "memory")
#define CP_WAIT0()  asm volatile("cp.async.wait_group 0;" ::: "memory")

__device__ __forceinline__ void ldm_x4(uint32_t* r, uint32_t addr) {
    asm volatile("ldmatrix.sync.aligned.m8n8.x4.shared.b16 {%0,%1,%2,%3}, [%4];"
                 : "=r"(r[0]), "=r"(r[1]), "=r"(r[2]), "=r"(r[3]) : "r"(addr));
}
__device__ __forceinline__ void ldm_x4t(uint32_t* r, uint32_t addr) {
    asm volatile("ldmatrix.sync.aligned.m8n8.x4.trans.shared.b16 {%0,%1,%2,%3}, [%4];"
                 : "=r"(r[0]), "=r"(r[1]), "=r"(r[2]), "=r"(r[3]) : "r"(addr));
}
__device__ __forceinline__ void mma_bf16(float* c, const uint32_t* a,
                                         const uint32_t* b) {
    asm volatile(
        "mma.sync.aligned.m16n8k16.row.col.f32.bf16.bf16.f32 "
        "{%0,%1,%2,%3}, {%4,%5,%6,%7}, {%8,%9}, {%0,%1,%2,%3};"
        : "+f"(c[0]), "+f"(c[1]), "+f"(c[2]), "+f"(c[3])
        : "r"(a[0]), "r"(a[1]), "r"(a[2]), "r"(a[3]), "r"(b[0]), "r"(b[1]));
}
__device__ __forceinline__ uint32_t pack2bf(float a, float b) {
    __nv_bfloat162 t = __floats2bfloat162_rn(a, b);
    return *(uint32_t*)&t;
}
__device__ __forceinline__ void split2(float a, float b, uint32_t& hi, uint32_t& lo) {
    __nv_bfloat16 ha = __float2bfloat16_rn(a);
    __nv_bfloat16 hb = __float2bfloat16_rn(b);
    hi = pack2bf(__bfloat162float(ha), __bfloat162float(hb));
    lo = pack2bf(a - __bfloat162float(ha), b - __bfloat162float(hb));
}

// ---------------------------------------------------------------------------
// Embedding
// ---------------------------------------------------------------------------
__global__ void embed_kernel(const int* __restrict__ tgt,
                             const float* __restrict__ emb,
                             const float* __restrict__ pos,
                             float* __restrict__ x,
                             __nv_bfloat16* __restrict__ xhi,
                             __nv_bfloat16* __restrict__ xlo) {
    int row = blockIdx.x;
    int d4  = threadIdx.x;
    int tok = tgt[row];
    int s   = row & (SS - 1);
    float4 e = ((const float4*)(emb + (size_t)tok*DD))[d4];
    float4 p = ((const float4*)(pos + (size_t)s*DD))[d4];
    float4 v = make_float4(e.x+p.x, e.y+p.y, e.z+p.z, e.w+p.w);
    ((float4*)(x + (size_t)row*DD))[d4] = v;
    uint32_t h0, l0, h1, l1;
    split2(v.x, v.y, h0, l0);
    split2(v.z, v.w, h1, l1);
    ((uint2*)(xhi + (size_t)row*DD))[d4] = make_uint2(h0, h1);
    ((uint2*)(xlo + (size_t)row*DD))[d4] = make_uint2(l0, l1);
}

// ---------------------------------------------------------------------------
// fp32 -> bf16 hi/lo (weights)
// ---------------------------------------------------------------------------
__global__ void __launch_bounds__(256)
conv_pair(const float* __restrict__ src, __nv_bfloat16* __restrict__ hi,
          __nv_bfloat16* __restrict__ lo) {
    size_t i = (size_t)blockIdx.x * 256 + threadIdx.x;
    float4 v = ((const float4*)src)[i];
    uint32_t h0, l0, h1, l1;
    split2(v.x, v.y, h0, l0);
    split2(v.z, v.w, h1, l1);
    ((uint2*)hi)[i] = make_uint2(h0, h1);
    ((uint2*)lo)[i] = make_uint2(l0, l1);
}

// ---------------------------------------------------------------------------
// HMMA bf16x3 GEMM, 128x128 CTA tile, 256 threads (8 warps 2x4), 3-stage
// cp.async pipeline with SINGLE sync per K-chunk (loads issued before compute,
// targeting stage (s+2)%3 whose last reader finished at the previous barrier).
// mode 0: fp32 C. mode 1: bf16 hi/lo + opt ReLU.
// Stage: Ahi 16K | Alo 16K | Bhi 16K | Blo 16K = 64 KB.
// ---------------------------------------------------------------------------
#define HSTAGE 65536
#define HSMEM  (3*HSTAGE)

__global__ void __launch_bounds__(256, 1)
gemm_hmma(const __nv_bfloat16* __restrict__ Ahi,
          const __nv_bfloat16* __restrict__ Alo,
          const __nv_bfloat16* __restrict__ Bhi,
          const __nv_bfloat16* __restrict__ Blo,
          const float* __restrict__ bias, float* __restrict__ C,
          __nv_bfloat16* __restrict__ Chi, __nv_bfloat16* __restrict__ Clo,
          int N, int K, int relu, int mode) {
    extern __shared__ char smg[];
    const uint32_t sa = smem_u32(smg);
    const int tid = threadIdx.x;
    const int wid = tid >> 5, lane = tid & 31;
    const int wM = wid >> 2, wN = wid & 3;       // 2 x 4 warps, 64x32 tiles
    const int bm = blockIdx.y * 128;
    const int bn = blockIdx.x * 128;
    const int kc = K >> 6;

    float acc[4][4][4];
    #pragma unroll
    for (int i = 0; i < 4; i++)
        #pragma unroll
        for (int j = 0; j < 4; j++)
            #pragma unroll
            for (int e = 0; e < 4; e++) acc[i][j][e] = 0.f;

    auto load_stage = [&](int s, int kk) {
        uint32_t stg = sa + s*HSTAGE;
        #pragma unroll
        for (int i = tid; i < 2048; i += 256) {
            int pool = i >> 10, r = (i >> 3) & 127, c = i & 7;
            const __nv_bfloat16* g =
                (pool ? Alo : Ahi) + (size_t)(bm + r)*K + kk*64 + c*8;
            cp_async16(stg + pool*16384 + r*128 + ((c*16) ^ ((r & 7) << 4)), g);
        }
        #pragma unroll
        for (int i = tid; i < 2048; i += 256) {
            int pool = i >> 10, r = (i >> 3) & 127, c = i & 7;
            const __nv_bfloat16* g =
                (pool ? Blo : Bhi) + (size_t)(bn + r)*K + kk*64 + c*8;
            cp_async16(stg + 32768 + pool*16384 + r*128 +
                       ((c*16) ^ ((r & 7) << 4)), g);
        }
    };

    load_stage(0, 0); CP_COMMIT();
    load_stage(1, 1); CP_COMMIT();

    const int laneA_row = lane & 15;
    const int laneA_b   = (lane >> 4) << 4;
    const int laneB_row = ((lane >> 4) << 3) + (lane & 7);
    const int laneB_b   = ((lane >> 3) & 1) << 4;

    int sidx = 0;
    for (int ch = 0; ch < kc; ch++) {
        CP_WAIT1();
        __syncthreads();          // single barrier per chunk

        // issue loads for ch+2 into stage (sidx+2)%3 — last read at iter ch-1
        if (ch + 2 < kc) {
            int st2 = sidx + 2; if (st2 >= 3) st2 -= 3;
            load_stage(st2, ch + 2);
        }
        CP_COMMIT();

        uint32_t stg = sa + sidx*HSTAGE;
        #pragma unroll
        for (int ks = 0; ks < 4; ks++) {
            uint32_t ah[4][4], al[4][4], bh[2][4], bl[2][4];
            #pragma unroll
            for (int mf = 0; mf < 4; mf++) {
                int r = wM*64 + mf*16 + laneA_row;
                uint32_t off = r*128 + (((uint32_t)(ks*32 + laneA_b)) ^ ((r & 7) << 4));
                ldm_x4(ah[mf], stg + off);
                ldm_x4(al[mf], stg + 16384 + off);
            }
            #pragma unroll
            for (int nf2 = 0; nf2 < 2; nf2++) {
                int r = wN*32 + nf2*16 + laneB_row;
                uint32_t off = r*128 + (((uint32_t)(ks*32 + laneB_b)) ^ ((r & 7) << 4));
                ldm_x4(bh[nf2], stg + 32768 + off);
                ldm_x4(bl[nf2], stg + 49152 + off);
            }
            #pragma unroll
            for (int mf = 0; mf < 4; mf++)
                #pragma unroll
                for (int nf = 0; nf < 4; nf++) {
                    const uint32_t* bhf = &bh[nf >> 1][(nf & 1)*2];
                    const uint32_t* blf = &bl[nf >> 1][(nf & 1)*2];
                    mma_bf16(acc[mf][nf], ah[mf], bhf);
                    mma_bf16(acc[mf][nf], ah[mf], blf);
                    mma_bf16(acc[mf][nf], al[mf], bhf);
                }
        }
        sidx = (sidx == 2) ? 0 : sidx + 1;
    }

    const int gid = lane >> 2, tig = lane & 3;
    #pragma unroll
    for (int mf = 0; mf < 4; mf++) {
        int r0 = bm + wM*64 + mf*16 + gid;
        #pragma unroll
        for (int nf = 0; nf < 4; nf++) {
            int col = bn + wN*32 + nf*8 + tig*2;
            float bx = __ldg(bias + col), by = __ldg(bias + col + 1);
            float v0x = acc[mf][nf][0] + bx, v0y = acc[mf][nf][1] + by;
            float v1x = acc[mf][nf][2] + bx, v1y = acc[mf][nf][3] + by;
            if (relu) {
                v0x = fmaxf(v0x, 0.f); v0y = fmaxf(v0y, 0.f);
                v1x = fmaxf(v1x, 0.f); v1y = fmaxf(v1y, 0.f);
            }
            if (mode == 0) {
                *(float2*)(C + (size_t)r0*N + col)       = make_float2(v0x, v0y);
                *(float2*)(C + (size_t)(r0 + 8)*N + col) = make_float2(v1x, v1y);
            } else {
                uint32_t h, l;
                size_t i0 = (size_t)r0*N + col, i1 = (size_t)(r0 + 8)*N + col;
                split2(v0x, v0y, h, l);
                *(uint32_t*)(Chi + i0) = h; *(uint32_t*)(Clo + i0) = l;
                split2(v1x, v1y, h, l);
                *(uint32_t*)(Chi + i1) = h; *(uint32_t*)(Clo + i1) = l;
            }
        }
    }
}

// ---------------------------------------------------------------------------
// HMMA causal attention (R7 passing version, split V group)
// ---------------------------------------------------------------------------
#define OQH 0
#define OQL 8192
#define OKH 16384
#define OKL 49152
#define OVH 81920
#define OVL 114688
#define OPH 147456
#define OPL 180224
#define ORED 212992
#define ATT_SMEM (ORED + 1024)

__global__ void __launch_bounds__(256, 1)
attn_hmma(const __nv_bfloat16* __restrict__ qhi,
          const __nv_bfloat16* __restrict__ qlo,
          __nv_bfloat16* __restrict__ ohi,
          __nv_bfloat16* __restrict__ olo) {
    extern __shared__ char smg[];
    const uint32_t sa = smem_u32(smg);
    const int tid = threadIdx.x;
    const int wid = tid >> 5, lane = tid & 31;
    const int wM = wid >> 1, wN = wid & 1;
    const int gid = lane >> 2, tig = lane & 3;

    const int bid = blockIdx.x;
    const int qb = bid & 3;
    const int h  = (bid >> 2) & 7;
    const int b  = bid >> 5;
    const int krows = (qb + 1) * 64;

    auto load_tile = [&](const __nv_bfloat16* g, uint32_t sbase, int rows) {
        for (int i = tid; i < rows*8; i += 256) {
            int r = i >> 3, c = i & 7;
            cp_async16(sa + sbase + r*128 + ((c*16) ^ ((r & 7) << 4)),
                       g + (size_t)r*1536 + c*8);
        }
    };
    const size_t qbase = (size_t)(b*SS + qb*64)*1536 + h*DH;
    const size_t kbase = (size_t)(b*SS)*1536 + DD + h*DH;
    const size_t vbase = (size_t)(b*SS)*1536 + 2*DD + h*DH;
    load_tile(qhi + qbase, OQH, 64);
    load_tile(qlo + qbase, OQL, 64);
    load_tile(qhi + kbase, OKH, krows);
    load_tile(qlo + kbase, OKL, krows);
    CP_COMMIT();
    load_tile(qhi + vbase, OVH, krows);
    load_tile(qlo + vbase, OVL, krows);
    CP_COMMIT();
    CP_WAIT1();
    __syncthreads();

    const int laneA_row = lane & 15;
    const int laneA_b   = (lane >> 4) << 4;
    const int laneB_row = ((lane >> 4) << 3) + (lane & 7);
    const int laneB_b   = ((lane >> 3) & 1) << 4;

    float s[16][4];
    #pragma unroll
    for (int nt = 0; nt < 16; nt++)
        #pragma unroll
        for (int e = 0; e < 4; e++) s[nt][e] = 0.f;

    #pragma unroll
    for (int ks = 0; ks < 4; ks++) {
        uint32_t ah[4], al[4];
        {
            int r = wM*16 + laneA_row;
            uint32_t off = r*128 + (((uint32_t)(ks*32 + laneA_b)) ^ ((r & 7) << 4));
            ldm_x4(ah, sa + OQH + off);
            ldm_x4(al, sa + OQL + off);
        }
        #pragma unroll
        for (int ng = 0; ng < 8; ng++) {
            uint32_t bh4[4], bl4[4];
            int r = wN*128 + ng*16 + laneB_row;
            uint32_t off = r*128 + (((uint32_t)(ks*32 + laneB_b)) ^ ((r & 7) << 4));
            ldm_x4(bh4, sa + OKH + off);
            ldm_x4(bl4, sa + OKL + off);
            #pragma unroll
            for (int j = 0; j < 2; j++) {
                float* a = s[ng*2 + j];
                mma_bf16(a, ah, &bh4[j*2]);
                mma_bf16(a, ah, &bl4[j*2]);
                mma_bf16(a, al, &bh4[j*2]);
            }
        }
    }

    const int qrow0 = qb*64 + wM*16 + gid;
    const int qrow1 = qrow0 + 8;
    float m0 = -1e30f, m1 = -1e30f;
    #pragma unroll
    for (int nt = 0; nt < 16; nt++) {
        int c0 = wN*128 + nt*8 + tig*2;
        s[nt][0] = (c0     <= qrow0) ? s[nt][0]*0.125f : -1e30f;
        s[nt][1] = (c0 + 1 <= qrow0) ? s[nt][1]*0.125f : -1e30f;
        s[nt][2] = (c0     <= qrow1) ? s[nt][2]*0.125f : -1e30f;
        s[nt][3] = (c0 + 1 <= qrow1) ? s[nt][3]*0.125f : -1e30f;
        m0 = fmaxf(m0, fmaxf(s[nt][0], s[nt][1]));
        m1 = fmaxf(m1, fmaxf(s[nt][2], s[nt][3]));
    }
    #pragma unroll
    for (int o = 1; o <= 2; o <<= 1) {
        m0 = fmaxf(m0, __shfl_xor_sync(~0u, m0, o));
        m1 = fmaxf(m1, __shfl_xor_sync(~0u, m1, o));
    }
    float* redm = (float*)(smg + ORED);
    float* reds = (float*)(smg + ORED + 512);
    int r0l = wM*16 + gid;
    if (tig == 0) { redm[wN*64 + r0l] = m0; redm[wN*64 + r0l + 8] = m1; }
    __syncthreads();
    m0 = fmaxf(redm[r0l],     redm[64 + r0l]);
    m1 = fmaxf(redm[r0l + 8], redm[64 + r0l + 8]);

    float sum0 = 0.f, sum1 = 0.f;
    #pragma unroll
    for (int nt = 0; nt < 16; nt++) {
        s[nt][0] = __expf(s[nt][0] - m0);
        s[nt][1] = __expf(s[nt][1] - m0);
        s[nt][2] = __expf(s[nt][2] - m1);
        s[nt][3] = __expf(s[nt][3] - m1);
        sum0 += s[nt][0] + s[nt][1];
        sum1 += s[nt][2] + s[nt][3];
    }
    #pragma unroll
    for (int o = 1; o <= 2; o <<= 1) {
        sum0 += __shfl_xor_sync(~0u, sum0, o);
        sum1 += __shfl_xor_sync(~0u, sum1, o);
    }
    if (tig == 0) { reds[wN*64 + r0l] = sum0; reds[wN*64 + r0l + 8] = sum1; }
    __syncthreads();
    float inv0 = 1.f / (reds[r0l]     + reds[64 + r0l]);
    float inv1 = 1.f / (reds[r0l + 8] + reds[64 + r0l + 8]);

    #pragma unroll
    for (int nt = 0; nt < 16; nt++) {
        int c0 = wN*128 + nt*8 + tig*2;
        int kb = c0 >> 6, cb = c0 & 63;
        uint32_t sw0 = (uint32_t)(cb*2) ^ ((r0l & 7) << 4);
        uint32_t sw1 = (uint32_t)(cb*2) ^ (((r0l + 8) & 7) << 4);
        uint32_t off0 = kb*8192 + r0l*128 + sw0;
        uint32_t off1 = kb*8192 + (r0l + 8)*128 + sw1;
        uint32_t h, l;
        split2(s[nt][0]*inv0, s[nt][1]*inv0, h, l);
        *(uint32_t*)(smg + OPH + off0) = h;
        *(uint32_t*)(smg + OPL + off0) = l;
        split2(s[nt][2]*inv1, s[nt][3]*inv1, h, l);
        *(uint32_t*)(smg + OPH + off1) = h;
        *(uint32_t*)(smg + OPL + off1) = l;
    }
    CP_WAIT0();
    __syncthreads();

    float o[4][4];
    #pragma unroll
    for (int nt = 0; nt < 4; nt++)
        #pragma unroll
        for (int e = 0; e < 4; e++) o[nt][e] = 0.f;

    const int vlrow = lane & 15;
    const uint32_t cbyte0 = (uint32_t)(wN*64 + ((lane >> 4) << 4));
    for (int kb = 0; kb <= qb; kb++) {
        #pragma unroll
        for (int ks = 0; ks < 4; ks++) {
            uint32_t ph4[4], pl4[4];
            {
                int r = wM*16 + laneA_row;
                uint32_t off = kb*8192 + r*128 +
                               (((uint32_t)(ks*32 + laneA_b)) ^ ((r & 7) << 4));
                ldm_x4(ph4, sa + OPH + off);
                ldm_x4(pl4, sa + OPL + off);
            }
            int vr = kb*64 + ks*16 + vlrow;
            #pragma unroll
            for (int chh = 0; chh < 2; chh++) {
                uint32_t vh4[4], vl4[4];
                uint32_t voff = vr*128 + ((cbyte0 + chh*32) ^ ((vr & 7) << 4));
                ldm_x4t(vh4, sa + OVH + voff);
                ldm_x4t(vl4, sa + OVL + voff);
                #pragma unroll
                for (int j = 0; j < 2; j++) {
                    float* a = o[chh*2 + j];
                    mma_bf16(a, ph4, &vh4[j*2]);
                    mma_bf16(a, ph4, &vl4[j*2]);
                    mma_bf16(a, pl4, &vh4[j*2]);
                }
            }
        }
    }

    const int gr0 = b*SS + qb*64 + wM*16 + gid;
    #pragma unroll
    for (int nt = 0; nt < 4; nt++) {
        int col = h*DH + wN*32 + nt*8 + tig*2;
        uint32_t h0, l0, h1, l1;
        split2(o[nt][0], o[nt][1], h0, l0);
        split2(o[nt][2], o[nt][3], h1, l1);
        size_t i0 = (size_t)gr0*DD + col, i1 = (size_t)(gr0 + 8)*DD + col;
        *(uint32_t*)(ohi + i0) = h0; *(uint32_t*)(olo + i0) = l0;
        *(uint32_t*)(ohi + i1) = h1; *(uint32_t*)(olo + i1) = l1;
    }
}

// ---------------------------------------------------------------------------
// fp32 SIMT NT GEMM, z-batched
// ---------------------------------------------------------------------------
__global__ void __launch_bounds__(256)
gemm_nt_b(const float* __restrict__ A, size_t astr,
          const float* __restrict__ B, size_t bstr,
          const float* __restrict__ bias, size_t bistr,
          float* __restrict__ C, size_t cstr,
          int M, int N, int K) {
    const int zz = blockIdx.z;
    A += zz*astr; B += zz*bstr; bias += zz*bistr; C += zz*cstr;

    __shared__ float As[8][128];
    __shared__ float Bs[8][128];
    const int bm = blockIdx.y * 128;
    const int bn = blockIdx.x * 128;
    const int tid = threadIdx.x;
    const int tx = tid & 15, ty = tid >> 4;
    const int lr = tid >> 1, lc = (tid & 1) * 4;
    const int arow = min(bm + lr, M - 1);
    const int brow = bn + lr;

    float acc[8][8];
    #pragma unroll
    for (int i = 0; i < 8; i++)
        #pragma unroll
        for (int j = 0; j < 8; j++) acc[i][j] = 0.f;

    for (int kt = 0; kt < K; kt += 8) {
        {
            float4 v = *(const float4*)(A + (size_t)arow*K + kt + lc);
            As[lc+0][lr] = v.x; As[lc+1][lr] = v.y;
            As[lc+2][lr] = v.z; As[lc+3][lr] = v.w;
        }
        {
            float4 v = *(const float4*)(B + (size_t)brow*K + kt + lc);
            Bs[lc+0][lr] = v.x; Bs[lc+1][lr] = v.y;
            Bs[lc+2][lr] = v.z; Bs[lc+3][lr] = v.w;
        }
        __syncthreads();
        #pragma unroll
        for (int k = 0; k < 8; k++) {
            float a[8], b[8];
            #pragma unroll
            for (int i = 0; i < 8; i++) a[i] = As[k][ty*8 + i];
            #pragma unroll
            for (int j = 0; j < 8; j++) b[j] = Bs[k][tx*8 + j];
            #pragma unroll
            for (int i = 0; i < 8; i++)
                #pragma unroll
                for (int j = 0; j < 8; j++)
                    acc[i][j] = fmaf(a[i], b[j], acc[i][j]);
        }
        __syncthreads();
    }
    #pragma unroll
    for (int i = 0; i < 8; i++) {
        int row = bm + ty*8 + i;
        if (row >= M) continue;
        #pragma unroll
        for (int j = 0; j < 8; j++) {
            int col = bn + tx*8 + j;
            C[(size_t)row*N + col] = acc[i][j] + bias[col];
        }
    }
}

// ---------------------------------------------------------------------------
// LN body (device helper)
// ---------------------------------------------------------------------------
__device__ __forceinline__ void ln_block(float* v, const float4 gv,
                                         const float4 bv, int t,
                                         float* red, float* o) {
    float sum = v[0] + v[1] + v[2] + v[3];
    #pragma unroll
    for (int oo = 16; oo; oo >>= 1) sum += __shfl_xor_sync(~0u, sum, oo);
    if ((t & 31) == 0) red[t >> 5] = sum;
    __syncthreads();
    float mean = (red[0] + red[1] + red[2] + red[3]) * (1.f/512.f);
    float var = 0.f;
    #pragma unroll
    for (int i = 0; i < 4; i++) {
        float d = v[i] - mean;
        var = fmaf(d, d, var);
    }
    #pragma unroll
    for (int oo = 16; oo; oo >>= 1) var += __shfl_xor_sync(~0u, var, oo);
    if ((t & 31) == 0) red[4 + (t >> 5)] = var;
    __syncthreads();
    float rs = rsqrtf((red[4] + red[5] + red[6] + red[7]) * (1.f/512.f) + 1e-5f);
    o[0] = (v[0] - mean) * rs * gv.x + bv.x;
    o[1] = (v[1] - mean) * rs * gv.y + bv.y;
    o[2] = (v[2] - mean) * rs * gv.z + bv.z;
    o[3] = (v[3] - mean) * rs * gv.w + bv.w;
}

__global__ void __launch_bounds__(128)
add_ln_kernel(float* __restrict__ x, const float* __restrict__ r,
              const float* __restrict__ g, const float* __restrict__ bt,
              __nv_bfloat16* __restrict__ xhi, __nv_bfloat16* __restrict__ xlo) {
    int row = blockIdx.x;
    const float* rp = r + (size_t)row*DD;
    float* xp = x + (size_t)row*DD;
    int t = threadIdx.x;
    __shared__ float red[8];

    float4 xv = ((const float4*)xp)[t];
    float4 rv = ((const float4*)rp)[t];
    float v[4] = {xv.x+rv.x, xv.y+rv.y, xv.z+rv.z, xv.w+rv.w};
    float o[4];
    ln_block(v, ((const float4*)g)[t], ((const float4*)bt)[t], t, red, o);
    ((float4*)xp)[t] = make_float4(o[0], o[1], o[2], o[3]);
    uint32_t h0, l0, h1, l1;
    split2(o[0], o[1], h0, l0);
    split2(o[2], o[3], h1, l1);
    ((uint2*)(xhi + (size_t)row*DD))[t] = make_uint2(h0, h1);
    ((uint2*)(xlo + (size_t)row*DD))[t] = make_uint2(l0, l1);
}

__global__ void __launch_bounds__(128)
add_ln2_kernel(float* __restrict__ x, const float* __restrict__ sub,
               const float* __restrict__ ca,
               const float* __restrict__ g1, const float* __restrict__ b1,
               const float* __restrict__ g2, const float* __restrict__ b2,
               __nv_bfloat16* __restrict__ xhi, __nv_bfloat16* __restrict__ xlo) {
    int row = blockIdx.x;
    float* xp = x + (size_t)row*DD;
    const float* sp = sub + (size_t)row*DD;
    const float* cp = ca + (size_t)(row >> 8)*DD;
    int t = threadIdx.x;
    __shared__ float red[8];

    float4 xv = ((const float4*)xp)[t];
    float4 sv = ((const float4*)sp)[t];
    float v[4] = {xv.x+sv.x, xv.y+sv.y, xv.z+sv.z, xv.w+sv.w};
    float y1[4];
    ln_block(v, ((const float4*)g1)[t], ((const float4*)b1)[t], t, red, y1);
    __syncthreads();

    float4 cv = ((const float4*)cp)[t];
    float v2[4] = {y1[0]+cv.x, y1[1]+cv.y, y1[2]+cv.z, y1[3]+cv.w};
    float o[4];
    ln_block(v2, ((const float4*)g2)[t], ((const float4*)b2)[t], t, red, o);
    ((float4*)xp)[t] = make_float4(o[0], o[1], o[2], o[3]);
    uint32_t h0, l0, h1, l1;
    split2(o[0], o[1], h0, l0);
    split2(o[2], o[3], h1, l1);
    ((uint2*)(xhi + (size_t)row*DD))[t] = make_uint2(h0, h1);
    ((uint2*)(xlo + (size_t)row*DD))[t] = make_uint2(l0, l1);
}

// ---------------------------------------------------------------------------
// Launch
// ---------------------------------------------------------------------------
extern "C" void kernel_launch(void* const* d_in, const int* in_sizes, int n_in,
                              void* d_out, int out_size) {
    const float* z      = (const float*)d_in[0];
    const int*   tgt    = (const int*)  d_in[1];
    const float* emb    = (const float*)d_in[2];
    const float* pos    = (const float*)d_in[3];
    const float* proj_w = (const float*)d_in[4];
    const float* proj_b = (const float*)d_in[5];
    const float* sa_w   = (const float*)d_in[6];
    const float* sa_b   = (const float*)d_in[7];
    const float* sa_ow  = (const float*)d_in[8];
    const float* sa_ob  = (const float*)d_in[9];
    const float* ca_w   = (const float*)d_in[10];
    const float* ca_b   = (const float*)d_in[11];
    const float* ca_ow  = (const float*)d_in[12];
    const float* ca_ob  = (const float*)d_in[13];
    const float* ln1_s  = (const float*)d_in[14];
    const float* ln1_b  = (const float*)d_in[15];
    const float* ln2_s  = (const float*)d_in[16];
    const float* ln2_b  = (const float*)d_in[17];
    const float* ln3_s  = (const float*)d_in[18];
    const float* ln3_b  = (const float*)d_in[19];
    const float* ff1_w  = (const float*)d_in[20];
    const float* ff1_b  = (const float*)d_in[21];
    const float* ff2_w  = (const float*)d_in[22];
    const float* ff2_b  = (const float*)d_in[23];
    const float* fc_w   = (const float*)d_in[24];
    const float* fc_b   = (const float*)d_in[25];
    float* out = (float*)d_out;

    float *x, *sub, *mem, *cav, *ca;
    __nv_bfloat16 *ahi, *alo, *qhi, *qlo, *fhi, *flo, *whi, *wlo;
    cudaGetSymbolAddress((void**)&x,   g_x);
    cudaGetSymbolAddress((void**)&sub, g_sub);
    cudaGetSymbolAddress((void**)&mem, g_mem);
    cudaGetSymbolAddress((void**)&cav, g_cav);
    cudaGetSymbolAddress((void**)&ca,  g_ca);
    cudaGetSymbolAddress((void**)&ahi, g_ahi);
    cudaGetSymbolAddress((void**)&alo, g_alo);
    cudaGetSymbolAddress((void**)&qhi, g_qhi);
    cudaGetSymbolAddress((void**)&qlo, g_qlo);
    cudaGetSymbolAddress((void**)&fhi, g_fhi);
    cudaGetSymbolAddress((void**)&flo, g_flo);
    cudaGetSymbolAddress((void**)&whi, g_whi);
    cudaGetSymbolAddress((void**)&wlo, g_wlo);

    cudaFuncSetAttribute(gemm_hmma,
                         cudaFuncAttributeMaxDynamicSharedMemorySize, HSMEM);
    cudaFuncSetAttribute(attn_hmma,
                         cudaFuncAttributeMaxDynamicSharedMemorySize, ATT_SMEM);

    // ---- weight conversion ----
    conv_pair<<<6*3*DD*DD/1024, 256>>>(sa_w,  whi + O_SAW,  wlo + O_SAW);
    conv_pair<<<6*DD*DD/1024,   256>>>(sa_ow, whi + O_SAOW, wlo + O_SAOW);
    conv_pair<<<6*DFF*DD/1024,  256>>>(ff1_w, whi + O_FF1,  wlo + O_FF1);
    conv_pair<<<6*DD*DFF/1024,  256>>>(ff2_w, whi + O_FF2,  wlo + O_FF2);
    conv_pair<<<VV*DD/1024,     256>>>(fc_w,  whi + O_FC,   wlo + O_FC);

    // ---- embedding + memory projection ----
    embed_kernel<<<M_TOK, 128>>>(tgt, emb, pos, x, ahi, alo);
    gemm_nt_b<<<dim3(DD/128, 1, 1), 256>>>(z, 0, proj_w, 0, proj_b, 0,
                                           mem, 0, BB, DD, DD);

    // ---- batched cross-attention vectors (all layers) ----
    gemm_nt_b<<<dim3(DD/128, 1, LL), 256>>>(
        mem, 0,
        ca_w + (size_t)2*DD*DD, (size_t)3*DD*DD,
        ca_b + 2*DD, (size_t)3*DD,
        cav, (size_t)BB*DD, BB, DD, DD);
    gemm_nt_b<<<dim3(DD/128, 1, LL), 256>>>(
        cav, (size_t)BB*DD,
        ca_ow, (size_t)DD*DD,
        ca_ob, (size_t)DD,
        ca, (size_t)BB*DD, BB, DD, DD);

    for (int l = 0; l < LL; l++) {
        const float* sabl  = sa_b  + (size_t)l*3*DD;
        const float* saobl = sa_ob + (size_t)l*DD;
        size_t o_qkv = O_SAW  + (size_t)l*3*DD*DD;
        size_t o_ow  = O_SAOW + (size_t)l*DD*DD;
        size_t o_ff1 = O_FF1  + (size_t)l*DFF*DD;
        size_t o_ff2 = O_FF2  + (size_t)l*DD*DFF;

        // self-attention
        gemm_hmma<<<dim3(12, 128), 256, HSMEM>>>(ahi, alo, whi + o_qkv,
                                                 wlo + o_qkv, sabl, nullptr,
                                                 qhi, qlo, 3*DD, DD, 0, 1);
        attn_hmma<<<BB*HH*4, 256, ATT_SMEM>>>(qhi, qlo, ahi, alo);
        gemm_hmma<<<dim3(4, 128), 256, HSMEM>>>(ahi, alo, whi + o_ow,
                                                wlo + o_ow, saobl, sub,
                                                nullptr, nullptr, DD, DD, 0, 0);
        add_ln2_kernel<<<M_TOK, 128>>>(x, sub, ca + (size_t)l*BB*DD,
                                       ln1_s + l*DD, ln1_b + l*DD,
                                       ln2_s + l*DD, ln2_b + l*DD, ahi, alo);

        // feed-forward
        gemm_hmma<<<dim3(16, 128), 256, HSMEM>>>(ahi, alo, whi + o_ff1,
                                                 wlo + o_ff1, ff1_b + l*DFF,
                                                 nullptr, fhi, flo,
                                                 DFF, DD, 1, 1);
        gemm_hmma<<<dim3(4, 128), 256, HSMEM>>>(fhi, flo, whi + o_ff2,
                                                wlo + o_ff2, ff2_b + l*DD,
                                                sub, nullptr, nullptr,
                                                DD, DFF, 0, 0);
        add_ln_kernel<<<M_TOK, 128>>>(x, sub, ln3_s + l*DD, ln3_b + l*DD,
                                      ahi, alo);
    }

    // final classifier
    gemm_hmma<<<dim3(1, 128), 256, HSMEM>>>(ahi, alo, whi + O_FC, wlo + O_FC,
                                            fc_b, out, nullptr, nullptr,
                                            VV, DD, 0, 0);
}

// round 10
// speedup vs baseline: 1.5817x; 1.0069x over previous
#include <cuda_runtime.h>
#include <cuda_bf16.h>
#include <math.h>
#include <stdint.h>

#define BB 64
#define SS 256
#define DD 512
#define HH 8
#define DH 64
#define DFF 2048
#define VV 128
#define LL 6
#define M_TOK (BB*SS)

// ---------------------------------------------------------------------------
// Scratch
// ---------------------------------------------------------------------------
__device__ float g_sub[M_TOK*DD];
__device__ float g_mem[BB*DD];
__device__ float g_cav[LL*BB*DD];
__device__ float g_ca [LL*BB*DD];

// residual stream lives ONLY as bf16 hi/lo (x = hi + lo)
__device__ __nv_bfloat16 g_ahi[(size_t)M_TOK*DD];
__device__ __nv_bfloat16 g_alo[(size_t)M_TOK*DD];
__device__ __nv_bfloat16 g_qhi[(size_t)M_TOK*3*DD];
__device__ __nv_bfloat16 g_qlo[(size_t)M_TOK*3*DD];
__device__ __nv_bfloat16 g_fhi[(size_t)M_TOK*DFF];   // ff1 out / attn out
__device__ __nv_bfloat16 g_flo[(size_t)M_TOK*DFF];

#define O_SAW  0u
#define O_SAOW 4718592u
#define O_FF1  6291456u
#define O_FF2  12582912u
#define O_FC   18874368u
#define WPOOL_E 18940032u
__device__ __nv_bfloat16 g_whi[WPOOL_E];
__device__ __nv_bfloat16 g_wlo[WPOOL_E];

// ---------------------------------------------------------------------------
// Helpers
// ---------------------------------------------------------------------------
__device__ __forceinline__ uint32_t smem_u32(const void* p) {
    uint32_t a;
    asm("{ .reg .u64 t; cvta.to.shared.u64 t, %1; cvt.u32.u64 %0, t; }"
        : "=r"(a) : "l"(p));
    return a;
}
__device__ __forceinline__ void cp_async16(uint32_t dst, const void* src) {
    asm volatile("cp.async.cg.shared.global [%0], [%1], 16;"
                 :: "r"(dst), "l"(src));
}
#define CP_COMMIT() asm volatile("cp.async.commit_group;" ::: "memory")
#define CP_WAIT1()  asm volatile("cp.async.wait_group 1;" ::: "memory")
#define CP_WAIT0()  asm volatile("cp.async.wait_group 0;" ::: "memory")

__device__ __forceinline__ void ldm_x4(uint32_t* r, uint32_t addr) {
    asm volatile("ldmatrix.sync.aligned.m8n8.x4.shared.b16 {%0,%1,%2,%3}, [%4];"
                 : "=r"(r[0]), "=r"(r[1]), "=r"(r[2]), "=r"(r[3]) : "r"(addr));
}
__device__ __forceinline__ void ldm_x4t(uint32_t* r, uint32_t addr) {
    asm volatile("ldmatrix.sync.aligned.m8n8.x4.trans.shared.b16 {%0,%1,%2,%3}, [%4];"
                 : "=r"(r[0]), "=r"(r[1]), "=r"(r[2]), "=r"(r[3]) : "r"(addr));
}
__device__ __forceinline__ void mma_bf16(float* c, const uint32_t* a,
                                         const uint32_t* b) {
    asm volatile(
        "mma.sync.aligned.m16n8k16.row.col.f32.bf16.bf16.f32 "
        "{%0,%1,%2,%3}, {%4,%5,%6,%7}, {%8,%9}, {%0,%1,%2,%3};"
        : "+f"(c[0]), "+f"(c[1]), "+f"(c[2]), "+f"(c[3])
        : "r"(a[0]), "r"(a[1]), "r"(a[2]), "r"(a[3]), "r"(b[0]), "r"(b[1]));
}
__device__ __forceinline__ uint32_t pack2bf(float a, float b) {
    __nv_bfloat162 t = __floats2bfloat162_rn(a, b);
    return *(uint32_t*)&t;
}
__device__ __forceinline__ void split2(float a, float b, uint32_t& hi, uint32_t& lo) {
    __nv_bfloat16 ha = __float2bfloat16_rn(a);
    __nv_bfloat16 hb = __float2bfloat16_rn(b);
    hi = pack2bf(__bfloat162float(ha), __bfloat162float(hb));
    lo = pack2bf(a - __bfloat162float(ha), b - __bfloat162float(hb));
}
// reconstruct two fp32 from packed hi/lo bf16x2
__device__ __forceinline__ void join2(uint32_t hi, uint32_t lo, float& a, float& b) {
    __nv_bfloat162 h = *(__nv_bfloat162*)&hi;
    __nv_bfloat162 l = *(__nv_bfloat162*)&lo;
    a = __bfloat162float(h.x) + __bfloat162float(l.x);
    b = __bfloat162float(h.y) + __bfloat162float(l.y);
}

// ---------------------------------------------------------------------------
// Embedding -> hi/lo residual stream only
// ---------------------------------------------------------------------------
__global__ void embed_kernel(const int* __restrict__ tgt,
                             const float* __restrict__ emb,
                             const float* __restrict__ pos,
                             __nv_bfloat16* __restrict__ xhi,
                             __nv_bfloat16* __restrict__ xlo) {
    int row = blockIdx.x;
    int d4  = threadIdx.x;
    int tok = tgt[row];
    int s   = row & (SS - 1);
    float4 e = ((const float4*)(emb + (size_t)tok*DD))[d4];
    float4 p = ((const float4*)(pos + (size_t)s*DD))[d4];
    float4 v = make_float4(e.x+p.x, e.y+p.y, e.z+p.z, e.w+p.w);
    uint32_t h0, l0, h1, l1;
    split2(v.x, v.y, h0, l0);
    split2(v.z, v.w, h1, l1);
    ((uint2*)(xhi + (size_t)row*DD))[d4] = make_uint2(h0, h1);
    ((uint2*)(xlo + (size_t)row*DD))[d4] = make_uint2(l0, l1);
}

// ---------------------------------------------------------------------------
// fp32 -> bf16 hi/lo (weights)
// ---------------------------------------------------------------------------
__global__ void __launch_bounds__(256)
conv_pair(const float* __restrict__ src, __nv_bfloat16* __restrict__ hi,
          __nv_bfloat16* __restrict__ lo) {
    size_t i = (size_t)blockIdx.x * 256 + threadIdx.x;
    float4 v = ((const float4*)src)[i];
    uint32_t h0, l0, h1, l1;
    split2(v.x, v.y, h0, l0);
    split2(v.z, v.w, h1, l1);
    ((uint2*)hi)[i] = make_uint2(h0, h1);
    ((uint2*)lo)[i] = make_uint2(l0, l1);
}

// ---------------------------------------------------------------------------
// HMMA bf16x3 GEMM, 128x128 CTA tile, 256 threads, 3-stage single-sync
// pipeline (unchanged from R9 winner).
// mode 0: fp32 C. mode 1: bf16 hi/lo + opt ReLU.
// ---------------------------------------------------------------------------
#define HSTAGE 65536
#define HSMEM  (3*HSTAGE)

__global__ void __launch_bounds__(256, 1)
gemm_hmma(const __nv_bfloat16* __restrict__ Ahi,
          const __nv_bfloat16* __restrict__ Alo,
          const __nv_bfloat16* __restrict__ Bhi,
          const __nv_bfloat16* __restrict__ Blo,
          const float* __restrict__ bias, float* __restrict__ C,
          __nv_bfloat16* __restrict__ Chi, __nv_bfloat16* __restrict__ Clo,
          int N, int K, int relu, int mode) {
    extern __shared__ char smg[];
    const uint32_t sa = smem_u32(smg);
    const int tid = threadIdx.x;
    const int wid = tid >> 5, lane = tid & 31;
    const int wM = wid >> 2, wN = wid & 3;
    const int bm = blockIdx.y * 128;
    const int bn = blockIdx.x * 128;
    const int kc = K >> 6;

    float acc[4][4][4];
    #pragma unroll
    for (int i = 0; i < 4; i++)
        #pragma unroll
        for (int j = 0; j < 4; j++)
            #pragma unroll
            for (int e = 0; e < 4; e++) acc[i][j][e] = 0.f;

    auto load_stage = [&](int s, int kk) {
        uint32_t stg = sa + s*HSTAGE;
        #pragma unroll
        for (int i = tid; i < 2048; i += 256) {
            int pool = i >> 10, r = (i >> 3) & 127, c = i & 7;
            const __nv_bfloat16* g =
                (pool ? Alo : Ahi) + (size_t)(bm + r)*K + kk*64 + c*8;
            cp_async16(stg + pool*16384 + r*128 + ((c*16) ^ ((r & 7) << 4)), g);
        }
        #pragma unroll
        for (int i = tid; i < 2048; i += 256) {
            int pool = i >> 10, r = (i >> 3) & 127, c = i & 7;
            const __nv_bfloat16* g =
                (pool ? Blo : Bhi) + (size_t)(bn + r)*K + kk*64 + c*8;
            cp_async16(stg + 32768 + pool*16384 + r*128 +
                       ((c*16) ^ ((r & 7) << 4)), g);
        }
    };

    load_stage(0, 0); CP_COMMIT();
    load_stage(1, 1); CP_COMMIT();

    const int laneA_row = lane & 15;
    const int laneA_b   = (lane >> 4) << 4;
    const int laneB_row = ((lane >> 4) << 3) + (lane & 7);
    const int laneB_b   = ((lane >> 3) & 1) << 4;

    int sidx = 0;
    for (int ch = 0; ch < kc; ch++) {
        CP_WAIT1();
        __syncthreads();

        if (ch + 2 < kc) {
            int st2 = sidx + 2; if (st2 >= 3) st2 -= 3;
            load_stage(st2, ch + 2);
        }
        CP_COMMIT();

        uint32_t stg = sa + sidx*HSTAGE;
        #pragma unroll
        for (int ks = 0; ks < 4; ks++) {
            uint32_t ah[4][4], al[4][4], bh[2][4], bl[2][4];
            #pragma unroll
            for (int mf = 0; mf < 4; mf++) {
                int r = wM*64 + mf*16 + laneA_row;
                uint32_t off = r*128 + (((uint32_t)(ks*32 + laneA_b)) ^ ((r & 7) << 4));
                ldm_x4(ah[mf], stg + off);
                ldm_x4(al[mf], stg + 16384 + off);
            }
            #pragma unroll
            for (int nf2 = 0; nf2 < 2; nf2++) {
                int r = wN*32 + nf2*16 + laneB_row;
                uint32_t off = r*128 + (((uint32_t)(ks*32 + laneB_b)) ^ ((r & 7) << 4));
                ldm_x4(bh[nf2], stg + 32768 + off);
                ldm_x4(bl[nf2], stg + 49152 + off);
            }
            #pragma unroll
            for (int mf = 0; mf < 4; mf++)
                #pragma unroll
                for (int nf = 0; nf < 4; nf++) {
                    const uint32_t* bhf = &bh[nf >> 1][(nf & 1)*2];
                    const uint32_t* blf = &bl[nf >> 1][(nf & 1)*2];
                    mma_bf16(acc[mf][nf], ah[mf], bhf);
                    mma_bf16(acc[mf][nf], ah[mf], blf);
                    mma_bf16(acc[mf][nf], al[mf], bhf);
                }
        }
        sidx = (sidx == 2) ? 0 : sidx + 1;
    }

    const int gid = lane >> 2, tig = lane & 3;
    #pragma unroll
    for (int mf = 0; mf < 4; mf++) {
        int r0 = bm + wM*64 + mf*16 + gid;
        #pragma unroll
        for (int nf = 0; nf < 4; nf++) {
            int col = bn + wN*32 + nf*8 + tig*2;
            float bx = __ldg(bias + col), by = __ldg(bias + col + 1);
            float v0x = acc[mf][nf][0] + bx, v0y = acc[mf][nf][1] + by;
            float v1x = acc[mf][nf][2] + bx, v1y = acc[mf][nf][3] + by;
            if (relu) {
                v0x = fmaxf(v0x, 0.f); v0y = fmaxf(v0y, 0.f);
                v1x = fmaxf(v1x, 0.f); v1y = fmaxf(v1y, 0.f);
            }
            if (mode == 0) {
                *(float2*)(C + (size_t)r0*N + col)       = make_float2(v0x, v0y);
                *(float2*)(C + (size_t)(r0 + 8)*N + col) = make_float2(v1x, v1y);
            } else {
                uint32_t h, l;
                size_t i0 = (size_t)r0*N + col, i1 = (size_t)(r0 + 8)*N + col;
                split2(v0x, v0y, h, l);
                *(uint32_t*)(Chi + i0) = h; *(uint32_t*)(Clo + i0) = l;
                split2(v1x, v1y, h, l);
                *(uint32_t*)(Chi + i1) = h; *(uint32_t*)(Clo + i1) = l;
            }
        }
    }
}

// ---------------------------------------------------------------------------
// HMMA causal attention (unchanged math; output row stride = DD into fhi/flo)
// ---------------------------------------------------------------------------
#define OQH 0
#define OQL 8192
#define OKH 16384
#define OKL 49152
#define OVH 81920
#define OVL 114688
#define OPH 147456
#define OPL 180224
#define ORED 212992
#define ATT_SMEM (ORED + 1024)

__global__ void __launch_bounds__(256, 1)
attn_hmma(const __nv_bfloat16* __restrict__ qhi,
          const __nv_bfloat16* __restrict__ qlo,
          __nv_bfloat16* __restrict__ ohi,
          __nv_bfloat16* __restrict__ olo) {
    extern __shared__ char smg[];
    const uint32_t sa = smem_u32(smg);
    const int tid = threadIdx.x;
    const int wid = tid >> 5, lane = tid & 31;
    const int wM = wid >> 1, wN = wid & 1;
    const int gid = lane >> 2, tig = lane & 3;

    const int bid = blockIdx.x;
    const int qb = bid & 3;
    const int h  = (bid >> 2) & 7;
    const int b  = bid >> 5;
    const int krows = (qb + 1) * 64;

    auto load_tile = [&](const __nv_bfloat16* g, uint32_t sbase, int rows) {
        for (int i = tid; i < rows*8; i += 256) {
            int r = i >> 3, c = i & 7;
            cp_async16(sa + sbase + r*128 + ((c*16) ^ ((r & 7) << 4)),
                       g + (size_t)r*1536 + c*8);
        }
    };
    const size_t qbase = (size_t)(b*SS + qb*64)*1536 + h*DH;
    const size_t kbase = (size_t)(b*SS)*1536 + DD + h*DH;
    const size_t vbase = (size_t)(b*SS)*1536 + 2*DD + h*DH;
    load_tile(qhi + qbase, OQH, 64);
    load_tile(qlo + qbase, OQL, 64);
    load_tile(qhi + kbase, OKH, krows);
    load_tile(qlo + kbase, OKL, krows);
    CP_COMMIT();
    load_tile(qhi + vbase, OVH, krows);
    load_tile(qlo + vbase, OVL, krows);
    CP_COMMIT();
    CP_WAIT1();
    __syncthreads();

    const int laneA_row = lane & 15;
    const int laneA_b   = (lane >> 4) << 4;
    const int laneB_row = ((lane >> 4) << 3) + (lane & 7);
    const int laneB_b   = ((lane >> 3) & 1) << 4;

    float s[16][4];
    #pragma unroll
    for (int nt = 0; nt < 16; nt++)
        #pragma unroll
        for (int e = 0; e < 4; e++) s[nt][e] = 0.f;

    #pragma unroll
    for (int ks = 0; ks < 4; ks++) {
        uint32_t ah[4], al[4];
        {
            int r = wM*16 + laneA_row;
            uint32_t off = r*128 + (((uint32_t)(ks*32 + laneA_b)) ^ ((r & 7) << 4));
            ldm_x4(ah, sa + OQH + off);
            ldm_x4(al, sa + OQL + off);
        }
        #pragma unroll
        for (int ng = 0; ng < 8; ng++) {
            uint32_t bh4[4], bl4[4];
            int r = wN*128 + ng*16 + laneB_row;
            uint32_t off = r*128 + (((uint32_t)(ks*32 + laneB_b)) ^ ((r & 7) << 4));
            ldm_x4(bh4, sa + OKH + off);
            ldm_x4(bl4, sa + OKL + off);
            #pragma unroll
            for (int j = 0; j < 2; j++) {
                float* a = s[ng*2 + j];
                mma_bf16(a, ah, &bh4[j*2]);
                mma_bf16(a, ah, &bl4[j*2]);
                mma_bf16(a, al, &bh4[j*2]);
            }
        }
    }

    const int qrow0 = qb*64 + wM*16 + gid;
    const int qrow1 = qrow0 + 8;
    float m0 = -1e30f, m1 = -1e30f;
    #pragma unroll
    for (int nt = 0; nt < 16; nt++) {
        int c0 = wN*128 + nt*8 + tig*2;
        s[nt][0] = (c0     <= qrow0) ? s[nt][0]*0.125f : -1e30f;
        s[nt][1] = (c0 + 1 <= qrow0) ? s[nt][1]*0.125f : -1e30f;
        s[nt][2] = (c0     <= qrow1) ? s[nt][2]*0.125f : -1e30f;
        s[nt][3] = (c0 + 1 <= qrow1) ? s[nt][3]*0.125f : -1e30f;
        m0 = fmaxf(m0, fmaxf(s[nt][0], s[nt][1]));
        m1 = fmaxf(m1, fmaxf(s[nt][2], s[nt][3]));
    }
    #pragma unroll
    for (int o = 1; o <= 2; o <<= 1) {
        m0 = fmaxf(m0, __shfl_xor_sync(~0u, m0, o));
        m1 = fmaxf(m1, __shfl_xor_sync(~0u, m1, o));
    }
    float* redm = (float*)(smg + ORED);
    float* reds = (float*)(smg + ORED + 512);
    int r0l = wM*16 + gid;
    if (tig == 0) { redm[wN*64 + r0l] = m0; redm[wN*64 + r0l + 8] = m1; }
    __syncthreads();
    m0 = fmaxf(redm[r0l],     redm[64 + r0l]);
    m1 = fmaxf(redm[r0l + 8], redm[64 + r0l + 8]);

    float sum0 = 0.f, sum1 = 0.f;
    #pragma unroll
    for (int nt = 0; nt < 16; nt++) {
        s[nt][0] = __expf(s[nt][0] - m0);
        s[nt][1] = __expf(s[nt][1] - m0);
        s[nt][2] = __expf(s[nt][2] - m1);
        s[nt][3] = __expf(s[nt][3] - m1);
        sum0 += s[nt][0] + s[nt][1];
        sum1 += s[nt][2] + s[nt][3];
    }
    #pragma unroll
    for (int o = 1; o <= 2; o <<= 1) {
        sum0 += __shfl_xor_sync(~0u, sum0, o);
        sum1 += __shfl_xor_sync(~0u, sum1, o);
    }
    if (tig == 0) { reds[wN*64 + r0l] = sum0; reds[wN*64 + r0l + 8] = sum1; }
    __syncthreads();
    float inv0 = 1.f / (reds[r0l]     + reds[64 + r0l]);
    float inv1 = 1.f / (reds[r0l + 8] + reds[64 + r0l + 8]);

    #pragma unroll
    for (int nt = 0; nt < 16; nt++) {
        int c0 = wN*128 + nt*8 + tig*2;
        int kb = c0 >> 6, cb = c0 & 63;
        uint32_t sw0 = (uint32_t)(cb*2) ^ ((r0l & 7) << 4);
        uint32_t sw1 = (uint32_t)(cb*2) ^ (((r0l + 8) & 7) << 4);
        uint32_t off0 = kb*8192 + r0l*128 + sw0;
        uint32_t off1 = kb*8192 + (r0l + 8)*128 + sw1;
        uint32_t h, l;
        split2(s[nt][0]*inv0, s[nt][1]*inv0, h, l);
        *(uint32_t*)(smg + OPH + off0) = h;
        *(uint32_t*)(smg + OPL + off0) = l;
        split2(s[nt][2]*inv1, s[nt][3]*inv1, h, l);
        *(uint32_t*)(smg + OPH + off1) = h;
        *(uint32_t*)(smg + OPL + off1) = l;
    }
    CP_WAIT0();
    __syncthreads();

    float o[4][4];
    #pragma unroll
    for (int nt = 0; nt < 4; nt++)
        #pragma unroll
        for (int e = 0; e < 4; e++) o[nt][e] = 0.f;

    const int vlrow = lane & 15;
    const uint32_t cbyte0 = (uint32_t)(wN*64 + ((lane >> 4) << 4));
    for (int kb = 0; kb <= qb; kb++) {
        #pragma unroll
        for (int ks = 0; ks < 4; ks++) {
            uint32_t ph4[4], pl4[4];
            {
                int r = wM*16 + laneA_row;
                uint32_t off = kb*8192 + r*128 +
                               (((uint32_t)(ks*32 + laneA_b)) ^ ((r & 7) << 4));
                ldm_x4(ph4, sa + OPH + off);
                ldm_x4(pl4, sa + OPL + off);
            }
            int vr = kb*64 + ks*16 + vlrow;
            #pragma unroll
            for (int chh = 0; chh < 2; chh++) {
                uint32_t vh4[4], vl4[4];
                uint32_t voff = vr*128 + ((cbyte0 + chh*32) ^ ((vr & 7) << 4));
                ldm_x4t(vh4, sa + OVH + voff);
                ldm_x4t(vl4, sa + OVL + voff);
                #pragma unroll
                for (int j = 0; j < 2; j++) {
                    float* a = o[chh*2 + j];
                    mma_bf16(a, ph4, &vh4[j*2]);
                    mma_bf16(a, ph4, &vl4[j*2]);
                    mma_bf16(a, pl4, &vh4[j*2]);
                }
            }
        }
    }

    const int gr0 = b*SS + qb*64 + wM*16 + gid;
    #pragma unroll
    for (int nt = 0; nt < 4; nt++) {
        int col = h*DH + wN*32 + nt*8 + tig*2;
        uint32_t h0, l0, h1, l1;
        split2(o[nt][0], o[nt][1], h0, l0);
        split2(o[nt][2], o[nt][3], h1, l1);
        size_t i0 = (size_t)gr0*DD + col, i1 = (size_t)(gr0 + 8)*DD + col;
        *(uint32_t*)(ohi + i0) = h0; *(uint32_t*)(olo + i0) = l0;
        *(uint32_t*)(ohi + i1) = h1; *(uint32_t*)(olo + i1) = l1;
    }
}

// ---------------------------------------------------------------------------
// fp32 SIMT NT GEMM, z-batched
// ---------------------------------------------------------------------------
__global__ void __launch_bounds__(256)
gemm_nt_b(const float* __restrict__ A, size_t astr,
          const float* __restrict__ B, size_t bstr,
          const float* __restrict__ bias, size_t bistr,
          float* __restrict__ C, size_t cstr,
          int M, int N, int K) {
    const int zz = blockIdx.z;
    A += zz*astr; B += zz*bstr; bias += zz*bistr; C += zz*cstr;

    __shared__ float As[8][128];
    __shared__ float Bs[8][128];
    const int bm = blockIdx.y * 128;
    const int bn = blockIdx.x * 128;
    const int tid = threadIdx.x;
    const int tx = tid & 15, ty = tid >> 4;
    const int lr = tid >> 1, lc = (tid & 1) * 4;
    const int arow = min(bm + lr, M - 1);
    const int brow = bn + lr;

    float acc[8][8];
    #pragma unroll
    for (int i = 0; i < 8; i++)
        #pragma unroll
        for (int j = 0; j < 8; j++) acc[i][j] = 0.f;

    for (int kt = 0; kt < K; kt += 8) {
        {
            float4 v = *(const float4*)(A + (size_t)arow*K + kt + lc);
            As[lc+0][lr] = v.x; As[lc+1][lr] = v.y;
            As[lc+2][lr] = v.z; As[lc+3][lr] = v.w;
        }
        {
            float4 v = *(const float4*)(B + (size_t)brow*K + kt + lc);
            Bs[lc+0][lr] = v.x; Bs[lc+1][lr] = v.y;
            Bs[lc+2][lr] = v.z; Bs[lc+3][lr] = v.w;
        }
        __syncthreads();
        #pragma unroll
        for (int k = 0; k < 8; k++) {
            float a[8], b[8];
            #pragma unroll
            for (int i = 0; i < 8; i++) a[i] = As[k][ty*8 + i];
            #pragma unroll
            for (int j = 0; j < 8; j++) b[j] = Bs[k][tx*8 + j];
            #pragma unroll
            for (int i = 0; i < 8; i++)
                #pragma unroll
                for (int j = 0; j < 8; j++)
                    acc[i][j] = fmaf(a[i], b[j], acc[i][j]);
        }
        __syncthreads();
    }
    #pragma unroll
    for (int i = 0; i < 8; i++) {
        int row = bm + ty*8 + i;
        if (row >= M) continue;
        #pragma unroll
        for (int j = 0; j < 8; j++) {
            int col = bn + tx*8 + j;
            C[(size_t)row*N + col] = acc[i][j] + bias[col];
        }
    }
}

// ---------------------------------------------------------------------------
// LN body (device helper)
// ---------------------------------------------------------------------------
__device__ __forceinline__ void ln_block(float* v, const float4 gv,
                                         const float4 bv, int t,
                                         float* red, float* o) {
    float sum = v[0] + v[1] + v[2] + v[3];
    #pragma unroll
    for (int oo = 16; oo; oo >>= 1) sum += __shfl_xor_sync(~0u, sum, oo);
    if ((t & 31) == 0) red[t >> 5] = sum;
    __syncthreads();
    float mean = (red[0] + red[1] + red[2] + red[3]) * (1.f/512.f);
    float var = 0.f;
    #pragma unroll
    for (int i = 0; i < 4; i++) {
        float d = v[i] - mean;
        var = fmaf(d, d, var);
    }
    #pragma unroll
    for (int oo = 16; oo; oo >>= 1) var += __shfl_xor_sync(~0u, var, oo);
    if ((t & 31) == 0) red[4 + (t >> 5)] = var;
    __syncthreads();
    float rs = rsqrtf((red[4] + red[5] + red[6] + red[7]) * (1.f/512.f) + 1e-5f);
    o[0] = (v[0] - mean) * rs * gv.x + bv.x;
    o[1] = (v[1] - mean) * rs * gv.y + bv.y;
    o[2] = (v[2] - mean) * rs * gv.z + bv.z;
    o[3] = (v[3] - mean) * rs * gv.w + bv.w;
}

// x' = LN(x + sub); residual stream in hi/lo only
__global__ void __launch_bounds__(128)
add_ln_kernel(__nv_bfloat16* __restrict__ xhi, __nv_bfloat16* __restrict__ xlo,
              const float* __restrict__ r,
              const float* __restrict__ g, const float* __restrict__ bt) {
    int row = blockIdx.x;
    const float* rp = r + (size_t)row*DD;
    int t = threadIdx.x;
    __shared__ float red[8];

    uint2 hp = ((const uint2*)(xhi + (size_t)row*DD))[t];
    uint2 lp = ((const uint2*)(xlo + (size_t)row*DD))[t];
    float v[4];
    join2(hp.x, lp.x, v[0], v[1]);
    join2(hp.y, lp.y, v[2], v[3]);
    float4 rv = ((const float4*)rp)[t];
    v[0] += rv.x; v[1] += rv.y; v[2] += rv.z; v[3] += rv.w;

    float o[4];
    ln_block(v, ((const float4*)g)[t], ((const float4*)bt)[t], t, red, o);
    uint32_t h0, l0, h1, l1;
    split2(o[0], o[1], h0, l0);
    split2(o[2], o[3], h1, l1);
    ((uint2*)(xhi + (size_t)row*DD))[t] = make_uint2(h0, h1);
    ((uint2*)(xlo + (size_t)row*DD))[t] = make_uint2(l0, l1);
}

// x' = LN2( LN1(x + sub) + ca[b] )
__global__ void __launch_bounds__(128)
add_ln2_kernel(__nv_bfloat16* __restrict__ xhi, __nv_bfloat16* __restrict__ xlo,
               const float* __restrict__ sub, const float* __restrict__ ca,
               const float* __restrict__ g1, const float* __restrict__ b1,
               const float* __restrict__ g2, const float* __restrict__ b2) {
    int row = blockIdx.x;
    const float* sp = sub + (size_t)row*DD;
    const float* cp = ca + (size_t)(row >> 8)*DD;
    int t = threadIdx.x;
    __shared__ float red[8];

    uint2 hp = ((const uint2*)(xhi + (size_t)row*DD))[t];
    uint2 lp = ((const uint2*)(xlo + (size_t)row*DD))[t];
    float v[4];
    join2(hp.x, lp.x, v[0], v[1]);
    join2(hp.y, lp.y, v[2], v[3]);
    float4 sv = ((const float4*)sp)[t];
    v[0] += sv.x; v[1] += sv.y; v[2] += sv.z; v[3] += sv.w;

    float y1[4];
    ln_block(v, ((const float4*)g1)[t], ((const float4*)b1)[t], t, red, y1);
    __syncthreads();

    float4 cv = ((const float4*)cp)[t];
    float v2[4] = {y1[0]+cv.x, y1[1]+cv.y, y1[2]+cv.z, y1[3]+cv.w};
    float o[4];
    ln_block(v2, ((const float4*)g2)[t], ((const float4*)b2)[t], t, red, o);
    uint32_t h0, l0, h1, l1;
    split2(o[0], o[1], h0, l0);
    split2(o[2], o[3], h1, l1);
    ((uint2*)(xhi + (size_t)row*DD))[t] = make_uint2(h0, h1);
    ((uint2*)(xlo + (size_t)row*DD))[t] = make_uint2(l0, l1);
}

// ---------------------------------------------------------------------------
// Launch
// ---------------------------------------------------------------------------
extern "C" void kernel_launch(void* const* d_in, const int* in_sizes, int n_in,
                              void* d_out, int out_size) {
    const float* z      = (const float*)d_in[0];
    const int*   tgt    = (const int*)  d_in[1];
    const float* emb    = (const float*)d_in[2];
    const float* pos    = (const float*)d_in[3];
    const float* proj_w = (const float*)d_in[4];
    const float* proj_b = (const float*)d_in[5];
    const float* sa_w   = (const float*)d_in[6];
    const float* sa_b   = (const float*)d_in[7];
    const float* sa_ow  = (const float*)d_in[8];
    const float* sa_ob  = (const float*)d_in[9];
    const float* ca_w   = (const float*)d_in[10];
    const float* ca_b   = (const float*)d_in[11];
    const float* ca_ow  = (const float*)d_in[12];
    const float* ca_ob  = (const float*)d_in[13];
    const float* ln1_s  = (const float*)d_in[14];
    const float* ln1_b  = (const float*)d_in[15];
    const float* ln2_s  = (const float*)d_in[16];
    const float* ln2_b  = (const float*)d_in[17];
    const float* ln3_s  = (const float*)d_in[18];
    const float* ln3_b  = (const float*)d_in[19];
    const float* ff1_w  = (const float*)d_in[20];
    const float* ff1_b  = (const float*)d_in[21];
    const float* ff2_w  = (const float*)d_in[22];
    const float* ff2_b  = (const float*)d_in[23];
    const float* fc_w   = (const float*)d_in[24];
    const float* fc_b   = (const float*)d_in[25];
    float* out = (float*)d_out;

    float *sub, *mem, *cav, *ca;
    __nv_bfloat16 *ahi, *alo, *qhi, *qlo, *fhi, *flo, *whi, *wlo;
    cudaGetSymbolAddress((void**)&sub, g_sub);
    cudaGetSymbolAddress((void**)&mem, g_mem);
    cudaGetSymbolAddress((void**)&cav, g_cav);
    cudaGetSymbolAddress((void**)&ca,  g_ca);
    cudaGetSymbolAddress((void**)&ahi, g_ahi);
    cudaGetSymbolAddress((void**)&alo, g_alo);
    cudaGetSymbolAddress((void**)&qhi, g_qhi);
    cudaGetSymbolAddress((void**)&qlo, g_qlo);
    cudaGetSymbolAddress((void**)&fhi, g_fhi);
    cudaGetSymbolAddress((void**)&flo, g_flo);
    cudaGetSymbolAddress((void**)&whi, g_whi);
    cudaGetSymbolAddress((void**)&wlo, g_wlo);

    cudaFuncSetAttribute(gemm_hmma,
                         cudaFuncAttributeMaxDynamicSharedMemorySize, HSMEM);
    cudaFuncSetAttribute(attn_hmma,
                         cudaFuncAttributeMaxDynamicSharedMemorySize, ATT_SMEM);

    // ---- weight conversion ----
    conv_pair<<<6*3*DD*DD/1024, 256>>>(sa_w,  whi + O_SAW,  wlo + O_SAW);
    conv_pair<<<6*DD*DD/1024,   256>>>(sa_ow, whi + O_SAOW, wlo + O_SAOW);
    conv_pair<<<6*DFF*DD/1024,  256>>>(ff1_w, whi + O_FF1,  wlo + O_FF1);
    conv_pair<<<6*DD*DFF/1024,  256>>>(ff2_w, whi + O_FF2,  wlo + O_FF2);
    conv_pair<<<VV*DD/1024,     256>>>(fc_w,  whi + O_FC,   wlo + O_FC);

    // ---- embedding + memory projection ----
    embed_kernel<<<M_TOK, 128>>>(tgt, emb, pos, ahi, alo);
    gemm_nt_b<<<dim3(DD/128, 1, 1), 256>>>(z, 0, proj_w, 0, proj_b, 0,
                                           mem, 0, BB, DD, DD);

    // ---- batched cross-attention vectors (all layers) ----
    gemm_nt_b<<<dim3(DD/128, 1, LL), 256>>>(
        mem, 0,
        ca_w + (size_t)2*DD*DD, (size_t)3*DD*DD,
        ca_b + 2*DD, (size_t)3*DD,
        cav, (size_t)BB*DD, BB, DD, DD);
    gemm_nt_b<<<dim3(DD/128, 1, LL), 256>>>(
        cav, (size_t)BB*DD,
        ca_ow, (size_t)DD*DD,
        ca_ob, (size_t)DD,
        ca, (size_t)BB*DD, BB, DD, DD);

    for (int l = 0; l < LL; l++) {
        const float* sabl  = sa_b  + (size_t)l*3*DD;
        const float* saobl = sa_ob + (size_t)l*DD;
        size_t o_qkv = O_SAW  + (size_t)l*3*DD*DD;
        size_t o_ow  = O_SAOW + (size_t)l*DD*DD;
        size_t o_ff1 = O_FF1  + (size_t)l*DFF*DD;
        size_t o_ff2 = O_FF2  + (size_t)l*DD*DFF;

        // self-attention (attn out -> fhi/flo; residual stays in ahi/alo)
        gemm_hmma<<<dim3(12, 128), 256, HSMEM>>>(ahi, alo, whi + o_qkv,
                                                 wlo + o_qkv, sabl, nullptr,
                                                 qhi, qlo, 3*DD, DD, 0, 1);
        attn_hmma<<<BB*HH*4, 256, ATT_SMEM>>>(qhi, qlo, fhi, flo);
        gemm_hmma<<<dim3(4, 128), 256, HSMEM>>>(fhi, flo, whi + o_ow,
                                                wlo + o_ow, saobl, sub,
                                                nullptr, nullptr, DD, DD, 0, 0);
        add_ln2_kernel<<<M_TOK, 128>>>(ahi, alo, sub, ca + (size_t)l*BB*DD,
                                       ln1_s + l*DD, ln1_b + l*DD,
                                       ln2_s + l*DD, ln2_b + l*DD);

        // feed-forward
        gemm_hmma<<<dim3(16, 128), 256, HSMEM>>>(ahi, alo, whi + o_ff1,
                                                 wlo + o_ff1, ff1_b + l*DFF,
                                                 nullptr, fhi, flo,
                                                 DFF, DD, 1, 1);
        gemm_hmma<<<dim3(4, 128), 256, HSMEM>>>(fhi, flo, whi + o_ff2,
                                                wlo + o_ff2, ff2_b + l*DD,
                                                sub, nullptr, nullptr,
                                                DD, DFF, 0, 0);
        add_ln_kernel<<<M_TOK, 128>>>(ahi, alo, sub,
                                      ln3_s + l*DD, ln3_b + l*DD);
    }

    // final classifier
    gemm_hmma<<<dim3(1, 128), 256, HSMEM>>>(ahi, alo, whi + O_FC, wlo + O_FC,
                                            fc_b, out, nullptr, nullptr,
                                            VV, DD, 0, 0);
}

// round 11
// speedup vs baseline: 1.5853x; 1.0023x over previous
#include <cuda_runtime.h>
#include <cuda_bf16.h>
#include <math.h>
#include <stdint.h>

#define BB 64
#define SS 256
#define DD 512
#define HH 8
#define DH 64
#define DFF 2048
#define VV 128
#define LL 6
#define M_TOK (BB*SS)

// ---------------------------------------------------------------------------
// Scratch
// ---------------------------------------------------------------------------
__device__ float g_sub[M_TOK*DD];
__device__ float g_mem[BB*DD];
__device__ float g_cav[LL*BB*DD];
__device__ float g_ca [LL*BB*DD];

// residual stream lives ONLY as bf16 hi/lo (x = hi + lo)
__device__ __nv_bfloat16 g_ahi[(size_t)M_TOK*DD];
__device__ __nv_bfloat16 g_alo[(size_t)M_TOK*DD];
__device__ __nv_bfloat16 g_qhi[(size_t)M_TOK*3*DD];
__device__ __nv_bfloat16 g_qlo[(size_t)M_TOK*3*DD];
__device__ __nv_bfloat16 g_fhi[(size_t)M_TOK*DFF];   // ff1 out / attn out
__device__ __nv_bfloat16 g_flo[(size_t)M_TOK*DFF];

#define O_SAW  0u
#define O_SAOW 4718592u
#define O_FF1  6291456u
#define O_FF2  12582912u
#define O_FC   18874368u
#define WPOOL_E 18940032u
__device__ __nv_bfloat16 g_whi[WPOOL_E];
__device__ __nv_bfloat16 g_wlo[WPOOL_E];

// ---------------------------------------------------------------------------
// Helpers
// ---------------------------------------------------------------------------
__device__ __forceinline__ uint32_t smem_u32(const void* p) {
    uint32_t a;
    asm("{ .reg .u64 t; cvta.to.shared.u64 t, %1; cvt.u32.u64 %0, t; }"
        : "=r"(a) : "l"(p));
    return a;
}
__device__ __forceinline__ void cp_async16(uint32_t dst, const void* src) {
    asm volatile("cp.async.cg.shared.global [%0], [%1], 16;"
                 :: "r"(dst), "l"(src));
}
#define CP_COMMIT() asm volatile("cp.async.commit_group;" ::: "memory")
#define CP_WAIT1()  asm volatile("cp.async.wait_group 1;" ::: "memory")
#define CP_WAIT0()  asm volatile("cp.async.wait_group 0;" ::: "memory")

__device__ __forceinline__ void ldm_x4(uint32_t* r, uint32_t addr) {
    asm volatile("ldmatrix.sync.aligned.m8n8.x4.shared.b16 {%0,%1,%2,%3}, [%4];"
                 : "=r"(r[0]), "=r"(r[1]), "=r"(r[2]), "=r"(r[3]) : "r"(addr));
}
__device__ __forceinline__ void ldm_x4t(uint32_t* r, uint32_t addr) {
    asm volatile("ldmatrix.sync.aligned.m8n8.x4.trans.shared.b16 {%0,%1,%2,%3}, [%4];"
                 : "=r"(r[0]), "=r"(r[1]), "=r"(r[2]), "=r"(r[3]) : "r"(addr));
}
__device__ __forceinline__ void mma_bf16(float* c, const uint32_t* a,
                                         const uint32_t* b) {
    asm volatile(
        "mma.sync.aligned.m16n8k16.row.col.f32.bf16.bf16.f32 "
        "{%0,%1,%2,%3}, {%4,%5,%6,%7}, {%8,%9}, {%0,%1,%2,%3};"
        : "+f"(c[0]), "+f"(c[1]), "+f"(c[2]), "+f"(c[3])
        : "r"(a[0]), "r"(a[1]), "r"(a[2]), "r"(a[3]), "r"(b[0]), "r"(b[1]));
}
__device__ __forceinline__ uint32_t pack2bf(float a, float b) {
    __nv_bfloat162 t = __floats2bfloat162_rn(a, b);
    return *(uint32_t*)&t;
}
__device__ __forceinline__ void split2(float a, float b, uint32_t& hi, uint32_t& lo) {
    __nv_bfloat16 ha = __float2bfloat16_rn(a);
    __nv_bfloat16 hb = __float2bfloat16_rn(b);
    hi = pack2bf(__bfloat162float(ha), __bfloat162float(hb));
    lo = pack2bf(a - __bfloat162float(ha), b - __bfloat162float(hb));
}
__device__ __forceinline__ void join2(uint32_t hi, uint32_t lo, float& a, float& b) {
    __nv_bfloat162 h = *(__nv_bfloat162*)&hi;
    __nv_bfloat162 l = *(__nv_bfloat162*)&lo;
    a = __bfloat162float(h.x) + __bfloat162float(l.x);
    b = __bfloat162float(h.y) + __bfloat162float(l.y);
}

// ---------------------------------------------------------------------------
// Embedding -> hi/lo residual stream only
// ---------------------------------------------------------------------------
__global__ void embed_kernel(const int* __restrict__ tgt,
                             const float* __restrict__ emb,
                             const float* __restrict__ pos,
                             __nv_bfloat16* __restrict__ xhi,
                             __nv_bfloat16* __restrict__ xlo) {
    int row = blockIdx.x;
    int d4  = threadIdx.x;
    int tok = tgt[row];
    int s   = row & (SS - 1);
    float4 e = ((const float4*)(emb + (size_t)tok*DD))[d4];
    float4 p = ((const float4*)(pos + (size_t)s*DD))[d4];
    float4 v = make_float4(e.x+p.x, e.y+p.y, e.z+p.z, e.w+p.w);
    uint32_t h0, l0, h1, l1;
    split2(v.x, v.y, h0, l0);
    split2(v.z, v.w, h1, l1);
    ((uint2*)(xhi + (size_t)row*DD))[d4] = make_uint2(h0, h1);
    ((uint2*)(xlo + (size_t)row*DD))[d4] = make_uint2(l0, l1);
}

// ---------------------------------------------------------------------------
// fp32 -> bf16 hi/lo (weights)
// ---------------------------------------------------------------------------
__global__ void __launch_bounds__(256)
conv_pair(const float* __restrict__ src, __nv_bfloat16* __restrict__ hi,
          __nv_bfloat16* __restrict__ lo) {
    size_t i = (size_t)blockIdx.x * 256 + threadIdx.x;
    float4 v = ((const float4*)src)[i];
    uint32_t h0, l0, h1, l1;
    split2(v.x, v.y, h0, l0);
    split2(v.z, v.w, h1, l1);
    ((uint2*)hi)[i] = make_uint2(h0, h1);
    ((uint2*)lo)[i] = make_uint2(l0, l1);
}

// ---------------------------------------------------------------------------
// PERSISTENT HMMA bf16x3 GEMM. 128x128 tile, 256 threads, 3-stage single-sync
// pipeline per tile. Each CTA loops over tiles: tile += gridDim.x.
// mode 0: fp32 C. mode 1: bf16 hi/lo + opt ReLU.
// ---------------------------------------------------------------------------
#define HSTAGE 65536
#define HSMEM  (3*HSTAGE)

__global__ void __launch_bounds__(256, 1)
gemm_hmma(const __nv_bfloat16* __restrict__ Ahi,
          const __nv_bfloat16* __restrict__ Alo,
          const __nv_bfloat16* __restrict__ Bhi,
          const __nv_bfloat16* __restrict__ Blo,
          const float* __restrict__ bias, float* __restrict__ C,
          __nv_bfloat16* __restrict__ Chi, __nv_bfloat16* __restrict__ Clo,
          int N, int K, int relu, int mode, int ntx, int ntiles) {
    extern __shared__ char smg[];
    const uint32_t sa = smem_u32(smg);
    const int tid = threadIdx.x;
    const int wid = tid >> 5, lane = tid & 31;
    const int wM = wid >> 2, wN = wid & 3;
    const int kc = K >> 6;

    const int laneA_row = lane & 15;
    const int laneA_b   = (lane >> 4) << 4;
    const int laneB_row = ((lane >> 4) << 3) + (lane & 7);
    const int laneB_b   = ((lane >> 3) & 1) << 4;
    const int gid = lane >> 2, tig = lane & 3;

    for (int tile = blockIdx.x; tile < ntiles; tile += gridDim.x) {
        const int bm = (tile / ntx) * 128;
        const int bn = (tile % ntx) * 128;

        __syncthreads();   // protect smem recycle across tile iterations

        float acc[4][4][4];
        #pragma unroll
        for (int i = 0; i < 4; i++)
            #pragma unroll
            for (int j = 0; j < 4; j++)
                #pragma unroll
                for (int e = 0; e < 4; e++) acc[i][j][e] = 0.f;

        auto load_stage = [&](int s, int kk) {
            uint32_t stg = sa + s*HSTAGE;
            #pragma unroll
            for (int i = tid; i < 2048; i += 256) {
                int pool = i >> 10, r = (i >> 3) & 127, c = i & 7;
                const __nv_bfloat16* g =
                    (pool ? Alo : Ahi) + (size_t)(bm + r)*K + kk*64 + c*8;
                cp_async16(stg + pool*16384 + r*128 + ((c*16) ^ ((r & 7) << 4)), g);
            }
            #pragma unroll
            for (int i = tid; i < 2048; i += 256) {
                int pool = i >> 10, r = (i >> 3) & 127, c = i & 7;
                const __nv_bfloat16* g =
                    (pool ? Blo : Bhi) + (size_t)(bn + r)*K + kk*64 + c*8;
                cp_async16(stg + 32768 + pool*16384 + r*128 +
                           ((c*16) ^ ((r & 7) << 4)), g);
            }
        };

        load_stage(0, 0); CP_COMMIT();
        load_stage(1, 1); CP_COMMIT();

        int sidx = 0;
        for (int ch = 0; ch < kc; ch++) {
            CP_WAIT1();
            __syncthreads();

            if (ch + 2 < kc) {
                int st2 = sidx + 2; if (st2 >= 3) st2 -= 3;
                load_stage(st2, ch + 2);
            }
            CP_COMMIT();

            uint32_t stg = sa + sidx*HSTAGE;
            #pragma unroll
            for (int ks = 0; ks < 4; ks++) {
                uint32_t ah[4][4], al[4][4], bh[2][4], bl[2][4];
                #pragma unroll
                for (int mf = 0; mf < 4; mf++) {
                    int r = wM*64 + mf*16 + laneA_row;
                    uint32_t off = r*128 + (((uint32_t)(ks*32 + laneA_b)) ^ ((r & 7) << 4));
                    ldm_x4(ah[mf], stg + off);
                    ldm_x4(al[mf], stg + 16384 + off);
                }
                #pragma unroll
                for (int nf2 = 0; nf2 < 2; nf2++) {
                    int r = wN*32 + nf2*16 + laneB_row;
                    uint32_t off = r*128 + (((uint32_t)(ks*32 + laneB_b)) ^ ((r & 7) << 4));
                    ldm_x4(bh[nf2], stg + 32768 + off);
                    ldm_x4(bl[nf2], stg + 49152 + off);
                }
                #pragma unroll
                for (int mf = 0; mf < 4; mf++)
                    #pragma unroll
                    for (int nf = 0; nf < 4; nf++) {
                        const uint32_t* bhf = &bh[nf >> 1][(nf & 1)*2];
                        const uint32_t* blf = &bl[nf >> 1][(nf & 1)*2];
                        mma_bf16(acc[mf][nf], ah[mf], bhf);
                        mma_bf16(acc[mf][nf], ah[mf], blf);
                        mma_bf16(acc[mf][nf], al[mf], bhf);
                    }
            }
            sidx = (sidx == 2) ? 0 : sidx + 1;
        }

        #pragma unroll
        for (int mf = 0; mf < 4; mf++) {
            int r0 = bm + wM*64 + mf*16 + gid;
            #pragma unroll
            for (int nf = 0; nf < 4; nf++) {
                int col = bn + wN*32 + nf*8 + tig*2;
                float bx = __ldg(bias + col), by = __ldg(bias + col + 1);
                float v0x = acc[mf][nf][0] + bx, v0y = acc[mf][nf][1] + by;
                float v1x = acc[mf][nf][2] + bx, v1y = acc[mf][nf][3] + by;
                if (relu) {
                    v0x = fmaxf(v0x, 0.f); v0y = fmaxf(v0y, 0.f);
                    v1x = fmaxf(v1x, 0.f); v1y = fmaxf(v1y, 0.f);
                }
                if (mode == 0) {
                    *(float2*)(C + (size_t)r0*N + col)       = make_float2(v0x, v0y);
                    *(float2*)(C + (size_t)(r0 + 8)*N + col) = make_float2(v1x, v1y);
                } else {
                    uint32_t h, l;
                    size_t i0 = (size_t)r0*N + col, i1 = (size_t)(r0 + 8)*N + col;
                    split2(v0x, v0y, h, l);
                    *(uint32_t*)(Chi + i0) = h; *(uint32_t*)(Clo + i0) = l;
                    split2(v1x, v1y, h, l);
                    *(uint32_t*)(Chi + i1) = h; *(uint32_t*)(Clo + i1) = l;
                }
            }
        }
    }
}

// ---------------------------------------------------------------------------
// HMMA causal attention (unchanged from R10)
// ---------------------------------------------------------------------------
#define OQH 0
#define OQL 8192
#define OKH 16384
#define OKL 49152
#define OVH 81920
#define OVL 114688
#define OPH 147456
#define OPL 180224
#define ORED 212992
#define ATT_SMEM (ORED + 1024)

__global__ void __launch_bounds__(256, 1)
attn_hmma(const __nv_bfloat16* __restrict__ qhi,
          const __nv_bfloat16* __restrict__ qlo,
          __nv_bfloat16* __restrict__ ohi,
          __nv_bfloat16* __restrict__ olo) {
    extern __shared__ char smg[];
    const uint32_t sa = smem_u32(smg);
    const int tid = threadIdx.x;
    const int wid = tid >> 5, lane = tid & 31;
    const int wM = wid >> 1, wN = wid & 1;
    const int gid = lane >> 2, tig = lane & 3;

    const int bid = blockIdx.x;
    const int qb = bid & 3;
    const int h  = (bid >> 2) & 7;
    const int b  = bid >> 5;
    const int krows = (qb + 1) * 64;

    auto load_tile = [&](const __nv_bfloat16* g, uint32_t sbase, int rows) {
        for (int i = tid; i < rows*8; i += 256) {
            int r = i >> 3, c = i & 7;
            cp_async16(sa + sbase + r*128 + ((c*16) ^ ((r & 7) << 4)),
                       g + (size_t)r*1536 + c*8);
        }
    };
    const size_t qbase = (size_t)(b*SS + qb*64)*1536 + h*DH;
    const size_t kbase = (size_t)(b*SS)*1536 + DD + h*DH;
    const size_t vbase = (size_t)(b*SS)*1536 + 2*DD + h*DH;
    load_tile(qhi + qbase, OQH, 64);
    load_tile(qlo + qbase, OQL, 64);
    load_tile(qhi + kbase, OKH, krows);
    load_tile(qlo + kbase, OKL, krows);
    CP_COMMIT();
    load_tile(qhi + vbase, OVH, krows);
    load_tile(qlo + vbase, OVL, krows);
    CP_COMMIT();
    CP_WAIT1();
    __syncthreads();

    const int laneA_row = lane & 15;
    const int laneA_b   = (lane >> 4) << 4;
    const int laneB_row = ((lane >> 4) << 3) + (lane & 7);
    const int laneB_b   = ((lane >> 3) & 1) << 4;

    float s[16][4];
    #pragma unroll
    for (int nt = 0; nt < 16; nt++)
        #pragma unroll
        for (int e = 0; e < 4; e++) s[nt][e] = 0.f;

    #pragma unroll
    for (int ks = 0; ks < 4; ks++) {
        uint32_t ah[4], al[4];
        {
            int r = wM*16 + laneA_row;
            uint32_t off = r*128 + (((uint32_t)(ks*32 + laneA_b)) ^ ((r & 7) << 4));
            ldm_x4(ah, sa + OQH + off);
            ldm_x4(al, sa + OQL + off);
        }
        #pragma unroll
        for (int ng = 0; ng < 8; ng++) {
            uint32_t bh4[4], bl4[4];
            int r = wN*128 + ng*16 + laneB_row;
            uint32_t off = r*128 + (((uint32_t)(ks*32 + laneB_b)) ^ ((r & 7) << 4));
            ldm_x4(bh4, sa + OKH + off);
            ldm_x4(bl4, sa + OKL + off);
            #pragma unroll
            for (int j = 0; j < 2; j++) {
                float* a = s[ng*2 + j];
                mma_bf16(a, ah, &bh4[j*2]);
                mma_bf16(a, ah, &bl4[j*2]);
                mma_bf16(a, al, &bh4[j*2]);
            }
        }
    }

    const int qrow0 = qb*64 + wM*16 + gid;
    const int qrow1 = qrow0 + 8;
    float m0 = -1e30f, m1 = -1e30f;
    #pragma unroll
    for (int nt = 0; nt < 16; nt++) {
        int c0 = wN*128 + nt*8 + tig*2;
        s[nt][0] = (c0     <= qrow0) ? s[nt][0]*0.125f : -1e30f;
        s[nt][1] = (c0 + 1 <= qrow0) ? s[nt][1]*0.125f : -1e30f;
        s[nt][2] = (c0     <= qrow1) ? s[nt][2]*0.125f : -1e30f;
        s[nt][3] = (c0 + 1 <= qrow1) ? s[nt][3]*0.125f : -1e30f;
        m0 = fmaxf(m0, fmaxf(s[nt][0], s[nt][1]));
        m1 = fmaxf(m1, fmaxf(s[nt][2], s[nt][3]));
    }
    #pragma unroll
    for (int o = 1; o <= 2; o <<= 1) {
        m0 = fmaxf(m0, __shfl_xor_sync(~0u, m0, o));
        m1 = fmaxf(m1, __shfl_xor_sync(~0u, m1, o));
    }
    float* redm = (float*)(smg + ORED);
    float* reds = (float*)(smg + ORED + 512);
    int r0l = wM*16 + gid;
    if (tig == 0) { redm[wN*64 + r0l] = m0; redm[wN*64 + r0l + 8] = m1; }
    __syncthreads();
    m0 = fmaxf(redm[r0l],     redm[64 + r0l]);
    m1 = fmaxf(redm[r0l + 8], redm[64 + r0l + 8]);

    float sum0 = 0.f, sum1 = 0.f;
    #pragma unroll
    for (int nt = 0; nt < 16; nt++) {
        s[nt][0] = __expf(s[nt][0] - m0);
        s[nt][1] = __expf(s[nt][1] - m0);
        s[nt][2] = __expf(s[nt][2] - m1);
        s[nt][3] = __expf(s[nt][3] - m1);
        sum0 += s[nt][0] + s[nt][1];
        sum1 += s[nt][2] + s[nt][3];
    }
    #pragma unroll
    for (int o = 1; o <= 2; o <<= 1) {
        sum0 += __shfl_xor_sync(~0u, sum0, o);
        sum1 += __shfl_xor_sync(~0u, sum1, o);
    }
    if (tig == 0) { reds[wN*64 + r0l] = sum0; reds[wN*64 + r0l + 8] = sum1; }
    __syncthreads();
    float inv0 = 1.f / (reds[r0l]     + reds[64 + r0l]);
    float inv1 = 1.f / (reds[r0l + 8] + reds[64 + r0l + 8]);

    #pragma unroll
    for (int nt = 0; nt < 16; nt++) {
        int c0 = wN*128 + nt*8 + tig*2;
        int kb = c0 >> 6, cb = c0 & 63;
        uint32_t sw0 = (uint32_t)(cb*2) ^ ((r0l & 7) << 4);
        uint32_t sw1 = (uint32_t)(cb*2) ^ (((r0l + 8) & 7) << 4);
        uint32_t off0 = kb*8192 + r0l*128 + sw0;
        uint32_t off1 = kb*8192 + (r0l + 8)*128 + sw1;
        uint32_t h, l;
        split2(s[nt][0]*inv0, s[nt][1]*inv0, h, l);
        *(uint32_t*)(smg + OPH + off0) = h;
        *(uint32_t*)(smg + OPL + off0) = l;
        split2(s[nt][2]*inv1, s[nt][3]*inv1, h, l);
        *(uint32_t*)(smg + OPH + off1) = h;
        *(uint32_t*)(smg + OPL + off1) = l;
    }
    CP_WAIT0();
    __syncthreads();

    float o[4][4];
    #pragma unroll
    for (int nt = 0; nt < 4; nt++)
        #pragma unroll
        for (int e = 0; e < 4; e++) o[nt][e] = 0.f;

    const int vlrow = lane & 15;
    const uint32_t cbyte0 = (uint32_t)(wN*64 + ((lane >> 4) << 4));
    for (int kb = 0; kb <= qb; kb++) {
        #pragma unroll
        for (int ks = 0; ks < 4; ks++) {
            uint32_t ph4[4], pl4[4];
            {
                int r = wM*16 + laneA_row;
                uint32_t off = kb*8192 + r*128 +
                               (((uint32_t)(ks*32 + laneA_b)) ^ ((r & 7) << 4));
                ldm_x4(ph4, sa + OPH + off);
                ldm_x4(pl4, sa + OPL + off);
            }
            int vr = kb*64 + ks*16 + vlrow;
            #pragma unroll
            for (int chh = 0; chh < 2; chh++) {
                uint32_t vh4[4], vl4[4];
                uint32_t voff = vr*128 + ((cbyte0 + chh*32) ^ ((vr & 7) << 4));
                ldm_x4t(vh4, sa + OVH + voff);
                ldm_x4t(vl4, sa + OVL + voff);
                #pragma unroll
                for (int j = 0; j < 2; j++) {
                    float* a = o[chh*2 + j];
                    mma_bf16(a, ph4, &vh4[j*2]);
                    mma_bf16(a, ph4, &vl4[j*2]);
                    mma_bf16(a, pl4, &vh4[j*2]);
                }
            }
        }
    }

    const int gr0 = b*SS + qb*64 + wM*16 + gid;
    #pragma unroll
    for (int nt = 0; nt < 4; nt++) {
        int col = h*DH + wN*32 + nt*8 + tig*2;
        uint32_t h0, l0, h1, l1;
        split2(o[nt][0], o[nt][1], h0, l0);
        split2(o[nt][2], o[nt][3], h1, l1);
        size_t i0 = (size_t)gr0*DD + col, i1 = (size_t)(gr0 + 8)*DD + col;
        *(uint32_t*)(ohi + i0) = h0; *(uint32_t*)(olo + i0) = l0;
        *(uint32_t*)(ohi + i1) = h1; *(uint32_t*)(olo + i1) = l1;
    }
}

// ---------------------------------------------------------------------------
// fp32 SIMT NT GEMM, z-batched
// ---------------------------------------------------------------------------
__global__ void __launch_bounds__(256)
gemm_nt_b(const float* __restrict__ A, size_t astr,
          const float* __restrict__ B, size_t bstr,
          const float* __restrict__ bias, size_t bistr,
          float* __restrict__ C, size_t cstr,
          int M, int N, int K) {
    const int zz = blockIdx.z;
    A += zz*astr; B += zz*bstr; bias += zz*bistr; C += zz*cstr;

    __shared__ float As[8][128];
    __shared__ float Bs[8][128];
    const int bm = blockIdx.y * 128;
    const int bn = blockIdx.x * 128;
    const int tid = threadIdx.x;
    const int tx = tid & 15, ty = tid >> 4;
    const int lr = tid >> 1, lc = (tid & 1) * 4;
    const int arow = min(bm + lr, M - 1);
    const int brow = bn + lr;

    float acc[8][8];
    #pragma unroll
    for (int i = 0; i < 8; i++)
        #pragma unroll
        for (int j = 0; j < 8; j++) acc[i][j] = 0.f;

    for (int kt = 0; kt < K; kt += 8) {
        {
            float4 v = *(const float4*)(A + (size_t)arow*K + kt + lc);
            As[lc+0][lr] = v.x; As[lc+1][lr] = v.y;
            As[lc+2][lr] = v.z; As[lc+3][lr] = v.w;
        }
        {
            float4 v = *(const float4*)(B + (size_t)brow*K + kt + lc);
            Bs[lc+0][lr] = v.x; Bs[lc+1][lr] = v.y;
            Bs[lc+2][lr] = v.z; Bs[lc+3][lr] = v.w;
        }
        __syncthreads();
        #pragma unroll
        for (int k = 0; k < 8; k++) {
            float a[8], b[8];
            #pragma unroll
            for (int i = 0; i < 8; i++) a[i] = As[k][ty*8 + i];
            #pragma unroll
            for (int j = 0; j < 8; j++) b[j] = Bs[k][tx*8 + j];
            #pragma unroll
            for (int i = 0; i < 8; i++)
                #pragma unroll
                for (int j = 0; j < 8; j++)
                    acc[i][j] = fmaf(a[i], b[j], acc[i][j]);
        }
        __syncthreads();
    }
    #pragma unroll
    for (int i = 0; i < 8; i++) {
        int row = bm + ty*8 + i;
        if (row >= M) continue;
        #pragma unroll
        for (int j = 0; j < 8; j++) {
            int col = bn + tx*8 + j;
            C[(size_t)row*N + col] = acc[i][j] + bias[col];
        }
    }
}

// ---------------------------------------------------------------------------
// LN body (device helper)
// ---------------------------------------------------------------------------
__device__ __forceinline__ void ln_block(float* v, const float4 gv,
                                         const float4 bv, int t,
                                         float* red, float* o) {
    float sum = v[0] + v[1] + v[2] + v[3];
    #pragma unroll
    for (int oo = 16; oo; oo >>= 1) sum += __shfl_xor_sync(~0u, sum, oo);
    if ((t & 31) == 0) red[t >> 5] = sum;
    __syncthreads();
    float mean = (red[0] + red[1] + red[2] + red[3]) * (1.f/512.f);
    float var = 0.f;
    #pragma unroll
    for (int i = 0; i < 4; i++) {
        float d = v[i] - mean;
        var = fmaf(d, d, var);
    }
    #pragma unroll
    for (int oo = 16; oo; oo >>= 1) var += __shfl_xor_sync(~0u, var, oo);
    if ((t & 31) == 0) red[4 + (t >> 5)] = var;
    __syncthreads();
    float rs = rsqrtf((red[4] + red[5] + red[6] + red[7]) * (1.f/512.f) + 1e-5f);
    o[0] = (v[0] - mean) * rs * gv.x + bv.x;
    o[1] = (v[1] - mean) * rs * gv.y + bv.y;
    o[2] = (v[2] - mean) * rs * gv.z + bv.z;
    o[3] = (v[3] - mean) * rs * gv.w + bv.w;
}

__global__ void __launch_bounds__(128)
add_ln_kernel(__nv_bfloat16* __restrict__ xhi, __nv_bfloat16* __restrict__ xlo,
              const float* __restrict__ r,
              const float* __restrict__ g, const float* __restrict__ bt) {
    int row = blockIdx.x;
    const float* rp = r + (size_t)row*DD;
    int t = threadIdx.x;
    __shared__ float red[8];

    uint2 hp = ((const uint2*)(xhi + (size_t)row*DD))[t];
    uint2 lp = ((const uint2*)(xlo + (size_t)row*DD))[t];
    float v[4];
    join2(hp.x, lp.x, v[0], v[1]);
    join2(hp.y, lp.y, v[2], v[3]);
    float4 rv = ((const float4*)rp)[t];
    v[0] += rv.x; v[1] += rv.y; v[2] += rv.z; v[3] += rv.w;

    float o[4];
    ln_block(v, ((const float4*)g)[t], ((const float4*)bt)[t], t, red, o);
    uint32_t h0, l0, h1, l1;
    split2(o[0], o[1], h0, l0);
    split2(o[2], o[3], h1, l1);
    ((uint2*)(xhi + (size_t)row*DD))[t] = make_uint2(h0, h1);
    ((uint2*)(xlo + (size_t)row*DD))[t] = make_uint2(l0, l1);
}

__global__ void __launch_bounds__(128)
add_ln2_kernel(__nv_bfloat16* __restrict__ xhi, __nv_bfloat16* __restrict__ xlo,
               const float* __restrict__ sub, const float* __restrict__ ca,
               const float* __restrict__ g1, const float* __restrict__ b1,
               const float* __restrict__ g2, const float* __restrict__ b2) {
    int row = blockIdx.x;
    const float* sp = sub + (size_t)row*DD;
    const float* cp = ca + (size_t)(row >> 8)*DD;
    int t = threadIdx.x;
    __shared__ float red[8];

    uint2 hp = ((const uint2*)(xhi + (size_t)row*DD))[t];
    uint2 lp = ((const uint2*)(xlo + (size_t)row*DD))[t];
    float v[4];
    join2(hp.x, lp.x, v[0], v[1]);
    join2(hp.y, lp.y, v[2], v[3]);
    float4 sv = ((const float4*)sp)[t];
    v[0] += sv.x; v[1] += sv.y; v[2] += sv.z; v[3] += sv.w;

    float y1[4];
    ln_block(v, ((const float4*)g1)[t], ((const float4*)b1)[t], t, red, y1);
    __syncthreads();

    float4 cv = ((const float4*)cp)[t];
    float v2[4] = {y1[0]+cv.x, y1[1]+cv.y, y1[2]+cv.z, y1[3]+cv.w};
    float o[4];
    ln_block(v2, ((const float4*)g2)[t], ((const float4*)b2)[t], t, red, o);
    uint32_t h0, l0, h1, l1;
    split2(o[0], o[1], h0, l0);
    split2(o[2], o[3], h1, l1);
    ((uint2*)(xhi + (size_t)row*DD))[t] = make_uint2(h0, h1);
    ((uint2*)(xlo + (size_t)row*DD))[t] = make_uint2(l0, l1);
}

// ---------------------------------------------------------------------------
// Launch
// ---------------------------------------------------------------------------
extern "C" void kernel_launch(void* const* d_in, const int* in_sizes, int n_in,
                              void* d_out, int out_size) {
    const float* z      = (const float*)d_in[0];
    const int*   tgt    = (const int*)  d_in[1];
    const float* emb    = (const float*)d_in[2];
    const float* pos    = (const float*)d_in[3];
    const float* proj_w = (const float*)d_in[4];
    const float* proj_b = (const float*)d_in[5];
    const float* sa_w   = (const float*)d_in[6];
    const float* sa_b   = (const float*)d_in[7];
    const float* sa_ow  = (const float*)d_in[8];
    const float* sa_ob  = (const float*)d_in[9];
    const float* ca_w   = (const float*)d_in[10];
    const float* ca_b   = (const float*)d_in[11];
    const float* ca_ow  = (const float*)d_in[12];
    const float* ca_ob  = (const float*)d_in[13];
    const float* ln1_s  = (const float*)d_in[14];
    const float* ln1_b  = (const float*)d_in[15];
    const float* ln2_s  = (const float*)d_in[16];
    const float* ln2_b  = (const float*)d_in[17];
    const float* ln3_s  = (const float*)d_in[18];
    const float* ln3_b  = (const float*)d_in[19];
    const float* ff1_w  = (const float*)d_in[20];
    const float* ff1_b  = (const float*)d_in[21];
    const float* ff2_w  = (const float*)d_in[22];
    const float* ff2_b  = (const float*)d_in[23];
    const float* fc_w   = (const float*)d_in[24];
    const float* fc_b   = (const float*)d_in[25];
    float* out = (float*)d_out;

    float *sub, *mem, *cav, *ca;
    __nv_bfloat16 *ahi, *alo, *qhi, *qlo, *fhi, *flo, *whi, *wlo;
    cudaGetSymbolAddress((void**)&sub, g_sub);
    cudaGetSymbolAddress((void**)&mem, g_mem);
    cudaGetSymbolAddress((void**)&cav, g_cav);
    cudaGetSymbolAddress((void**)&ca,  g_ca);
    cudaGetSymbolAddress((void**)&ahi, g_ahi);
    cudaGetSymbolAddress((void**)&alo, g_alo);
    cudaGetSymbolAddress((void**)&qhi, g_qhi);
    cudaGetSymbolAddress((void**)&qlo, g_qlo);
    cudaGetSymbolAddress((void**)&fhi, g_fhi);
    cudaGetSymbolAddress((void**)&flo, g_flo);
    cudaGetSymbolAddress((void**)&whi, g_whi);
    cudaGetSymbolAddress((void**)&wlo, g_wlo);

    cudaFuncSetAttribute(gemm_hmma,
                         cudaFuncAttributeMaxDynamicSharedMemorySize, HSMEM);
    cudaFuncSetAttribute(attn_hmma,
                         cudaFuncAttributeMaxDynamicSharedMemorySize, ATT_SMEM);

    // ---- weight conversion ----
    conv_pair<<<6*3*DD*DD/1024, 256>>>(sa_w,  whi + O_SAW,  wlo + O_SAW);
    conv_pair<<<6*DD*DD/1024,   256>>>(sa_ow, whi + O_SAOW, wlo + O_SAOW);
    conv_pair<<<6*DFF*DD/1024,  256>>>(ff1_w, whi + O_FF1,  wlo + O_FF1);
    conv_pair<<<6*DD*DFF/1024,  256>>>(ff2_w, whi + O_FF2,  wlo + O_FF2);
    conv_pair<<<VV*DD/1024,     256>>>(fc_w,  whi + O_FC,   wlo + O_FC);

    // ---- embedding + memory projection ----
    embed_kernel<<<M_TOK, 128>>>(tgt, emb, pos, ahi, alo);
    gemm_nt_b<<<dim3(DD/128, 1, 1), 256>>>(z, 0, proj_w, 0, proj_b, 0,
                                           mem, 0, BB, DD, DD);

    // ---- batched cross-attention vectors (all layers) ----
    gemm_nt_b<<<dim3(DD/128, 1, LL), 256>>>(
        mem, 0,
        ca_w + (size_t)2*DD*DD, (size_t)3*DD*DD,
        ca_b + 2*DD, (size_t)3*DD,
        cav, (size_t)BB*DD, BB, DD, DD);
    gemm_nt_b<<<dim3(DD/128, 1, LL), 256>>>(
        cav, (size_t)BB*DD,
        ca_ow, (size_t)DD*DD,
        ca_ob, (size_t)DD,
        ca, (size_t)BB*DD, BB, DD, DD);

    const int PGRID = 148;   // persistent grid (1 CTA/SM)

    for (int l = 0; l < LL; l++) {
        const float* sabl  = sa_b  + (size_t)l*3*DD;
        const float* saobl = sa_ob + (size_t)l*DD;
        size_t o_qkv = O_SAW  + (size_t)l*3*DD*DD;
        size_t o_ow  = O_SAOW + (size_t)l*DD*DD;
        size_t o_ff1 = O_FF1  + (size_t)l*DFF*DD;
        size_t o_ff2 = O_FF2  + (size_t)l*DD*DFF;

        // self-attention (attn out -> fhi/flo; residual stays in ahi/alo)
        gemm_hmma<<<PGRID, 256, HSMEM>>>(ahi, alo, whi + o_qkv, wlo + o_qkv,
                                         sabl, nullptr, qhi, qlo,
                                         3*DD, DD, 0, 1, 12, 12*128);
        attn_hmma<<<BB*HH*4, 256, ATT_SMEM>>>(qhi, qlo, fhi, flo);
        gemm_hmma<<<PGRID, 256, HSMEM>>>(fhi, flo, whi + o_ow, wlo + o_ow,
                                         saobl, sub, nullptr, nullptr,
                                         DD, DD, 0, 0, 4, 4*128);
        add_ln2_kernel<<<M_TOK, 128>>>(ahi, alo, sub, ca + (size_t)l*BB*DD,
                                       ln1_s + l*DD, ln1_b + l*DD,
                                       ln2_s + l*DD, ln2_b + l*DD);

        // feed-forward
        gemm_hmma<<<PGRID, 256, HSMEM>>>(ahi, alo, whi + o_ff1, wlo + o_ff1,
                                         ff1_b + l*DFF, nullptr, fhi, flo,
                                         DFF, DD, 1, 1, 16, 16*128);
        gemm_hmma<<<PGRID, 256, HSMEM>>>(fhi, flo, whi + o_ff2, wlo + o_ff2,
                                         ff2_b + l*DD, sub, nullptr, nullptr,
                                         DD, DFF, 0, 0, 4, 4*128);
        add_ln_kernel<<<M_TOK, 128>>>(ahi, alo, sub,
                                      ln3_s + l*DD, ln3_b + l*DD);
    }

    // final classifier
    gemm_hmma<<<128, 256, HSMEM>>>(ahi, alo, whi + O_FC, wlo + O_FC,
                                   fc_b, out, nullptr, nullptr,
                                   VV, DD, 0, 0, 1, 128);
}

// round 12
// speedup vs baseline: 1.5915x; 1.0039x over previous
#include <cuda_runtime.h>
#include <cuda_bf16.h>
#include <math.h>
#include <stdint.h>

#define BB 64
#define SS 256
#define DD 512
#define HH 8
#define DH 64
#define DFF 2048
#define VV 128
#define LL 6
#define M_TOK (BB*SS)

// ---------------------------------------------------------------------------
// Scratch
// ---------------------------------------------------------------------------
__device__ float g_sub[M_TOK*DD];
__device__ float g_mem[BB*DD];
__device__ float g_cav[LL*BB*DD];
__device__ float g_ca [LL*BB*DD];

__device__ __nv_bfloat16 g_ahi[(size_t)M_TOK*DD];
__device__ __nv_bfloat16 g_alo[(size_t)M_TOK*DD];
__device__ __nv_bfloat16 g_qhi[(size_t)M_TOK*3*DD];
__device__ __nv_bfloat16 g_qlo[(size_t)M_TOK*3*DD];
__device__ __nv_bfloat16 g_fhi[(size_t)M_TOK*DFF];
__device__ __nv_bfloat16 g_flo[(size_t)M_TOK*DFF];

#define O_SAW  0u
#define O_SAOW 4718592u
#define O_FF1  6291456u
#define O_FF2  12582912u
#define O_FC   18874368u
#define WPOOL_E 18940032u
__device__ __nv_bfloat16 g_whi[WPOOL_E];
__device__ __nv_bfloat16 g_wlo[WPOOL_E];

// ---------------------------------------------------------------------------
// Helpers
// ---------------------------------------------------------------------------
__device__ __forceinline__ uint32_t smem_u32(const void* p) {
    uint32_t a;
    asm("{ .reg .u64 t; cvta.to.shared.u64 t, %1; cvt.u32.u64 %0, t; }"
        : "=r"(a) : "l"(p));
    return a;
}
__device__ __forceinline__ void cp_async16(uint32_t dst, const void* src) {
    asm volatile("cp.async.cg.shared.global [%0], [%1], 16;"
                 :: "r"(dst), "l"(src));
}
#define CP_COMMIT() asm volatile("cp.async.commit_group;" ::: "memory")
#define CP_WAIT1()  asm volatile("cp.async.wait_group 1;" ::: "memory")
#define CP_WAIT0()  asm volatile("cp.async.wait_group 0;" ::: "memory")

__device__ __forceinline__ void ldm_x4(uint32_t* r, uint32_t addr) {
    asm volatile("ldmatrix.sync.aligned.m8n8.x4.shared.b16 {%0,%1,%2,%3}, [%4];"
                 : "=r"(r[0]), "=r"(r[1]), "=r"(r[2]), "=r"(r[3]) : "r"(addr));
}
__device__ __forceinline__ void ldm_x4t(uint32_t* r, uint32_t addr) {
    asm volatile("ldmatrix.sync.aligned.m8n8.x4.trans.shared.b16 {%0,%1,%2,%3}, [%4];"
                 : "=r"(r[0]), "=r"(r[1]), "=r"(r[2]), "=r"(r[3]) : "r"(addr));
}
__device__ __forceinline__ void mma_bf16(float* c, const uint32_t* a,
                                         const uint32_t* b) {
    asm volatile(
        "mma.sync.aligned.m16n8k16.row.col.f32.bf16.bf16.f32 "
        "{%0,%1,%2,%3}, {%4,%5,%6,%7}, {%8,%9}, {%0,%1,%2,%3};"
        : "+f"(c[0]), "+f"(c[1]), "+f"(c[2]), "+f"(c[3])
        : "r"(a[0]), "r"(a[1]), "r"(a[2]), "r"(a[3]), "r"(b[0]), "r"(b[1]));
}
__device__ __forceinline__ uint32_t pack2bf(float a, float b) {
    __nv_bfloat162 t = __floats2bfloat162_rn(a, b);
    return *(uint32_t*)&t;
}
__device__ __forceinline__ void split2(float a, float b, uint32_t& hi, uint32_t& lo) {
    __nv_bfloat16 ha = __float2bfloat16_rn(a);
    __nv_bfloat16 hb = __float2bfloat16_rn(b);
    hi = pack2bf(__bfloat162float(ha), __bfloat162float(hb));
    lo = pack2bf(a - __bfloat162float(ha), b - __bfloat162float(hb));
}
__device__ __forceinline__ void join2(uint32_t hi, uint32_t lo, float& a, float& b) {
    __nv_bfloat162 h = *(__nv_bfloat162*)&hi;
    __nv_bfloat162 l = *(__nv_bfloat162*)&lo;
    a = __bfloat162float(h.x) + __bfloat162float(l.x);
    b = __bfloat162float(h.y) + __bfloat162float(l.y);
}

// ---------------------------------------------------------------------------
// Embedding -> hi/lo residual stream only
// ---------------------------------------------------------------------------
__global__ void embed_kernel(const int* __restrict__ tgt,
                             const float* __restrict__ emb,
                             const float* __restrict__ pos,
                             __nv_bfloat16* __restrict__ xhi,
                             __nv_bfloat16* __restrict__ xlo) {
    int row = blockIdx.x;
    int d4  = threadIdx.x;
    int tok = tgt[row];
    int s   = row & (SS - 1);
    float4 e = ((const float4*)(emb + (size_t)tok*DD))[d4];
    float4 p = ((const float4*)(pos + (size_t)s*DD))[d4];
    float4 v = make_float4(e.x+p.x, e.y+p.y, e.z+p.z, e.w+p.w);
    uint32_t h0, l0, h1, l1;
    split2(v.x, v.y, h0, l0);
    split2(v.z, v.w, h1, l1);
    ((uint2*)(xhi + (size_t)row*DD))[d4] = make_uint2(h0, h1);
    ((uint2*)(xlo + (size_t)row*DD))[d4] = make_uint2(l0, l1);
}

// ---------------------------------------------------------------------------
// fp32 -> bf16 hi/lo (weights)
// ---------------------------------------------------------------------------
__global__ void __launch_bounds__(256)
conv_pair(const float* __restrict__ src, __nv_bfloat16* __restrict__ hi,
          __nv_bfloat16* __restrict__ lo) {
    size_t i = (size_t)blockIdx.x * 256 + threadIdx.x;
    float4 v = ((const float4*)src)[i];
    uint32_t h0, l0, h1, l1;
    split2(v.x, v.y, h0, l0);
    split2(v.z, v.w, h1, l1);
    ((uint2*)hi)[i] = make_uint2(h0, h1);
    ((uint2*)lo)[i] = make_uint2(l0, l1);
}

// ---------------------------------------------------------------------------
// PERSISTENT HMMA bf16x3 GEMM. 128x128 tile, 256 threads, 3-stage single-sync
// pipeline. Loader addresses PRECOMPUTED per tile (hoisted out of the chunk
// loop) — load_stage is 16 x (add + cp.async).
// mode 0: fp32 C. mode 1: bf16 hi/lo + opt ReLU.
// ---------------------------------------------------------------------------
#define HSTAGE 65536
#define HSMEM  (3*HSTAGE)

__global__ void __launch_bounds__(256, 1)
gemm_hmma(const __nv_bfloat16* __restrict__ Ahi,
          const __nv_bfloat16* __restrict__ Alo,
          const __nv_bfloat16* __restrict__ Bhi,
          const __nv_bfloat16* __restrict__ Blo,
          const float* __restrict__ bias, float* __restrict__ C,
          __nv_bfloat16* __restrict__ Chi, __nv_bfloat16* __restrict__ Clo,
          int N, int K, int relu, int mode, int ntx, int ntiles) {
    extern __shared__ char smg[];
    const uint32_t sa = smem_u32(smg);
    const int tid = threadIdx.x;
    const int wid = tid >> 5, lane = tid & 31;
    const int wM = wid >> 2, wN = wid & 3;
    const int kc = K >> 6;

    const int laneA_row = lane & 15;
    const int laneA_b   = (lane >> 4) << 4;
    const int laneB_row = ((lane >> 4) << 3) + (lane & 7);
    const int laneB_b   = ((lane >> 3) & 1) << 4;
    const int gid = lane >> 2, tig = lane & 3;

    // per-thread loader decode (tile-independent parts)
    int dec_pool[8], dec_r[8];
    uint32_t offA[8], offB[8];
    #pragma unroll
    for (int it = 0; it < 8; it++) {
        int i = tid + it*256;
        int pool = i >> 10, r = (i >> 3) & 127, c = i & 7;
        dec_pool[it] = pool; dec_r[it] = r;
        uint32_t sw = (uint32_t)((c*16) ^ ((r & 7) << 4));
        offA[it] = pool*16384 + r*128 + sw;
        offB[it] = 32768 + pool*16384 + r*128 + sw;
    }

    for (int tile = blockIdx.x; tile < ntiles; tile += gridDim.x) {
        const int bm = (tile / ntx) * 128;
        const int bn = (tile % ntx) * 128;

        // per-tile GMEM base pointers (advance by kk*128 bytes per chunk)
        const char* srcA[8];
        const char* srcB[8];
        #pragma unroll
        for (int it = 0; it < 8; it++) {
            int i = tid + it*256;
            int c = i & 7;
            srcA[it] = (const char*)((dec_pool[it] ? Alo : Ahi) +
                                     (size_t)(bm + dec_r[it])*K + c*8);
            srcB[it] = (const char*)((dec_pool[it] ? Blo : Bhi) +
                                     (size_t)(bn + dec_r[it])*K + c*8);
        }

        __syncthreads();   // protect smem recycle across tile iterations

        float acc[4][4][4];
        #pragma unroll
        for (int i = 0; i < 4; i++)
            #pragma unroll
            for (int j = 0; j < 4; j++)
                #pragma unroll
                for (int e = 0; e < 4; e++) acc[i][j][e] = 0.f;

        auto load_stage = [&](int s, int kk) {
            uint32_t stg = sa + s*HSTAGE;
            int kb = kk << 7;     // kk*128 bytes
            #pragma unroll
            for (int it = 0; it < 8; it++)
                cp_async16(stg + offA[it], srcA[it] + kb);
            #pragma unroll
            for (int it = 0; it < 8; it++)
                cp_async16(stg + offB[it], srcB[it] + kb);
        };

        load_stage(0, 0); CP_COMMIT();
        load_stage(1, 1); CP_COMMIT();

        int sidx = 0;
        for (int ch = 0; ch < kc; ch++) {
            CP_WAIT1();
            __syncthreads();

            if (ch + 2 < kc) {
                int st2 = sidx + 2; if (st2 >= 3) st2 -= 3;
                load_stage(st2, ch + 2);
            }
            CP_COMMIT();

            uint32_t stg = sa + sidx*HSTAGE;
            #pragma unroll
            for (int ks = 0; ks < 4; ks++) {
                uint32_t ah[4][4], al[4][4], bh[2][4], bl[2][4];
                #pragma unroll
                for (int mf = 0; mf < 4; mf++) {
                    int r = wM*64 + mf*16 + laneA_row;
                    uint32_t off = r*128 + (((uint32_t)(ks*32 + laneA_b)) ^ ((r & 7) << 4));
                    ldm_x4(ah[mf], stg + off);
                    ldm_x4(al[mf], stg + 16384 + off);
                }
                #pragma unroll
                for (int nf2 = 0; nf2 < 2; nf2++) {
                    int r = wN*32 + nf2*16 + laneB_row;
                    uint32_t off = r*128 + (((uint32_t)(ks*32 + laneB_b)) ^ ((r & 7) << 4));
                    ldm_x4(bh[nf2], stg + 32768 + off);
                    ldm_x4(bl[nf2], stg + 49152 + off);
                }
                #pragma unroll
                for (int mf = 0; mf < 4; mf++)
                    #pragma unroll
                    for (int nf = 0; nf < 4; nf++) {
                        const uint32_t* bhf = &bh[nf >> 1][(nf & 1)*2];
                        const uint32_t* blf = &bl[nf >> 1][(nf & 1)*2];
                        mma_bf16(acc[mf][nf], ah[mf], bhf);
                        mma_bf16(acc[mf][nf], ah[mf], blf);
                        mma_bf16(acc[mf][nf], al[mf], bhf);
                    }
            }
            sidx = (sidx == 2) ? 0 : sidx + 1;
        }

        #pragma unroll
        for (int mf = 0; mf < 4; mf++) {
            int r0 = bm + wM*64 + mf*16 + gid;
            #pragma unroll
            for (int nf = 0; nf < 4; nf++) {
                int col = bn + wN*32 + nf*8 + tig*2;
                float bx = __ldg(bias + col), by = __ldg(bias + col + 1);
                float v0x = acc[mf][nf][0] + bx, v0y = acc[mf][nf][1] + by;
                float v1x = acc[mf][nf][2] + bx, v1y = acc[mf][nf][3] + by;
                if (relu) {
                    v0x = fmaxf(v0x, 0.f); v0y = fmaxf(v0y, 0.f);
                    v1x = fmaxf(v1x, 0.f); v1y = fmaxf(v1y, 0.f);
                }
                if (mode == 0) {
                    *(float2*)(C + (size_t)r0*N + col)       = make_float2(v0x, v0y);
                    *(float2*)(C + (size_t)(r0 + 8)*N + col) = make_float2(v1x, v1y);
                } else {
                    uint32_t h, l;
                    size_t i0 = (size_t)r0*N + col, i1 = (size_t)(r0 + 8)*N + col;
                    split2(v0x, v0y, h, l);
                    *(uint32_t*)(Chi + i0) = h; *(uint32_t*)(Clo + i0) = l;
                    split2(v1x, v1y, h, l);
                    *(uint32_t*)(Chi + i1) = h; *(uint32_t*)(Clo + i1) = l;
                }
            }
        }
    }
}

// ---------------------------------------------------------------------------
// HMMA causal attention (unchanged)
// ---------------------------------------------------------------------------
#define OQH 0
#define OQL 8192
#define OKH 16384
#define OKL 49152
#define OVH 81920
#define OVL 114688
#define OPH 147456
#define OPL 180224
#define ORED 212992
#define ATT_SMEM (ORED + 1024)

__global__ void __launch_bounds__(256, 1)
attn_hmma(const __nv_bfloat16* __restrict__ qhi,
          const __nv_bfloat16* __restrict__ qlo,
          __nv_bfloat16* __restrict__ ohi,
          __nv_bfloat16* __restrict__ olo) {
    extern __shared__ char smg[];
    const uint32_t sa = smem_u32(smg);
    const int tid = threadIdx.x;
    const int wid = tid >> 5, lane = tid & 31;
    const int wM = wid >> 1, wN = wid & 1;
    const int gid = lane >> 2, tig = lane & 3;

    const int bid = blockIdx.x;
    const int qb = bid & 3;
    const int h  = (bid >> 2) & 7;
    const int b  = bid >> 5;
    const int krows = (qb + 1) * 64;

    auto load_tile = [&](const __nv_bfloat16* g, uint32_t sbase, int rows) {
        for (int i = tid; i < rows*8; i += 256) {
            int r = i >> 3, c = i & 7;
            cp_async16(sa + sbase + r*128 + ((c*16) ^ ((r & 7) << 4)),
                       g + (size_t)r*1536 + c*8);
        }
    };
    const size_t qbase = (size_t)(b*SS + qb*64)*1536 + h*DH;
    const size_t kbase = (size_t)(b*SS)*1536 + DD + h*DH;
    const size_t vbase = (size_t)(b*SS)*1536 + 2*DD + h*DH;
    load_tile(qhi + qbase, OQH, 64);
    load_tile(qlo + qbase, OQL, 64);
    load_tile(qhi + kbase, OKH, krows);
    load_tile(qlo + kbase, OKL, krows);
    CP_COMMIT();
    load_tile(qhi + vbase, OVH, krows);
    load_tile(qlo + vbase, OVL, krows);
    CP_COMMIT();
    CP_WAIT1();
    __syncthreads();

    const int laneA_row = lane & 15;
    const int laneA_b   = (lane >> 4) << 4;
    const int laneB_row = ((lane >> 4) << 3) + (lane & 7);
    const int laneB_b   = ((lane >> 3) & 1) << 4;

    float s[16][4];
    #pragma unroll
    for (int nt = 0; nt < 16; nt++)
        #pragma unroll
        for (int e = 0; e < 4; e++) s[nt][e] = 0.f;

    #pragma unroll
    for (int ks = 0; ks < 4; ks++) {
        uint32_t ah[4], al[4];
        {
            int r = wM*16 + laneA_row;
            uint32_t off = r*128 + (((uint32_t)(ks*32 + laneA_b)) ^ ((r & 7) << 4));
            ldm_x4(ah, sa + OQH + off);
            ldm_x4(al, sa + OQL + off);
        }
        #pragma unroll
        for (int ng = 0; ng < 8; ng++) {
            uint32_t bh4[4], bl4[4];
            int r = wN*128 + ng*16 + laneB_row;
            uint32_t off = r*128 + (((uint32_t)(ks*32 + laneB_b)) ^ ((r & 7) << 4));
            ldm_x4(bh4, sa + OKH + off);
            ldm_x4(bl4, sa + OKL + off);
            #pragma unroll
            for (int j = 0; j < 2; j++) {
                float* a = s[ng*2 + j];
                mma_bf16(a, ah, &bh4[j*2]);
                mma_bf16(a, ah, &bl4[j*2]);
                mma_bf16(a, al, &bh4[j*2]);
            }
        }
    }

    const int qrow0 = qb*64 + wM*16 + gid;
    const int qrow1 = qrow0 + 8;
    float m0 = -1e30f, m1 = -1e30f;
    #pragma unroll
    for (int nt = 0; nt < 16; nt++) {
        int c0 = wN*128 + nt*8 + tig*2;
        s[nt][0] = (c0     <= qrow0) ? s[nt][0]*0.125f : -1e30f;
        s[nt][1] = (c0 + 1 <= qrow0) ? s[nt][1]*0.125f : -1e30f;
        s[nt][2] = (c0     <= qrow1) ? s[nt][2]*0.125f : -1e30f;
        s[nt][3] = (c0 + 1 <= qrow1) ? s[nt][3]*0.125f : -1e30f;
        m0 = fmaxf(m0, fmaxf(s[nt][0], s[nt][1]));
        m1 = fmaxf(m1, fmaxf(s[nt][2], s[nt][3]));
    }
    #pragma unroll
    for (int o = 1; o <= 2; o <<= 1) {
        m0 = fmaxf(m0, __shfl_xor_sync(~0u, m0, o));
        m1 = fmaxf(m1, __shfl_xor_sync(~0u, m1, o));
    }
    float* redm = (float*)(smg + ORED);
    float* reds = (float*)(smg + ORED + 512);
    int r0l = wM*16 + gid;
    if (tig == 0) { redm[wN*64 + r0l] = m0; redm[wN*64 + r0l + 8] = m1; }
    __syncthreads();
    m0 = fmaxf(redm[r0l],     redm[64 + r0l]);
    m1 = fmaxf(redm[r0l + 8], redm[64 + r0l + 8]);

    float sum0 = 0.f, sum1 = 0.f;
    #pragma unroll
    for (int nt = 0; nt < 16; nt++) {
        s[nt][0] = __expf(s[nt][0] - m0);
        s[nt][1] = __expf(s[nt][1] - m0);
        s[nt][2] = __expf(s[nt][2] - m1);
        s[nt][3] = __expf(s[nt][3] - m1);
        sum0 += s[nt][0] + s[nt][1];
        sum1 += s[nt][2] + s[nt][3];
    }
    #pragma unroll
    for (int o = 1; o <= 2; o <<= 1) {
        sum0 += __shfl_xor_sync(~0u, sum0, o);
        sum1 += __shfl_xor_sync(~0u, sum1, o);
    }
    if (tig == 0) { reds[wN*64 + r0l] = sum0; reds[wN*64 + r0l + 8] = sum1; }
    __syncthreads();
    float inv0 = 1.f / (reds[r0l]     + reds[64 + r0l]);
    float inv1 = 1.f / (reds[r0l + 8] + reds[64 + r0l + 8]);

    #pragma unroll
    for (int nt = 0; nt < 16; nt++) {
        int c0 = wN*128 + nt*8 + tig*2;
        int kb = c0 >> 6, cb = c0 & 63;
        uint32_t sw0 = (uint32_t)(cb*2) ^ ((r0l & 7) << 4);
        uint32_t sw1 = (uint32_t)(cb*2) ^ (((r0l + 8) & 7) << 4);
        uint32_t off0 = kb*8192 + r0l*128 + sw0;
        uint32_t off1 = kb*8192 + (r0l + 8)*128 + sw1;
        uint32_t h, l;
        split2(s[nt][0]*inv0, s[nt][1]*inv0, h, l);
        *(uint32_t*)(smg + OPH + off0) = h;
        *(uint32_t*)(smg + OPL + off0) = l;
        split2(s[nt][2]*inv1, s[nt][3]*inv1, h, l);
        *(uint32_t*)(smg + OPH + off1) = h;
        *(uint32_t*)(smg + OPL + off1) = l;
    }
    CP_WAIT0();
    __syncthreads();

    float o[4][4];
    #pragma unroll
    for (int nt = 0; nt < 4; nt++)
        #pragma unroll
        for (int e = 0; e < 4; e++) o[nt][e] = 0.f;

    const int vlrow = lane & 15;
    const uint32_t cbyte0 = (uint32_t)(wN*64 + ((lane >> 4) << 4));
    for (int kb = 0; kb <= qb; kb++) {
        #pragma unroll
        for (int ks = 0; ks < 4; ks++) {
            uint32_t ph4[4], pl4[4];
            {
                int r = wM*16 + laneA_row;
                uint32_t off = kb*8192 + r*128 +
                               (((uint32_t)(ks*32 + laneA_b)) ^ ((r & 7) << 4));
                ldm_x4(ph4, sa + OPH + off);
                ldm_x4(pl4, sa + OPL + off);
            }
            int vr = kb*64 + ks*16 + vlrow;
            #pragma unroll
            for (int chh = 0; chh < 2; chh++) {
                uint32_t vh4[4], vl4[4];
                uint32_t voff = vr*128 + ((cbyte0 + chh*32) ^ ((vr & 7) << 4));
                ldm_x4t(vh4, sa + OVH + voff);
                ldm_x4t(vl4, sa + OVL + voff);
                #pragma unroll
                for (int j = 0; j < 2; j++) {
                    float* a = o[chh*2 + j];
                    mma_bf16(a, ph4, &vh4[j*2]);
                    mma_bf16(a, ph4, &vl4[j*2]);
                    mma_bf16(a, pl4, &vh4[j*2]);
                }
            }
        }
    }

    const int gr0 = b*SS + qb*64 + wM*16 + gid;
    #pragma unroll
    for (int nt = 0; nt < 4; nt++) {
        int col = h*DH + wN*32 + nt*8 + tig*2;
        uint32_t h0, l0, h1, l1;
        split2(o[nt][0], o[nt][1], h0, l0);
        split2(o[nt][2], o[nt][3], h1, l1);
        size_t i0 = (size_t)gr0*DD + col, i1 = (size_t)(gr0 + 8)*DD + col;
        *(uint32_t*)(ohi + i0) = h0; *(uint32_t*)(olo + i0) = l0;
        *(uint32_t*)(ohi + i1) = h1; *(uint32_t*)(olo + i1) = l1;
    }
}

// ---------------------------------------------------------------------------
// fp32 SIMT NT GEMM, z-batched
// ---------------------------------------------------------------------------
__global__ void __launch_bounds__(256)
gemm_nt_b(const float* __restrict__ A, size_t astr,
          const float* __restrict__ B, size_t bstr,
          const float* __restrict__ bias, size_t bistr,
          float* __restrict__ C, size_t cstr,
          int M, int N, int K) {
    const int zz = blockIdx.z;
    A += zz*astr; B += zz*bstr; bias += zz*bistr; C += zz*cstr;

    __shared__ float As[8][128];
    __shared__ float Bs[8][128];
    const int bm = blockIdx.y * 128;
    const int bn = blockIdx.x * 128;
    const int tid = threadIdx.x;
    const int tx = tid & 15, ty = tid >> 4;
    const int lr = tid >> 1, lc = (tid & 1) * 4;
    const int arow = min(bm + lr, M - 1);
    const int brow = bn + lr;

    float acc[8][8];
    #pragma unroll
    for (int i = 0; i < 8; i++)
        #pragma unroll
        for (int j = 0; j < 8; j++) acc[i][j] = 0.f;

    for (int kt = 0; kt < K; kt += 8) {
        {
            float4 v = *(const float4*)(A + (size_t)arow*K + kt + lc);
            As[lc+0][lr] = v.x; As[lc+1][lr] = v.y;
            As[lc+2][lr] = v.z; As[lc+3][lr] = v.w;
        }
        {
            float4 v = *(const float4*)(B + (size_t)brow*K + kt + lc);
            Bs[lc+0][lr] = v.x; Bs[lc+1][lr] = v.y;
            Bs[lc+2][lr] = v.z; Bs[lc+3][lr] = v.w;
        }
        __syncthreads();
        #pragma unroll
        for (int k = 0; k < 8; k++) {
            float a[8], b[8];
            #pragma unroll
            for (int i = 0; i < 8; i++) a[i] = As[k][ty*8 + i];
            #pragma unroll
            for (int j = 0; j < 8; j++) b[j] = Bs[k][tx*8 + j];
            #pragma unroll
            for (int i = 0; i < 8; i++)
                #pragma unroll
                for (int j = 0; j < 8; j++)
                    acc[i][j] = fmaf(a[i], b[j], acc[i][j]);
        }
        __syncthreads();
    }
    #pragma unroll
    for (int i = 0; i < 8; i++) {
        int row = bm + ty*8 + i;
        if (row >= M) continue;
        #pragma unroll
        for (int j = 0; j < 8; j++) {
            int col = bn + tx*8 + j;
            C[(size_t)row*N + col] = acc[i][j] + bias[col];
        }
    }
}

// ---------------------------------------------------------------------------
// LN body (device helper)
// ---------------------------------------------------------------------------
__device__ __forceinline__ void ln_block(float* v, const float4 gv,
                                         const float4 bv, int t,
                                         float* red, float* o) {
    float sum = v[0] + v[1] + v[2] + v[3];
    #pragma unroll
    for (int oo = 16; oo; oo >>= 1) sum += __shfl_xor_sync(~0u, sum, oo);
    if ((t & 31) == 0) red[t >> 5] = sum;
    __syncthreads();
    float mean = (red[0] + red[1] + red[2] + red[3]) * (1.f/512.f);
    float var = 0.f;
    #pragma unroll
    for (int i = 0; i < 4; i++) {
        float d = v[i] - mean;
        var = fmaf(d, d, var);
    }
    #pragma unroll
    for (int oo = 16; oo; oo >>= 1) var += __shfl_xor_sync(~0u, var, oo);
    if ((t & 31) == 0) red[4 + (t >> 5)] = var;
    __syncthreads();
    float rs = rsqrtf((red[4] + red[5] + red[6] + red[7]) * (1.f/512.f) + 1e-5f);
    o[0] = (v[0] - mean) * rs * gv.x + bv.x;
    o[1] = (v[1] - mean) * rs * gv.y + bv.y;
    o[2] = (v[2] - mean) * rs * gv.z + bv.z;
    o[3] = (v[3] - mean) * rs * gv.w + bv.w;
}

__global__ void __launch_bounds__(128)
add_ln_kernel(__nv_bfloat16* __restrict__ xhi, __nv_bfloat16* __restrict__ xlo,
              const float* __restrict__ r,
              const float* __restrict__ g, const float* __restrict__ bt) {
    int row = blockIdx.x;
    const float* rp = r + (size_t)row*DD;
    int t = threadIdx.x;
    __shared__ float red[8];

    uint2 hp = ((const uint2*)(xhi + (size_t)row*DD))[t];
    uint2 lp = ((const uint2*)(xlo + (size_t)row*DD))[t];
    float v[4];
    join2(hp.x, lp.x, v[0], v[1]);
    join2(hp.y, lp.y, v[2], v[3]);
    float4 rv = ((const float4*)rp)[t];
    v[0] += rv.x; v[1] += rv.y; v[2] += rv.z; v[3] += rv.w;

    float o[4];
    ln_block(v, ((const float4*)g)[t], ((const float4*)bt)[t], t, red, o);
    uint32_t h0, l0, h1, l1;
    split2(o[0], o[1], h0, l0);
    split2(o[2], o[3], h1, l1);
    ((uint2*)(xhi + (size_t)row*DD))[t] = make_uint2(h0, h1);
    ((uint2*)(xlo + (size_t)row*DD))[t] = make_uint2(l0, l1);
}

__global__ void __launch_bounds__(128)
add_ln2_kernel(__nv_bfloat16* __restrict__ xhi, __nv_bfloat16* __restrict__ xlo,
               const float* __restrict__ sub, const float* __restrict__ ca,
               const float* __restrict__ g1, const float* __restrict__ b1,
               const float* __restrict__ g2, const float* __restrict__ b2) {
    int row = blockIdx.x;
    const float* sp = sub + (size_t)row*DD;
    const float* cp = ca + (size_t)(row >> 8)*DD;
    int t = threadIdx.x;
    __shared__ float red[8];

    uint2 hp = ((const uint2*)(xhi + (size_t)row*DD))[t];
    uint2 lp = ((const uint2*)(xlo + (size_t)row*DD))[t];
    float v[4];
    join2(hp.x, lp.x, v[0], v[1]);
    join2(hp.y, lp.y, v[2], v[3]);
    float4 sv = ((const float4*)sp)[t];
    v[0] += sv.x; v[1] += sv.y; v[2] += sv.z; v[3] += sv.w;

    float y1[4];
    ln_block(v, ((const float4*)g1)[t], ((const float4*)b1)[t], t, red, y1);
    __syncthreads();

    float4 cv = ((const float4*)cp)[t];
    float v2[4] = {y1[0]+cv.x, y1[1]+cv.y, y1[2]+cv.z, y1[3]+cv.w};
    float o[4];
    ln_block(v2, ((const float4*)g2)[t], ((const float4*)b2)[t], t, red, o);
    uint32_t h0, l0, h1, l1;
    split2(o[0], o[1], h0, l0);
    split2(o[2], o[3], h1, l1);
    ((uint2*)(xhi + (size_t)row*DD))[t] = make_uint2(h0, h1);
    ((uint2*)(xlo + (size_t)row*DD))[t] = make_uint2(l0, l1);
}

// ---------------------------------------------------------------------------
// Launch
// ---------------------------------------------------------------------------
extern "C" void kernel_launch(void* const* d_in, const int* in_sizes, int n_in,
                              void* d_out, int out_size) {
    const float* z      = (const float*)d_in[0];
    const int*   tgt    = (const int*)  d_in[1];
    const float* emb    = (const float*)d_in[2];
    const float* pos    = (const float*)d_in[3];
    const float* proj_w = (const float*)d_in[4];
    const float* proj_b = (const float*)d_in[5];
    const float* sa_w   = (const float*)d_in[6];
    const float* sa_b   = (const float*)d_in[7];
    const float* sa_ow  = (const float*)d_in[8];
    const float* sa_ob  = (const float*)d_in[9];
    const float* ca_w   = (const float*)d_in[10];
    const float* ca_b   = (const float*)d_in[11];
    const float* ca_ow  = (const float*)d_in[12];
    const float* ca_ob  = (const float*)d_in[13];
    const float* ln1_s  = (const float*)d_in[14];
    const float* ln1_b  = (const float*)d_in[15];
    const float* ln2_s  = (const float*)d_in[16];
    const float* ln2_b  = (const float*)d_in[17];
    const float* ln3_s  = (const float*)d_in[18];
    const float* ln3_b  = (const float*)d_in[19];
    const float* ff1_w  = (const float*)d_in[20];
    const float* ff1_b  = (const float*)d_in[21];
    const float* ff2_w  = (const float*)d_in[22];
    const float* ff2_b  = (const float*)d_in[23];
    const float* fc_w   = (const float*)d_in[24];
    const float* fc_b   = (const float*)d_in[25];
    float* out = (float*)d_out;

    float *sub, *mem, *cav, *ca;
    __nv_bfloat16 *ahi, *alo, *qhi, *qlo, *fhi, *flo, *whi, *wlo;
    cudaGetSymbolAddress((void**)&sub, g_sub);
    cudaGetSymbolAddress((void**)&mem, g_mem);
    cudaGetSymbolAddress((void**)&cav, g_cav);
    cudaGetSymbolAddress((void**)&ca,  g_ca);
    cudaGetSymbolAddress((void**)&ahi, g_ahi);
    cudaGetSymbolAddress((void**)&alo, g_alo);
    cudaGetSymbolAddress((void**)&qhi, g_qhi);
    cudaGetSymbolAddress((void**)&qlo, g_qlo);
    cudaGetSymbolAddress((void**)&fhi, g_fhi);
    cudaGetSymbolAddress((void**)&flo, g_flo);
    cudaGetSymbolAddress((void**)&whi, g_whi);
    cudaGetSymbolAddress((void**)&wlo, g_wlo);

    cudaFuncSetAttribute(gemm_hmma,
                         cudaFuncAttributeMaxDynamicSharedMemorySize, HSMEM);
    cudaFuncSetAttribute(attn_hmma,
                         cudaFuncAttributeMaxDynamicSharedMemorySize, ATT_SMEM);

    // ---- weight conversion ----
    conv_pair<<<6*3*DD*DD/1024, 256>>>(sa_w,  whi + O_SAW,  wlo + O_SAW);
    conv_pair<<<6*DD*DD/1024,   256>>>(sa_ow, whi + O_SAOW, wlo + O_SAOW);
    conv_pair<<<6*DFF*DD/1024,  256>>>(ff1_w, whi + O_FF1,  wlo + O_FF1);
    conv_pair<<<6*DD*DFF/1024,  256>>>(ff2_w, whi + O_FF2,  wlo + O_FF2);
    conv_pair<<<VV*DD/1024,     256>>>(fc_w,  whi + O_FC,   wlo + O_FC);

    // ---- embedding + memory projection ----
    embed_kernel<<<M_TOK, 128>>>(tgt, emb, pos, ahi, alo);
    gemm_nt_b<<<dim3(DD/128, 1, 1), 256>>>(z, 0, proj_w, 0, proj_b, 0,
                                           mem, 0, BB, DD, DD);

    // ---- batched cross-attention vectors (all layers) ----
    gemm_nt_b<<<dim3(DD/128, 1, LL), 256>>>(
        mem, 0,
        ca_w + (size_t)2*DD*DD, (size_t)3*DD*DD,
        ca_b + 2*DD, (size_t)3*DD,
        cav, (size_t)BB*DD, BB, DD, DD);
    gemm_nt_b<<<dim3(DD/128, 1, LL), 256>>>(
        cav, (size_t)BB*DD,
        ca_ow, (size_t)DD*DD,
        ca_ob, (size_t)DD,
        ca, (size_t)BB*DD, BB, DD, DD);

    const int PGRID = 148;

    for (int l = 0; l < LL; l++) {
        const float* sabl  = sa_b  + (size_t)l*3*DD;
        const float* saobl = sa_ob + (size_t)l*DD;
        size_t o_qkv = O_SAW  + (size_t)l*3*DD*DD;
        size_t o_ow  = O_SAOW + (size_t)l*DD*DD;
        size_t o_ff1 = O_FF1  + (size_t)l*DFF*DD;
        size_t o_ff2 = O_FF2  + (size_t)l*DD*DFF;

        // self-attention
        gemm_hmma<<<PGRID, 256, HSMEM>>>(ahi, alo, whi + o_qkv, wlo + o_qkv,
                                         sabl, nullptr, qhi, qlo,
                                         3*DD, DD, 0, 1, 12, 12*128);
        attn_hmma<<<BB*HH*4, 256, ATT_SMEM>>>(qhi, qlo, fhi, flo);
        gemm_hmma<<<PGRID, 256, HSMEM>>>(fhi, flo, whi + o_ow, wlo + o_ow,
                                         saobl, sub, nullptr, nullptr,
                                         DD, DD, 0, 0, 4, 4*128);
        add_ln2_kernel<<<M_TOK, 128>>>(ahi, alo, sub, ca + (size_t)l*BB*DD,
                                       ln1_s + l*DD, ln1_b + l*DD,
                                       ln2_s + l*DD, ln2_b + l*DD);

        // feed-forward
        gemm_hmma<<<PGRID, 256, HSMEM>>>(ahi, alo, whi + o_ff1, wlo + o_ff1,
                                         ff1_b + l*DFF, nullptr, fhi, flo,
                                         DFF, DD, 1, 1, 16, 16*128);
        gemm_hmma<<<PGRID, 256, HSMEM>>>(fhi, flo, whi + o_ff2, wlo + o_ff2,
                                         ff2_b + l*DD, sub, nullptr, nullptr,
                                         DD, DFF, 0, 0, 4, 4*128);
        add_ln_kernel<<<M_TOK, 128>>>(ahi, alo, sub,
                                      ln3_s + l*DD, ln3_b + l*DD);
    }

    // final classifier
    gemm_hmma<<<128, 256, HSMEM>>>(ahi, alo, whi + O_FC, wlo + O_FC,
                                   fc_b, out, nullptr, nullptr,
                                   VV, DD, 0, 0, 1, 128);
}

// round 13
// speedup vs baseline: 1.5981x; 1.0042x over previous
#include <cuda_runtime.h>
#include <cuda_bf16.h>
#include <math.h>
#include <stdint.h>

#define BB 64
#define SS 256
#define DD 512
#define HH 8
#define DH 64
#define DFF 2048
#define VV 128
#define LL 6
#define M_TOK (BB*SS)

// ---------------------------------------------------------------------------
// Scratch
// ---------------------------------------------------------------------------
__device__ float g_sub[M_TOK*DD];
__device__ float g_mem[BB*DD];
__device__ float g_cav[LL*BB*DD];
__device__ float g_ca [LL*BB*DD];

__device__ __nv_bfloat16 g_ahi[(size_t)M_TOK*DD];
__device__ __nv_bfloat16 g_alo[(size_t)M_TOK*DD];
__device__ __nv_bfloat16 g_qhi[(size_t)M_TOK*3*DD];
__device__ __nv_bfloat16 g_qlo[(size_t)M_TOK*3*DD];
__device__ __nv_bfloat16 g_fhi[(size_t)M_TOK*DFF];
__device__ __nv_bfloat16 g_flo[(size_t)M_TOK*DFF];

#define O_SAW  0u
#define O_SAOW 4718592u
#define O_FF1  6291456u
#define O_FF2  12582912u
#define O_FC   18874368u
#define WPOOL_E 18940032u
__device__ __nv_bfloat16 g_whi[WPOOL_E];
__device__ __nv_bfloat16 g_wlo[WPOOL_E];

// ---------------------------------------------------------------------------
// Helpers
// ---------------------------------------------------------------------------
__device__ __forceinline__ uint32_t smem_u32(const void* p) {
    uint32_t a;
    asm("{ .reg .u64 t; cvta.to.shared.u64 t, %1; cvt.u32.u64 %0, t; }"
        : "=r"(a) : "l"(p));
    return a;
}
__device__ __forceinline__ void cp_async16(uint32_t dst, const void* src) {
    asm volatile("cp.async.cg.shared.global [%0], [%1], 16;"
                 :: "r"(dst), "l"(src));
}
#define CP_COMMIT() asm volatile("cp.async.commit_group;" ::: "memory")
#define CP_WAIT1()  asm volatile("cp.async.wait_group 1;" ::: "memory")
#define CP_WAIT0()  asm volatile("cp.async.wait_group 0;" ::: "memory")

__device__ __forceinline__ void ldm_x4(uint32_t* r, uint32_t addr) {
    asm volatile("ldmatrix.sync.aligned.m8n8.x4.shared.b16 {%0,%1,%2,%3}, [%4];"
                 : "=r"(r[0]), "=r"(r[1]), "=r"(r[2]), "=r"(r[3]) : "r"(addr));
}
__device__ __forceinline__ void ldm_x4t(uint32_t* r, uint32_t addr) {
    asm volatile("ldmatrix.sync.aligned.m8n8.x4.trans.shared.b16 {%0,%1,%2,%3}, [%4];"
                 : "=r"(r[0]), "=r"(r[1]), "=r"(r[2]), "=r"(r[3]) : "r"(addr));
}
__device__ __forceinline__ void mma_bf16(float* c, const uint32_t* a,
                                         const uint32_t* b) {
    asm volatile(
        "mma.sync.aligned.m16n8k16.row.col.f32.bf16.bf16.f32 "
        "{%0,%1,%2,%3}, {%4,%5,%6,%7}, {%8,%9}, {%0,%1,%2,%3};"
        : "+f"(c[0]), "+f"(c[1]), "+f"(c[2]), "+f"(c[3])
        : "r"(a[0]), "r"(a[1]), "r"(a[2]), "r"(a[3]), "r"(b[0]), "r"(b[1]));
}
__device__ __forceinline__ uint32_t pack2bf(float a, float b) {
    __nv_bfloat162 t = __floats2bfloat162_rn(a, b);
    return *(uint32_t*)&t;
}
__device__ __forceinline__ void split2(float a, float b, uint32_t& hi, uint32_t& lo) {
    __nv_bfloat16 ha = __float2bfloat16_rn(a);
    __nv_bfloat16 hb = __float2bfloat16_rn(b);
    hi = pack2bf(__bfloat162float(ha), __bfloat162float(hb));
    lo = pack2bf(a - __bfloat162float(ha), b - __bfloat162float(hb));
}
__device__ __forceinline__ void join2(uint32_t hi, uint32_t lo, float& a, float& b) {
    __nv_bfloat162 h = *(__nv_bfloat162*)&hi;
    __nv_bfloat162 l = *(__nv_bfloat162*)&lo;
    a = __bfloat162float(h.x) + __bfloat162float(l.x);
    b = __bfloat162float(h.y) + __bfloat162float(l.y);
}

// ---------------------------------------------------------------------------
// Embedding -> hi/lo residual stream only
// ---------------------------------------------------------------------------
__global__ void embed_kernel(const int* __restrict__ tgt,
                             const float* __restrict__ emb,
                             const float* __restrict__ pos,
                             __nv_bfloat16* __restrict__ xhi,
                             __nv_bfloat16* __restrict__ xlo) {
    int row = blockIdx.x;
    int d4  = threadIdx.x;
    int tok = tgt[row];
    int s   = row & (SS - 1);
    float4 e = ((const float4*)(emb + (size_t)tok*DD))[d4];
    float4 p = ((const float4*)(pos + (size_t)s*DD))[d4];
    float4 v = make_float4(e.x+p.x, e.y+p.y, e.z+p.z, e.w+p.w);
    uint32_t h0, l0, h1, l1;
    split2(v.x, v.y, h0, l0);
    split2(v.z, v.w, h1, l1);
    ((uint2*)(xhi + (size_t)row*DD))[d4] = make_uint2(h0, h1);
    ((uint2*)(xlo + (size_t)row*DD))[d4] = make_uint2(l0, l1);
}

// ---------------------------------------------------------------------------
// Merged weight conversion: all 5 pools in ONE launch (segment dispatch).
// Block = 256 threads x 4 floats = 1024 elements.
// ---------------------------------------------------------------------------
#define CB_SAW  4608
#define CB_SAOW 1536
#define CB_FF1  6144
#define CB_FF2  6144
#define CB_FC   64
#define CB_TOT  (CB_SAW + CB_SAOW + CB_FF1 + CB_FF2 + CB_FC)

__global__ void __launch_bounds__(256)
conv_all(const float* __restrict__ sa_w, const float* __restrict__ sa_ow,
         const float* __restrict__ ff1_w, const float* __restrict__ ff2_w,
         const float* __restrict__ fc_w,
         __nv_bfloat16* __restrict__ whi, __nv_bfloat16* __restrict__ wlo) {
    int bid = blockIdx.x;
    const float* src;
    size_t dst;
    if (bid < CB_SAW)                       { src = sa_w;  dst = O_SAW;  }
    else if ((bid -= CB_SAW)  < CB_SAOW)    { src = sa_ow; dst = O_SAOW; }
    else if ((bid -= CB_SAOW) < CB_FF1)     { src = ff1_w; dst = O_FF1;  }
    else if ((bid -= CB_FF1)  < CB_FF2)     { src = ff2_w; dst = O_FF2;  }
    else    { bid -= CB_FF2;                  src = fc_w;  dst = O_FC;   }

    size_t i = (size_t)bid * 256 + threadIdx.x;   // float4 index in segment
    float4 v = ((const float4*)src)[i];
    uint32_t h0, l0, h1, l1;
    split2(v.x, v.y, h0, l0);
    split2(v.z, v.w, h1, l1);
    ((uint2*)(whi + dst))[i] = make_uint2(h0, h1);
    ((uint2*)(wlo + dst))[i] = make_uint2(l0, l1);
}

// ---------------------------------------------------------------------------
// PERSISTENT HMMA bf16x3 GEMM (unchanged from R12 winner)
// ---------------------------------------------------------------------------
#define HSTAGE 65536
#define HSMEM  (3*HSTAGE)

__global__ void __launch_bounds__(256, 1)
gemm_hmma(const __nv_bfloat16* __restrict__ Ahi,
          const __nv_bfloat16* __restrict__ Alo,
          const __nv_bfloat16* __restrict__ Bhi,
          const __nv_bfloat16* __restrict__ Blo,
          const float* __restrict__ bias, float* __restrict__ C,
          __nv_bfloat16* __restrict__ Chi, __nv_bfloat16* __restrict__ Clo,
          int N, int K, int relu, int mode, int ntx, int ntiles) {
    extern __shared__ char smg[];
    const uint32_t sa = smem_u32(smg);
    const int tid = threadIdx.x;
    const int wid = tid >> 5, lane = tid & 31;
    const int wM = wid >> 2, wN = wid & 3;
    const int kc = K >> 6;

    const int laneA_row = lane & 15;
    const int laneA_b   = (lane >> 4) << 4;
    const int laneB_row = ((lane >> 4) << 3) + (lane & 7);
    const int laneB_b   = ((lane >> 3) & 1) << 4;
    const int gid = lane >> 2, tig = lane & 3;

    int dec_pool[8], dec_r[8];
    uint32_t offA[8], offB[8];
    #pragma unroll
    for (int it = 0; it < 8; it++) {
        int i = tid + it*256;
        int pool = i >> 10, r = (i >> 3) & 127, c = i & 7;
        dec_pool[it] = pool; dec_r[it] = r;
        uint32_t sw = (uint32_t)((c*16) ^ ((r & 7) << 4));
        offA[it] = pool*16384 + r*128 + sw;
        offB[it] = 32768 + pool*16384 + r*128 + sw;
    }

    for (int tile = blockIdx.x; tile < ntiles; tile += gridDim.x) {
        const int bm = (tile / ntx) * 128;
        const int bn = (tile % ntx) * 128;

        const char* srcA[8];
        const char* srcB[8];
        #pragma unroll
        for (int it = 0; it < 8; it++) {
            int i = tid + it*256;
            int c = i & 7;
            srcA[it] = (const char*)((dec_pool[it] ? Alo : Ahi) +
                                     (size_t)(bm + dec_r[it])*K + c*8);
            srcB[it] = (const char*)((dec_pool[it] ? Blo : Bhi) +
                                     (size_t)(bn + dec_r[it])*K + c*8);
        }

        __syncthreads();

        float acc[4][4][4];
        #pragma unroll
        for (int i = 0; i < 4; i++)
            #pragma unroll
            for (int j = 0; j < 4; j++)
                #pragma unroll
                for (int e = 0; e < 4; e++) acc[i][j][e] = 0.f;

        auto load_stage = [&](int s, int kk) {
            uint32_t stg = sa + s*HSTAGE;
            int kb = kk << 7;
            #pragma unroll
            for (int it = 0; it < 8; it++)
                cp_async16(stg + offA[it], srcA[it] + kb);
            #pragma unroll
            for (int it = 0; it < 8; it++)
                cp_async16(stg + offB[it], srcB[it] + kb);
        };

        load_stage(0, 0); CP_COMMIT();
        load_stage(1, 1); CP_COMMIT();

        int sidx = 0;
        for (int ch = 0; ch < kc; ch++) {
            CP_WAIT1();
            __syncthreads();

            if (ch + 2 < kc) {
                int st2 = sidx + 2; if (st2 >= 3) st2 -= 3;
                load_stage(st2, ch + 2);
            }
            CP_COMMIT();

            uint32_t stg = sa + sidx*HSTAGE;
            #pragma unroll
            for (int ks = 0; ks < 4; ks++) {
                uint32_t ah[4][4], al[4][4], bh[2][4], bl[2][4];
                #pragma unroll
                for (int mf = 0; mf < 4; mf++) {
                    int r = wM*64 + mf*16 + laneA_row;
                    uint32_t off = r*128 + (((uint32_t)(ks*32 + laneA_b)) ^ ((r & 7) << 4));
                    ldm_x4(ah[mf], stg + off);
                    ldm_x4(al[mf], stg + 16384 + off);
                }
                #pragma unroll
                for (int nf2 = 0; nf2 < 2; nf2++) {
                    int r = wN*32 + nf2*16 + laneB_row;
                    uint32_t off = r*128 + (((uint32_t)(ks*32 + laneB_b)) ^ ((r & 7) << 4));
                    ldm_x4(bh[nf2], stg + 32768 + off);
                    ldm_x4(bl[nf2], stg + 49152 + off);
                }
                #pragma unroll
                for (int mf = 0; mf < 4; mf++)
                    #pragma unroll
                    for (int nf = 0; nf < 4; nf++) {
                        const uint32_t* bhf = &bh[nf >> 1][(nf & 1)*2];
                        const uint32_t* blf = &bl[nf >> 1][(nf & 1)*2];
                        mma_bf16(acc[mf][nf], ah[mf], bhf);
                        mma_bf16(acc[mf][nf], ah[mf], blf);
                        mma_bf16(acc[mf][nf], al[mf], bhf);
                    }
            }
            sidx = (sidx == 2) ? 0 : sidx + 1;
        }

        #pragma unroll
        for (int mf = 0; mf < 4; mf++) {
            int r0 = bm + wM*64 + mf*16 + gid;
            #pragma unroll
            for (int nf = 0; nf < 4; nf++) {
                int col = bn + wN*32 + nf*8 + tig*2;
                float bx = __ldg(bias + col), by = __ldg(bias + col + 1);
                float v0x = acc[mf][nf][0] + bx, v0y = acc[mf][nf][1] + by;
                float v1x = acc[mf][nf][2] + bx, v1y = acc[mf][nf][3] + by;
                if (relu) {
                    v0x = fmaxf(v0x, 0.f); v0y = fmaxf(v0y, 0.f);
                    v1x = fmaxf(v1x, 0.f); v1y = fmaxf(v1y, 0.f);
                }
                if (mode == 0) {
                    *(float2*)(C + (size_t)r0*N + col)       = make_float2(v0x, v0y);
                    *(float2*)(C + (size_t)(r0 + 8)*N + col) = make_float2(v1x, v1y);
                } else {
                    uint32_t h, l;
                    size_t i0 = (size_t)r0*N + col, i1 = (size_t)(r0 + 8)*N + col;
                    split2(v0x, v0y, h, l);
                    *(uint32_t*)(Chi + i0) = h; *(uint32_t*)(Clo + i0) = l;
                    split2(v1x, v1y, h, l);
                    *(uint32_t*)(Chi + i1) = h; *(uint32_t*)(Clo + i1) = l;
                }
            }
        }
    }
}

// ---------------------------------------------------------------------------
// HMMA causal attention (qb reversed: heavy blocks scheduled first)
// ---------------------------------------------------------------------------
#define OQH 0
#define OQL 8192
#define OKH 16384
#define OKL 49152
#define OVH 81920
#define OVL 114688
#define OPH 147456
#define OPL 180224
#define ORED 212992
#define ATT_SMEM (ORED + 1024)

__global__ void __launch_bounds__(256, 1)
attn_hmma(const __nv_bfloat16* __restrict__ qhi,
          const __nv_bfloat16* __restrict__ qlo,
          __nv_bfloat16* __restrict__ ohi,
          __nv_bfloat16* __restrict__ olo) {
    extern __shared__ char smg[];
    const uint32_t sa = smem_u32(smg);
    const int tid = threadIdx.x;
    const int wid = tid >> 5, lane = tid & 31;
    const int wM = wid >> 1, wN = wid & 1;
    const int gid = lane >> 2, tig = lane & 3;

    const int bid = blockIdx.x;
    const int qb = 3 - (bid & 3);          // heavy first
    const int h  = (bid >> 2) & 7;
    const int b  = bid >> 5;
    const int krows = (qb + 1) * 64;

    auto load_tile = [&](const __nv_bfloat16* g, uint32_t sbase, int rows) {
        for (int i = tid; i < rows*8; i += 256) {
            int r = i >> 3, c = i & 7;
            cp_async16(sa + sbase + r*128 + ((c*16) ^ ((r & 7) << 4)),
                       g + (size_t)r*1536 + c*8);
        }
    };
    const size_t qbase = (size_t)(b*SS + qb*64)*1536 + h*DH;
    const size_t kbase = (size_t)(b*SS)*1536 + DD + h*DH;
    const size_t vbase = (size_t)(b*SS)*1536 + 2*DD + h*DH;
    load_tile(qhi + qbase, OQH, 64);
    load_tile(qlo + qbase, OQL, 64);
    load_tile(qhi + kbase, OKH, krows);
    load_tile(qlo + kbase, OKL, krows);
    CP_COMMIT();
    load_tile(qhi + vbase, OVH, krows);
    load_tile(qlo + vbase, OVL, krows);
    CP_COMMIT();
    CP_WAIT1();
    __syncthreads();

    const int laneA_row = lane & 15;
    const int laneA_b   = (lane >> 4) << 4;
    const int laneB_row = ((lane >> 4) << 3) + (lane & 7);
    const int laneB_b   = ((lane >> 3) & 1) << 4;

    float s[16][4];
    #pragma unroll
    for (int nt = 0; nt < 16; nt++)
        #pragma unroll
        for (int e = 0; e < 4; e++) s[nt][e] = 0.f;

    #pragma unroll
    for (int ks = 0; ks < 4; ks++) {
        uint32_t ah[4], al[4];
        {
            int r = wM*16 + laneA_row;
            uint32_t off = r*128 + (((uint32_t)(ks*32 + laneA_b)) ^ ((r & 7) << 4));
            ldm_x4(ah, sa + OQH + off);
            ldm_x4(al, sa + OQL + off);
        }
        #pragma unroll
        for (int ng = 0; ng < 8; ng++) {
            uint32_t bh4[4], bl4[4];
            int r = wN*128 + ng*16 + laneB_row;
            uint32_t off = r*128 + (((uint32_t)(ks*32 + laneB_b)) ^ ((r & 7) << 4));
            ldm_x4(bh4, sa + OKH + off);
            ldm_x4(bl4, sa + OKL + off);
            #pragma unroll
            for (int j = 0; j < 2; j++) {
                float* a = s[ng*2 + j];
                mma_bf16(a, ah, &bh4[j*2]);
                mma_bf16(a, ah, &bl4[j*2]);
                mma_bf16(a, al, &bh4[j*2]);
            }
        }
    }

    const int qrow0 = qb*64 + wM*16 + gid;
    const int qrow1 = qrow0 + 8;
    float m0 = -1e30f, m1 = -1e30f;
    #pragma unroll
    for (int nt = 0; nt < 16; nt++) {
        int c0 = wN*128 + nt*8 + tig*2;
        s[nt][0] = (c0     <= qrow0) ? s[nt][0]*0.125f : -1e30f;
        s[nt][1] = (c0 + 1 <= qrow0) ? s[nt][1]*0.125f : -1e30f;
        s[nt][2] = (c0     <= qrow1) ? s[nt][2]*0.125f : -1e30f;
        s[nt][3] = (c0 + 1 <= qrow1) ? s[nt][3]*0.125f : -1e30f;
        m0 = fmaxf(m0, fmaxf(s[nt][0], s[nt][1]));
        m1 = fmaxf(m1, fmaxf(s[nt][2], s[nt][3]));
    }
    #pragma unroll
    for (int o = 1; o <= 2; o <<= 1) {
        m0 = fmaxf(m0, __shfl_xor_sync(~0u, m0, o));
        m1 = fmaxf(m1, __shfl_xor_sync(~0u, m1, o));
    }
    float* redm = (float*)(smg + ORED);
    float* reds = (float*)(smg + ORED + 512);
    int r0l = wM*16 + gid;
    if (tig == 0) { redm[wN*64 + r0l] = m0; redm[wN*64 + r0l + 8] = m1; }
    __syncthreads();
    m0 = fmaxf(redm[r0l],     redm[64 + r0l]);
    m1 = fmaxf(redm[r0l + 8], redm[64 + r0l + 8]);

    float sum0 = 0.f, sum1 = 0.f;
    #pragma unroll
    for (int nt = 0; nt < 16; nt++) {
        s[nt][0] = __expf(s[nt][0] - m0);
        s[nt][1] = __expf(s[nt][1] - m0);
        s[nt][2] = __expf(s[nt][2] - m1);
        s[nt][3] = __expf(s[nt][3] - m1);
        sum0 += s[nt][0] + s[nt][1];
        sum1 += s[nt][2] + s[nt][3];
    }
    #pragma unroll
    for (int o = 1; o <= 2; o <<= 1) {
        sum0 += __shfl_xor_sync(~0u, sum0, o);
        sum1 += __shfl_xor_sync(~0u, sum1, o);
    }
    if (tig == 0) { reds[wN*64 + r0l] = sum0; reds[wN*64 + r0l + 8] = sum1; }
    __syncthreads();
    float inv0 = 1.f / (reds[r0l]     + reds[64 + r0l]);
    float inv1 = 1.f / (reds[r0l + 8] + reds[64 + r0l + 8]);

    #pragma unroll
    for (int nt = 0; nt < 16; nt++) {
        int c0 = wN*128 + nt*8 + tig*2;
        int kb = c0 >> 6, cb = c0 & 63;
        uint32_t sw0 = (uint32_t)(cb*2) ^ ((r0l & 7) << 4);
        uint32_t sw1 = (uint32_t)(cb*2) ^ (((r0l + 8) & 7) << 4);
        uint32_t off0 = kb*8192 + r0l*128 + sw0;
        uint32_t off1 = kb*8192 + (r0l + 8)*128 + sw1;
        uint32_t h, l;
        split2(s[nt][0]*inv0, s[nt][1]*inv0, h, l);
        *(uint32_t*)(smg + OPH + off0) = h;
        *(uint32_t*)(smg + OPL + off0) = l;
        split2(s[nt][2]*inv1, s[nt][3]*inv1, h, l);
        *(uint32_t*)(smg + OPH + off1) = h;
        *(uint32_t*)(smg + OPL + off1) = l;
    }
    CP_WAIT0();
    __syncthreads();

    float o[4][4];
    #pragma unroll
    for (int nt = 0; nt < 4; nt++)
        #pragma unroll
        for (int e = 0; e < 4; e++) o[nt][e] = 0.f;

    const int vlrow = lane & 15;
    const uint32_t cbyte0 = (uint32_t)(wN*64 + ((lane >> 4) << 4));
    for (int kb = 0; kb <= qb; kb++) {
        #pragma unroll
        for (int ks = 0; ks < 4; ks++) {
            uint32_t ph4[4], pl4[4];
            {
                int r = wM*16 + laneA_row;
                uint32_t off = kb*8192 + r*128 +
                               (((uint32_t)(ks*32 + laneA_b)) ^ ((r & 7) << 4));
                ldm_x4(ph4, sa + OPH + off);
                ldm_x4(pl4, sa + OPL + off);
            }
            int vr = kb*64 + ks*16 + vlrow;
            #pragma unroll
            for (int chh = 0; chh < 2; chh++) {
                uint32_t vh4[4], vl4[4];
                uint32_t voff = vr*128 + ((cbyte0 + chh*32) ^ ((vr & 7) << 4));
                ldm_x4t(vh4, sa + OVH + voff);
                ldm_x4t(vl4, sa + OVL + voff);
                #pragma unroll
                for (int j = 0; j < 2; j++) {
                    float* a = o[chh*2 + j];
                    mma_bf16(a, ph4, &vh4[j*2]);
                    mma_bf16(a, ph4, &vl4[j*2]);
                    mma_bf16(a, pl4, &vh4[j*2]);
                }
            }
        }
    }

    const int gr0 = b*SS + qb*64 + wM*16 + gid;
    #pragma unroll
    for (int nt = 0; nt < 4; nt++) {
        int col = h*DH + wN*32 + nt*8 + tig*2;
        uint32_t h0, l0, h1, l1;
        split2(o[nt][0], o[nt][1], h0, l0);
        split2(o[nt][2], o[nt][3], h1, l1);
        size_t i0 = (size_t)gr0*DD + col, i1 = (size_t)(gr0 + 8)*DD + col;
        *(uint32_t*)(ohi + i0) = h0; *(uint32_t*)(olo + i0) = l0;
        *(uint32_t*)(ohi + i1) = h1; *(uint32_t*)(olo + i1) = l1;
    }
}

// ---------------------------------------------------------------------------
// fp32 SIMT NT GEMM, z-batched
// ---------------------------------------------------------------------------
__global__ void __launch_bounds__(256)
gemm_nt_b(const float* __restrict__ A, size_t astr,
          const float* __restrict__ B, size_t bstr,
          const float* __restrict__ bias, size_t bistr,
          float* __restrict__ C, size_t cstr,
          int M, int N, int K) {
    const int zz = blockIdx.z;
    A += zz*astr; B += zz*bstr; bias += zz*bistr; C += zz*cstr;

    __shared__ float As[8][128];
    __shared__ float Bs[8][128];
    const int bm = blockIdx.y * 128;
    const int bn = blockIdx.x * 128;
    const int tid = threadIdx.x;
    const int tx = tid & 15, ty = tid >> 4;
    const int lr = tid >> 1, lc = (tid & 1) * 4;
    const int arow = min(bm + lr, M - 1);
    const int brow = bn + lr;

    float acc[8][8];
    #pragma unroll
    for (int i = 0; i < 8; i++)
        #pragma unroll
        for (int j = 0; j < 8; j++) acc[i][j] = 0.f;

    for (int kt = 0; kt < K; kt += 8) {
        {
            float4 v = *(const float4*)(A + (size_t)arow*K + kt + lc);
            As[lc+0][lr] = v.x; As[lc+1][lr] = v.y;
            As[lc+2][lr] = v.z; As[lc+3][lr] = v.w;
        }
        {
            float4 v = *(const float4*)(B + (size_t)brow*K + kt + lc);
            Bs[lc+0][lr] = v.x; Bs[lc+1][lr] = v.y;
            Bs[lc+2][lr] = v.z; Bs[lc+3][lr] = v.w;
        }
        __syncthreads();
        #pragma unroll
        for (int k = 0; k < 8; k++) {
            float a[8], b[8];
            #pragma unroll
            for (int i = 0; i < 8; i++) a[i] = As[k][ty*8 + i];
            #pragma unroll
            for (int j = 0; j < 8; j++) b[j] = Bs[k][tx*8 + j];
            #pragma unroll
            for (int i = 0; i < 8; i++)
                #pragma unroll
                for (int j = 0; j < 8; j++)
                    acc[i][j] = fmaf(a[i], b[j], acc[i][j]);
        }
        __syncthreads();
    }
    #pragma unroll
    for (int i = 0; i < 8; i++) {
        int row = bm + ty*8 + i;
        if (row >= M) continue;
        #pragma unroll
        for (int j = 0; j < 8; j++) {
            int col = bn + tx*8 + j;
            C[(size_t)row*N + col] = acc[i][j] + bias[col];
        }
    }
}

// ---------------------------------------------------------------------------
// LN body (device helper)
// ---------------------------------------------------------------------------
__device__ __forceinline__ void ln_block(float* v, const float4 gv,
                                         const float4 bv, int t,
                                         float* red, float* o) {
    float sum = v[0] + v[1] + v[2] + v[3];
    #pragma unroll
    for (int oo = 16; oo; oo >>= 1) sum += __shfl_xor_sync(~0u, sum, oo);
    if ((t & 31) == 0) red[t >> 5] = sum;
    __syncthreads();
    float mean = (red[0] + red[1] + red[2] + red[3]) * (1.f/512.f);
    float var = 0.f;
    #pragma unroll
    for (int i = 0; i < 4; i++) {
        float d = v[i] - mean;
        var = fmaf(d, d, var);
    }
    #pragma unroll
    for (int oo = 16; oo; oo >>= 1) var += __shfl_xor_sync(~0u, var, oo);
    if ((t & 31) == 0) red[4 + (t >> 5)] = var;
    __syncthreads();
    float rs = rsqrtf((red[4] + red[5] + red[6] + red[7]) * (1.f/512.f) + 1e-5f);
    o[0] = (v[0] - mean) * rs * gv.x + bv.x;
    o[1] = (v[1] - mean) * rs * gv.y + bv.y;
    o[2] = (v[2] - mean) * rs * gv.z + bv.z;
    o[3] = (v[3] - mean) * rs * gv.w + bv.w;
}

__global__ void __launch_bounds__(128)
add_ln_kernel(__nv_bfloat16* __restrict__ xhi, __nv_bfloat16* __restrict__ xlo,
              const float* __restrict__ r,
              const float* __restrict__ g, const float* __restrict__ bt) {
    int row = blockIdx.x;
    const float* rp = r + (size_t)row*DD;
    int t = threadIdx.x;
    __shared__ float red[8];

    uint2 hp = ((const uint2*)(xhi + (size_t)row*DD))[t];
    uint2 lp = ((const uint2*)(xlo + (size_t)row*DD))[t];
    float v[4];
    join2(hp.x, lp.x, v[0], v[1]);
    join2(hp.y, lp.y, v[2], v[3]);
    float4 rv = ((const float4*)rp)[t];
    v[0] += rv.x; v[1] += rv.y; v[2] += rv.z; v[3] += rv.w;

    float o[4];
    ln_block(v, ((const float4*)g)[t], ((const float4*)bt)[t], t, red, o);
    uint32_t h0, l0, h1, l1;
    split2(o[0], o[1], h0, l0);
    split2(o[2], o[3], h1, l1);
    ((uint2*)(xhi + (size_t)row*DD))[t] = make_uint2(h0, h1);
    ((uint2*)(xlo + (size_t)row*DD))[t] = make_uint2(l0, l1);
}

__global__ void __launch_bounds__(128)
add_ln2_kernel(__nv_bfloat16* __restrict__ xhi, __nv_bfloat16* __restrict__ xlo,
               const float* __restrict__ sub, const float* __restrict__ ca,
               const float* __restrict__ g1, const float* __restrict__ b1,
               const float* __restrict__ g2, const float* __restrict__ b2) {
    int row = blockIdx.x;
    const float* sp = sub + (size_t)row*DD;
    const float* cp = ca + (size_t)(row >> 8)*DD;
    int t = threadIdx.x;
    __shared__ float red[8];

    uint2 hp = ((const uint2*)(xhi + (size_t)row*DD))[t];
    uint2 lp = ((const uint2*)(xlo + (size_t)row*DD))[t];
    float v[4];
    join2(hp.x, lp.x, v[0], v[1]);
    join2(hp.y, lp.y, v[2], v[3]);
    float4 sv = ((const float4*)sp)[t];
    v[0] += sv.x; v[1] += sv.y; v[2] += sv.z; v[3] += sv.w;

    float y1[4];
    ln_block(v, ((const float4*)g1)[t], ((const float4*)b1)[t], t, red, y1);
    __syncthreads();

    float4 cv = ((const float4*)cp)[t];
    float v2[4] = {y1[0]+cv.x, y1[1]+cv.y, y1[2]+cv.z, y1[3]+cv.w};
    float o[4];
    ln_block(v2, ((const float4*)g2)[t], ((const float4*)b2)[t], t, red, o);
    uint32_t h0, l0, h1, l1;
    split2(o[0], o[1], h0, l0);
    split2(o[2], o[3], h1, l1);
    ((uint2*)(xhi + (size_t)row*DD))[t] = make_uint2(h0, h1);
    ((uint2*)(xlo + (size_t)row*DD))[t] = make_uint2(l0, l1);
}

// ---------------------------------------------------------------------------
// Launch
// ---------------------------------------------------------------------------
extern "C" void kernel_launch(void* const* d_in, const int* in_sizes, int n_in,
                              void* d_out, int out_size) {
    const float* z      = (const float*)d_in[0];
    const int*   tgt    = (const int*)  d_in[1];
    const float* emb    = (const float*)d_in[2];
    const float* pos    = (const float*)d_in[3];
    const float* proj_w = (const float*)d_in[4];
    const float* proj_b = (const float*)d_in[5];
    const float* sa_w   = (const float*)d_in[6];
    const float* sa_b   = (const float*)d_in[7];
    const float* sa_ow  = (const float*)d_in[8];
    const float* sa_ob  = (const float*)d_in[9];
    const float* ca_w   = (const float*)d_in[10];
    const float* ca_b   = (const float*)d_in[11];
    const float* ca_ow  = (const float*)d_in[12];
    const float* ca_ob  = (const float*)d_in[13];
    const float* ln1_s  = (const float*)d_in[14];
    const float* ln1_b  = (const float*)d_in[15];
    const float* ln2_s  = (const float*)d_in[16];
    const float* ln2_b  = (const float*)d_in[17];
    const float* ln3_s  = (const float*)d_in[18];
    const float* ln3_b  = (const float*)d_in[19];
    const float* ff1_w  = (const float*)d_in[20];
    const float* ff1_b  = (const float*)d_in[21];
    const float* ff2_w  = (const float*)d_in[22];
    const float* ff2_b  = (const float*)d_in[23];
    const float* fc_w   = (const float*)d_in[24];
    const float* fc_b   = (const float*)d_in[25];
    float* out = (float*)d_out;

    float *sub, *mem, *cav, *ca;
    __nv_bfloat16 *ahi, *alo, *qhi, *qlo, *fhi, *flo, *whi, *wlo;
    cudaGetSymbolAddress((void**)&sub, g_sub);
    cudaGetSymbolAddress((void**)&mem, g_mem);
    cudaGetSymbolAddress((void**)&cav, g_cav);
    cudaGetSymbolAddress((void**)&ca,  g_ca);
    cudaGetSymbolAddress((void**)&ahi, g_ahi);
    cudaGetSymbolAddress((void**)&alo, g_alo);
    cudaGetSymbolAddress((void**)&qhi, g_qhi);
    cudaGetSymbolAddress((void**)&qlo, g_qlo);
    cudaGetSymbolAddress((void**)&fhi, g_fhi);
    cudaGetSymbolAddress((void**)&flo, g_flo);
    cudaGetSymbolAddress((void**)&whi, g_whi);
    cudaGetSymbolAddress((void**)&wlo, g_wlo);

    cudaFuncSetAttribute(gemm_hmma,
                         cudaFuncAttributeMaxDynamicSharedMemorySize, HSMEM);
    cudaFuncSetAttribute(attn_hmma,
                         cudaFuncAttributeMaxDynamicSharedMemorySize, ATT_SMEM);

    // (1) merged weight conversion — single launch
    conv_all<<<CB_TOT, 256>>>(sa_w, sa_ow, ff1_w, ff2_w, fc_w, whi, wlo);

    // (2) embedding
    embed_kernel<<<M_TOK, 128>>>(tgt, emb, pos, ahi, alo);

    // (3-5) memory projection + batched cross-attention vectors
    gemm_nt_b<<<dim3(DD/128, 1, 1), 256>>>(z, 0, proj_w, 0, proj_b, 0,
                                           mem, 0, BB, DD, DD);
    gemm_nt_b<<<dim3(DD/128, 1, LL), 256>>>(
        mem, 0,
        ca_w + (size_t)2*DD*DD, (size_t)3*DD*DD,
        ca_b + 2*DD, (size_t)3*DD,
        cav, (size_t)BB*DD, BB, DD, DD);
    gemm_nt_b<<<dim3(DD/128, 1, LL), 256>>>(
        cav, (size_t)BB*DD,
        ca_ow, (size_t)DD*DD,
        ca_ob, (size_t)DD,
        ca, (size_t)BB*DD, BB, DD, DD);

    const int PGRID = 148;

    for (int l = 0; l < LL; l++) {
        const float* sabl  = sa_b  + (size_t)l*3*DD;
        const float* saobl = sa_ob + (size_t)l*DD;
        size_t o_qkv = O_SAW  + (size_t)l*3*DD*DD;
        size_t o_ow  = O_SAOW + (size_t)l*DD*DD;
        size_t o_ff1 = O_FF1  + (size_t)l*DFF*DD;
        size_t o_ff2 = O_FF2  + (size_t)l*DD*DFF;

        // (6 on l==0) self-attention qkv GEMM — ncu capture target
        gemm_hmma<<<PGRID, 256, HSMEM>>>(ahi, alo, whi + o_qkv, wlo + o_qkv,
                                         sabl, nullptr, qhi, qlo,
                                         3*DD, DD, 0, 1, 12, 12*128);
        attn_hmma<<<BB*HH*4, 256, ATT_SMEM>>>(qhi, qlo, fhi, flo);
        gemm_hmma<<<PGRID, 256, HSMEM>>>(fhi, flo, whi + o_ow, wlo + o_ow,
                                         saobl, sub, nullptr, nullptr,
                                         DD, DD, 0, 0, 4, 4*128);
        add_ln2_kernel<<<M_TOK, 128>>>(ahi, alo, sub, ca + (size_t)l*BB*DD,
                                       ln1_s + l*DD, ln1_b + l*DD,
                                       ln2_s + l*DD, ln2_b + l*DD);

        // feed-forward
        gemm_hmma<<<PGRID, 256, HSMEM>>>(ahi, alo, whi + o_ff1, wlo + o_ff1,
                                         ff1_b + l*DFF, nullptr, fhi, flo,
                                         DFF, DD, 1, 1, 16, 16*128);
        gemm_hmma<<<PGRID, 256, HSMEM>>>(fhi, flo, whi + o_ff2, wlo + o_ff2,
                                         ff2_b + l*DD, sub, nullptr, nullptr,
                                         DD, DFF, 0, 0, 4, 4*128);
        add_ln_kernel<<<M_TOK, 128>>>(ahi, alo, sub,
                                      ln3_s + l*DD, ln3_b + l*DD);
    }

    // final classifier
    gemm_hmma<<<128, 256, HSMEM>>>(ahi, alo, whi + O_FC, wlo + O_FC,
                                   fc_b, out, nullptr, nullptr,
                                   VV, DD, 0, 0, 1, 128);
}

// round 14
// speedup vs baseline: 1.6461x; 1.0300x over previous
#include <cuda_runtime.h>
#include <cuda_bf16.h>
#include <math.h>
#include <stdint.h>

#define BB 64
#define SS 256
#define DD 512
#define HH 8
#define DH 64
#define DFF 2048
#define VV 128
#define LL 6
#define M_TOK (BB*SS)

// ---------------------------------------------------------------------------
// Scratch
// ---------------------------------------------------------------------------
__device__ float g_sub[M_TOK*DD];
__device__ float g_mem[BB*DD];
__device__ float g_cav[LL*BB*DD];
__device__ float g_ca [LL*BB*DD];

__device__ __nv_bfloat16 g_ahi[(size_t)M_TOK*DD];
__device__ __nv_bfloat16 g_alo[(size_t)M_TOK*DD];
__device__ __nv_bfloat16 g_qhi[(size_t)M_TOK*3*DD];
__device__ __nv_bfloat16 g_qlo[(size_t)M_TOK*3*DD];
__device__ __nv_bfloat16 g_fhi[(size_t)M_TOK*DFF];
__device__ __nv_bfloat16 g_flo[(size_t)M_TOK*DFF];

#define O_SAW  0u
#define O_SAOW 4718592u
#define O_FF1  6291456u
#define O_FF2  12582912u
#define O_FC   18874368u
#define WPOOL_E 18940032u
__device__ __nv_bfloat16 g_whi[WPOOL_E];
__device__ __nv_bfloat16 g_wlo[WPOOL_E];

// ---------------------------------------------------------------------------
// Helpers
// ---------------------------------------------------------------------------
__device__ __forceinline__ uint32_t smem_u32(const void* p) {
    uint32_t a;
    asm("{ .reg .u64 t; cvta.to.shared.u64 t, %1; cvt.u32.u64 %0, t; }"
        : "=r"(a) : "l"(p));
    return a;
}
__device__ __forceinline__ void cp_async16(uint32_t dst, const void* src) {
    asm volatile("cp.async.cg.shared.global [%0], [%1], 16;"
                 :: "r"(dst), "l"(src));
}
#define CP_COMMIT() asm volatile("cp.async.commit_group;" ::: "memory")
#define CP_WAIT1()  asm volatile("cp.async.wait_group 1;" ::: "memory")
#define CP_WAIT0()  asm volatile("cp.async.wait_group 0;" ::: "memory")

__device__ __forceinline__ void ldm_x4(uint32_t* r, uint32_t addr) {
    asm volatile("ldmatrix.sync.aligned.m8n8.x4.shared.b16 {%0,%1,%2,%3}, [%4];"
                 : "=r"(r[0]), "=r"(r[1]), "=r"(r[2]), "=r"(r[3]) : "r"(addr));
}
__device__ __forceinline__ void ldm_x4t(uint32_t* r, uint32_t addr) {
    asm volatile("ldmatrix.sync.aligned.m8n8.x4.trans.shared.b16 {%0,%1,%2,%3}, [%4];"
                 : "=r"(r[0]), "=r"(r[1]), "=r"(r[2]), "=r"(r[3]) : "r"(addr));
}
__device__ __forceinline__ void mma_bf16(float* c, const uint32_t* a,
                                         const uint32_t* b) {
    asm volatile(
        "mma.sync.aligned.m16n8k16.row.col.f32.bf16.bf16.f32 "
        "{%0,%1,%2,%3}, {%4,%5,%6,%7}, {%8,%9}, {%0,%1,%2,%3};"
        : "+f"(c[0]), "+f"(c[1]), "+f"(c[2]), "+f"(c[3])
        : "r"(a[0]), "r"(a[1]), "r"(a[2]), "r"(a[3]), "r"(b[0]), "r"(b[1]));
}
__device__ __forceinline__ uint32_t pack2bf(float a, float b) {
    __nv_bfloat162 t = __floats2bfloat162_rn(a, b);
    return *(uint32_t*)&t;
}
__device__ __forceinline__ void split2(float a, float b, uint32_t& hi, uint32_t& lo) {
    __nv_bfloat16 ha = __float2bfloat16_rn(a);
    __nv_bfloat16 hb = __float2bfloat16_rn(b);
    hi = pack2bf(__bfloat162float(ha), __bfloat162float(hb));
    lo = pack2bf(a - __bfloat162float(ha), b - __bfloat162float(hb));
}
__device__ __forceinline__ void join2(uint32_t hi, uint32_t lo, float& a, float& b) {
    __nv_bfloat162 h = *(__nv_bfloat162*)&hi;
    __nv_bfloat162 l = *(__nv_bfloat162*)&lo;
    a = __bfloat162float(h.x) + __bfloat162float(l.x);
    b = __bfloat162float(h.y) + __bfloat162float(l.y);
}

// ---------------------------------------------------------------------------
// Embedding -> hi/lo residual stream only
// ---------------------------------------------------------------------------
__global__ void embed_kernel(const int* __restrict__ tgt,
                             const float* __restrict__ emb,
                             const float* __restrict__ pos,
                             __nv_bfloat16* __restrict__ xhi,
                             __nv_bfloat16* __restrict__ xlo) {
    int row = blockIdx.x;
    int d4  = threadIdx.x;
    int tok = tgt[row];
    int s   = row & (SS - 1);
    float4 e = ((const float4*)(emb + (size_t)tok*DD))[d4];
    float4 p = ((const float4*)(pos + (size_t)s*DD))[d4];
    float4 v = make_float4(e.x+p.x, e.y+p.y, e.z+p.z, e.w+p.w);
    uint32_t h0, l0, h1, l1;
    split2(v.x, v.y, h0, l0);
    split2(v.z, v.w, h1, l1);
    ((uint2*)(xhi + (size_t)row*DD))[d4] = make_uint2(h0, h1);
    ((uint2*)(xlo + (size_t)row*DD))[d4] = make_uint2(l0, l1);
}

// ---------------------------------------------------------------------------
// Merged weight conversion: all 5 pools in ONE launch (segment dispatch).
// ---------------------------------------------------------------------------
#define CB_SAW  4608
#define CB_SAOW 1536
#define CB_FF1  6144
#define CB_FF2  6144
#define CB_FC   64
#define CB_TOT  (CB_SAW + CB_SAOW + CB_FF1 + CB_FF2 + CB_FC)

__global__ void __launch_bounds__(256)
conv_all(const float* __restrict__ sa_w, const float* __restrict__ sa_ow,
         const float* __restrict__ ff1_w, const float* __restrict__ ff2_w,
         const float* __restrict__ fc_w,
         __nv_bfloat16* __restrict__ whi, __nv_bfloat16* __restrict__ wlo) {
    int bid = blockIdx.x;
    const float* src;
    size_t dst;
    if (bid < CB_SAW)                       { src = sa_w;  dst = O_SAW;  }
    else if ((bid -= CB_SAW)  < CB_SAOW)    { src = sa_ow; dst = O_SAOW; }
    else if ((bid -= CB_SAOW) < CB_FF1)     { src = ff1_w; dst = O_FF1;  }
    else if ((bid -= CB_FF1)  < CB_FF2)     { src = ff2_w; dst = O_FF2;  }
    else    { bid -= CB_FF2;                  src = fc_w;  dst = O_FC;   }

    size_t i = (size_t)bid * 256 + threadIdx.x;
    float4 v = ((const float4*)src)[i];
    uint32_t h0, l0, h1, l1;
    split2(v.x, v.y, h0, l0);
    split2(v.z, v.w, h1, l1);
    ((uint2*)(whi + dst))[i] = make_uint2(h0, h1);
    ((uint2*)(wlo + dst))[i] = make_uint2(l0, l1);
}

// ---------------------------------------------------------------------------
// Warp-per-output dot-product GEMM for tiny M=64 shapes (z-batched).
// C[b,n] = sum_k A[b,k]*W[n,k] + bias[n].  K multiple of 128. N=512, B=64.
// grid: (BB*N/8, 1, z), block 256 (8 warps, 1 output each).
// ---------------------------------------------------------------------------
__global__ void __launch_bounds__(256)
gemm_dot(const float* __restrict__ A, size_t astr,
         const float* __restrict__ W, size_t wstr,
         const float* __restrict__ bias, size_t bistr,
         float* __restrict__ C, size_t cstr, int N, int K) {
    const int zz = blockIdx.z;
    A += zz*astr; W += zz*wstr; bias += zz*bistr; C += zz*cstr;

    int gw = blockIdx.x*8 + (threadIdx.x >> 5);
    int lane = threadIdx.x & 31;
    int b = gw / N, n = gw - b*N;
    const float* ap = A + (size_t)b*K;
    const float* wp = W + (size_t)n*K;

    float acc = 0.f;
    for (int k = lane*4; k < K; k += 128) {
        float4 av = *(const float4*)(ap + k);
        float4 wv = *(const float4*)(wp + k);
        acc = fmaf(av.x, wv.x, acc);
        acc = fmaf(av.y, wv.y, acc);
        acc = fmaf(av.z, wv.z, acc);
        acc = fmaf(av.w, wv.w, acc);
    }
    #pragma unroll
    for (int o = 16; o; o >>= 1) acc += __shfl_xor_sync(~0u, acc, o);
    if (lane == 0) C[(size_t)b*N + n] = acc + bias[n];
}

// ---------------------------------------------------------------------------
// PERSISTENT HMMA bf16x3 GEMM (unchanged from R13 winner)
// ---------------------------------------------------------------------------
#define HSTAGE 65536
#define HSMEM  (3*HSTAGE)

__global__ void __launch_bounds__(256, 1)
gemm_hmma(const __nv_bfloat16* __restrict__ Ahi,
          const __nv_bfloat16* __restrict__ Alo,
          const __nv_bfloat16* __restrict__ Bhi,
          const __nv_bfloat16* __restrict__ Blo,
          const float* __restrict__ bias, float* __restrict__ C,
          __nv_bfloat16* __restrict__ Chi, __nv_bfloat16* __restrict__ Clo,
          int N, int K, int relu, int mode, int ntx, int ntiles) {
    extern __shared__ char smg[];
    const uint32_t sa = smem_u32(smg);
    const int tid = threadIdx.x;
    const int wid = tid >> 5, lane = tid & 31;
    const int wM = wid >> 2, wN = wid & 3;
    const int kc = K >> 6;

    const int laneA_row = lane & 15;
    const int laneA_b   = (lane >> 4) << 4;
    const int laneB_row = ((lane >> 4) << 3) + (lane & 7);
    const int laneB_b   = ((lane >> 3) & 1) << 4;
    const int gid = lane >> 2, tig = lane & 3;

    int dec_pool[8], dec_r[8];
    uint32_t offA[8], offB[8];
    #pragma unroll
    for (int it = 0; it < 8; it++) {
        int i = tid + it*256;
        int pool = i >> 10, r = (i >> 3) & 127, c = i & 7;
        dec_pool[it] = pool; dec_r[it] = r;
        uint32_t sw = (uint32_t)((c*16) ^ ((r & 7) << 4));
        offA[it] = pool*16384 + r*128 + sw;
        offB[it] = 32768 + pool*16384 + r*128 + sw;
    }

    for (int tile = blockIdx.x; tile < ntiles; tile += gridDim.x) {
        const int bm = (tile / ntx) * 128;
        const int bn = (tile % ntx) * 128;

        const char* srcA[8];
        const char* srcB[8];
        #pragma unroll
        for (int it = 0; it < 8; it++) {
            int i = tid + it*256;
            int c = i & 7;
            srcA[it] = (const char*)((dec_pool[it] ? Alo : Ahi) +
                                     (size_t)(bm + dec_r[it])*K + c*8);
            srcB[it] = (const char*)((dec_pool[it] ? Blo : Bhi) +
                                     (size_t)(bn + dec_r[it])*K + c*8);
        }

        __syncthreads();

        float acc[4][4][4];
        #pragma unroll
        for (int i = 0; i < 4; i++)
            #pragma unroll
            for (int j = 0; j < 4; j++)
                #pragma unroll
                for (int e = 0; e < 4; e++) acc[i][j][e] = 0.f;

        auto load_stage = [&](int s, int kk) {
            uint32_t stg = sa + s*HSTAGE;
            int kb = kk << 7;
            #pragma unroll
            for (int it = 0; it < 8; it++)
                cp_async16(stg + offA[it], srcA[it] + kb);
            #pragma unroll
            for (int it = 0; it < 8; it++)
                cp_async16(stg + offB[it], srcB[it] + kb);
        };

        load_stage(0, 0); CP_COMMIT();
        load_stage(1, 1); CP_COMMIT();

        int sidx = 0;
        for (int ch = 0; ch < kc; ch++) {
            CP_WAIT1();
            __syncthreads();

            if (ch + 2 < kc) {
                int st2 = sidx + 2; if (st2 >= 3) st2 -= 3;
                load_stage(st2, ch + 2);
            }
            CP_COMMIT();

            uint32_t stg = sa + sidx*HSTAGE;
            #pragma unroll
            for (int ks = 0; ks < 4; ks++) {
                uint32_t ah[4][4], al[4][4], bh[2][4], bl[2][4];
                #pragma unroll
                for (int mf = 0; mf < 4; mf++) {
                    int r = wM*64 + mf*16 + laneA_row;
                    uint32_t off = r*128 + (((uint32_t)(ks*32 + laneA_b)) ^ ((r & 7) << 4));
                    ldm_x4(ah[mf], stg + off);
                    ldm_x4(al[mf], stg + 16384 + off);
                }
                #pragma unroll
                for (int nf2 = 0; nf2 < 2; nf2++) {
                    int r = wN*32 + nf2*16 + laneB_row;
                    uint32_t off = r*128 + (((uint32_t)(ks*32 + laneB_b)) ^ ((r & 7) << 4));
                    ldm_x4(bh[nf2], stg + 32768 + off);
                    ldm_x4(bl[nf2], stg + 49152 + off);
                }
                #pragma unroll
                for (int mf = 0; mf < 4; mf++)
                    #pragma unroll
                    for (int nf = 0; nf < 4; nf++) {
                        const uint32_t* bhf = &bh[nf >> 1][(nf & 1)*2];
                        const uint32_t* blf = &bl[nf >> 1][(nf & 1)*2];
                        mma_bf16(acc[mf][nf], ah[mf], bhf);
                        mma_bf16(acc[mf][nf], ah[mf], blf);
                        mma_bf16(acc[mf][nf], al[mf], bhf);
                    }
            }
            sidx = (sidx == 2) ? 0 : sidx + 1;
        }

        #pragma unroll
        for (int mf = 0; mf < 4; mf++) {
            int r0 = bm + wM*64 + mf*16 + gid;
            #pragma unroll
            for (int nf = 0; nf < 4; nf++) {
                int col = bn + wN*32 + nf*8 + tig*2;
                float bx = __ldg(bias + col), by = __ldg(bias + col + 1);
                float v0x = acc[mf][nf][0] + bx, v0y = acc[mf][nf][1] + by;
                float v1x = acc[mf][nf][2] + bx, v1y = acc[mf][nf][3] + by;
                if (relu) {
                    v0x = fmaxf(v0x, 0.f); v0y = fmaxf(v0y, 0.f);
                    v1x = fmaxf(v1x, 0.f); v1y = fmaxf(v1y, 0.f);
                }
                if (mode == 0) {
                    *(float2*)(C + (size_t)r0*N + col)       = make_float2(v0x, v0y);
                    *(float2*)(C + (size_t)(r0 + 8)*N + col) = make_float2(v1x, v1y);
                } else {
                    uint32_t h, l;
                    size_t i0 = (size_t)r0*N + col, i1 = (size_t)(r0 + 8)*N + col;
                    split2(v0x, v0y, h, l);
                    *(uint32_t*)(Chi + i0) = h; *(uint32_t*)(Clo + i0) = l;
                    split2(v1x, v1y, h, l);
                    *(uint32_t*)(Chi + i1) = h; *(uint32_t*)(Clo + i1) = l;
                }
            }
        }
    }
}

// ---------------------------------------------------------------------------
// HMMA causal attention (unchanged)
// ---------------------------------------------------------------------------
#define OQH 0
#define OQL 8192
#define OKH 16384
#define OKL 49152
#define OVH 81920
#define OVL 114688
#define OPH 147456
#define OPL 180224
#define ORED 212992
#define ATT_SMEM (ORED + 1024)

__global__ void __launch_bounds__(256, 1)
attn_hmma(const __nv_bfloat16* __restrict__ qhi,
          const __nv_bfloat16* __restrict__ qlo,
          __nv_bfloat16* __restrict__ ohi,
          __nv_bfloat16* __restrict__ olo) {
    extern __shared__ char smg[];
    const uint32_t sa = smem_u32(smg);
    const int tid = threadIdx.x;
    const int wid = tid >> 5, lane = tid & 31;
    const int wM = wid >> 1, wN = wid & 1;
    const int gid = lane >> 2, tig = lane & 3;

    const int bid = blockIdx.x;
    const int qb = 3 - (bid & 3);
    const int h  = (bid >> 2) & 7;
    const int b  = bid >> 5;
    const int krows = (qb + 1) * 64;

    auto load_tile = [&](const __nv_bfloat16* g, uint32_t sbase, int rows) {
        for (int i = tid; i < rows*8; i += 256) {
            int r = i >> 3, c = i & 7;
            cp_async16(sa + sbase + r*128 + ((c*16) ^ ((r & 7) << 4)),
                       g + (size_t)r*1536 + c*8);
        }
    };
    const size_t qbase = (size_t)(b*SS + qb*64)*1536 + h*DH;
    const size_t kbase = (size_t)(b*SS)*1536 + DD + h*DH;
    const size_t vbase = (size_t)(b*SS)*1536 + 2*DD + h*DH;
    load_tile(qhi + qbase, OQH, 64);
    load_tile(qlo + qbase, OQL, 64);
    load_tile(qhi + kbase, OKH, krows);
    load_tile(qlo + kbase, OKL, krows);
    CP_COMMIT();
    load_tile(qhi + vbase, OVH, krows);
    load_tile(qlo + vbase, OVL, krows);
    CP_COMMIT();
    CP_WAIT1();
    __syncthreads();

    const int laneA_row = lane & 15;
    const int laneA_b   = (lane >> 4) << 4;
    const int laneB_row = ((lane >> 4) << 3) + (lane & 7);
    const int laneB_b   = ((lane >> 3) & 1) << 4;

    float s[16][4];
    #pragma unroll
    for (int nt = 0; nt < 16; nt++)
        #pragma unroll
        for (int e = 0; e < 4; e++) s[nt][e] = 0.f;

    #pragma unroll
    for (int ks = 0; ks < 4; ks++) {
        uint32_t ah[4], al[4];
        {
            int r = wM*16 + laneA_row;
            uint32_t off = r*128 + (((uint32_t)(ks*32 + laneA_b)) ^ ((r & 7) << 4));
            ldm_x4(ah, sa + OQH + off);
            ldm_x4(al, sa + OQL + off);
        }
        #pragma unroll
        for (int ng = 0; ng < 8; ng++) {
            uint32_t bh4[4], bl4[4];
            int r = wN*128 + ng*16 + laneB_row;
            uint32_t off = r*128 + (((uint32_t)(ks*32 + laneB_b)) ^ ((r & 7) << 4));
            ldm_x4(bh4, sa + OKH + off);
            ldm_x4(bl4, sa + OKL + off);
            #pragma unroll
            for (int j = 0; j < 2; j++) {
                float* a = s[ng*2 + j];
                mma_bf16(a, ah, &bh4[j*2]);
                mma_bf16(a, ah, &bl4[j*2]);
                mma_bf16(a, al, &bh4[j*2]);
            }
        }
    }

    const int qrow0 = qb*64 + wM*16 + gid;
    const int qrow1 = qrow0 + 8;
    float m0 = -1e30f, m1 = -1e30f;
    #pragma unroll
    for (int nt = 0; nt < 16; nt++) {
        int c0 = wN*128 + nt*8 + tig*2;
        s[nt][0] = (c0     <= qrow0) ? s[nt][0]*0.125f : -1e30f;
        s[nt][1] = (c0 + 1 <= qrow0) ? s[nt][1]*0.125f : -1e30f;
        s[nt][2] = (c0     <= qrow1) ? s[nt][2]*0.125f : -1e30f;
        s[nt][3] = (c0 + 1 <= qrow1) ? s[nt][3]*0.125f : -1e30f;
        m0 = fmaxf(m0, fmaxf(s[nt][0], s[nt][1]));
        m1 = fmaxf(m1, fmaxf(s[nt][2], s[nt][3]));
    }
    #pragma unroll
    for (int o = 1; o <= 2; o <<= 1) {
        m0 = fmaxf(m0, __shfl_xor_sync(~0u, m0, o));
        m1 = fmaxf(m1, __shfl_xor_sync(~0u, m1, o));
    }
    float* redm = (float*)(smg + ORED);
    float* reds = (float*)(smg + ORED + 512);
    int r0l = wM*16 + gid;
    if (tig == 0) { redm[wN*64 + r0l] = m0; redm[wN*64 + r0l + 8] = m1; }
    __syncthreads();
    m0 = fmaxf(redm[r0l],     redm[64 + r0l]);
    m1 = fmaxf(redm[r0l + 8], redm[64 + r0l + 8]);

    float sum0 = 0.f, sum1 = 0.f;
    #pragma unroll
    for (int nt = 0; nt < 16; nt++) {
        s[nt][0] = __expf(s[nt][0] - m0);
        s[nt][1] = __expf(s[nt][1] - m0);
        s[nt][2] = __expf(s[nt][2] - m1);
        s[nt][3] = __expf(s[nt][3] - m1);
        sum0 += s[nt][0] + s[nt][1];
        sum1 += s[nt][2] + s[nt][3];
    }
    #pragma unroll
    for (int o = 1; o <= 2; o <<= 1) {
        sum0 += __shfl_xor_sync(~0u, sum0, o);
        sum1 += __shfl_xor_sync(~0u, sum1, o);
    }
    if (tig == 0) { reds[wN*64 + r0l] = sum0; reds[wN*64 + r0l + 8] = sum1; }
    __syncthreads();
    float inv0 = 1.f / (reds[r0l]     + reds[64 + r0l]);
    float inv1 = 1.f / (reds[r0l + 8] + reds[64 + r0l + 8]);

    #pragma unroll
    for (int nt = 0; nt < 16; nt++) {
        int c0 = wN*128 + nt*8 + tig*2;
        int kb = c0 >> 6, cb = c0 & 63;
        uint32_t sw0 = (uint32_t)(cb*2) ^ ((r0l & 7) << 4);
        uint32_t sw1 = (uint32_t)(cb*2) ^ (((r0l + 8) & 7) << 4);
        uint32_t off0 = kb*8192 + r0l*128 + sw0;
        uint32_t off1 = kb*8192 + (r0l + 8)*128 + sw1;
        uint32_t h, l;
        split2(s[nt][0]*inv0, s[nt][1]*inv0, h, l);
        *(uint32_t*)(smg + OPH + off0) = h;
        *(uint32_t*)(smg + OPL + off0) = l;
        split2(s[nt][2]*inv1, s[nt][3]*inv1, h, l);
        *(uint32_t*)(smg + OPH + off1) = h;
        *(uint32_t*)(smg + OPL + off1) = l;
    }
    CP_WAIT0();
    __syncthreads();

    float o[4][4];
    #pragma unroll
    for (int nt = 0; nt < 4; nt++)
        #pragma unroll
        for (int e = 0; e < 4; e++) o[nt][e] = 0.f;

    const int vlrow = lane & 15;
    const uint32_t cbyte0 = (uint32_t)(wN*64 + ((lane >> 4) << 4));
    for (int kb = 0; kb <= qb; kb++) {
        #pragma unroll
        for (int ks = 0; ks < 4; ks++) {
            uint32_t ph4[4], pl4[4];
            {
                int r = wM*16 + laneA_row;
                uint32_t off = kb*8192 + r*128 +
                               (((uint32_t)(ks*32 + laneA_b)) ^ ((r & 7) << 4));
                ldm_x4(ph4, sa + OPH + off);
                ldm_x4(pl4, sa + OPL + off);
            }
            int vr = kb*64 + ks*16 + vlrow;
            #pragma unroll
            for (int chh = 0; chh < 2; chh++) {
                uint32_t vh4[4], vl4[4];
                uint32_t voff = vr*128 + ((cbyte0 + chh*32) ^ ((vr & 7) << 4));
                ldm_x4t(vh4, sa + OVH + voff);
                ldm_x4t(vl4, sa + OVL + voff);
                #pragma unroll
                for (int j = 0; j < 2; j++) {
                    float* a = o[chh*2 + j];
                    mma_bf16(a, ph4, &vh4[j*2]);
                    mma_bf16(a, ph4, &vl4[j*2]);
                    mma_bf16(a, pl4, &vh4[j*2]);
                }
            }
        }
    }

    const int gr0 = b*SS + qb*64 + wM*16 + gid;
    #pragma unroll
    for (int nt = 0; nt < 4; nt++) {
        int col = h*DH + wN*32 + nt*8 + tig*2;
        uint32_t h0, l0, h1, l1;
        split2(o[nt][0], o[nt][1], h0, l0);
        split2(o[nt][2], o[nt][3], h1, l1);
        size_t i0 = (size_t)gr0*DD + col, i1 = (size_t)(gr0 + 8)*DD + col;
        *(uint32_t*)(ohi + i0) = h0; *(uint32_t*)(olo + i0) = l0;
        *(uint32_t*)(ohi + i1) = h1; *(uint32_t*)(olo + i1) = l1;
    }
}

// ---------------------------------------------------------------------------
// LN body (device helper)
// ---------------------------------------------------------------------------
__device__ __forceinline__ void ln_block(float* v, const float4 gv,
                                         const float4 bv, int t,
                                         float* red, float* o) {
    float sum = v[0] + v[1] + v[2] + v[3];
    #pragma unroll
    for (int oo = 16; oo; oo >>= 1) sum += __shfl_xor_sync(~0u, sum, oo);
    if ((t & 31) == 0) red[t >> 5] = sum;
    __syncthreads();
    float mean = (red[0] + red[1] + red[2] + red[3]) * (1.f/512.f);
    float var = 0.f;
    #pragma unroll
    for (int i = 0; i < 4; i++) {
        float d = v[i] - mean;
        var = fmaf(d, d, var);
    }
    #pragma unroll
    for (int oo = 16; oo; oo >>= 1) var += __shfl_xor_sync(~0u, var, oo);
    if ((t & 31) == 0) red[4 + (t >> 5)] = var;
    __syncthreads();
    float rs = rsqrtf((red[4] + red[5] + red[6] + red[7]) * (1.f/512.f) + 1e-5f);
    o[0] = (v[0] - mean) * rs * gv.x + bv.x;
    o[1] = (v[1] - mean) * rs * gv.y + bv.y;
    o[2] = (v[2] - mean) * rs * gv.z + bv.z;
    o[3] = (v[3] - mean) * rs * gv.w + bv.w;
}

__global__ void __launch_bounds__(128)
add_ln_kernel(__nv_bfloat16* __restrict__ xhi, __nv_bfloat16* __restrict__ xlo,
              const float* __restrict__ r,
              const float* __restrict__ g, const float* __restrict__ bt) {
    int row = blockIdx.x;
    const float* rp = r + (size_t)row*DD;
    int t = threadIdx.x;
    __shared__ float red[8];

    uint2 hp = ((const uint2*)(xhi + (size_t)row*DD))[t];
    uint2 lp = ((const uint2*)(xlo + (size_t)row*DD))[t];
    float v[4];
    join2(hp.x, lp.x, v[0], v[1]);
    join2(hp.y, lp.y, v[2], v[3]);
    float4 rv = ((const float4*)rp)[t];
    v[0] += rv.x; v[1] += rv.y; v[2] += rv.z; v[3] += rv.w;

    float o[4];
    ln_block(v, ((const float4*)g)[t], ((const float4*)bt)[t], t, red, o);
    uint32_t h0, l0, h1, l1;
    split2(o[0], o[1], h0, l0);
    split2(o[2], o[3], h1, l1);
    ((uint2*)(xhi + (size_t)row*DD))[t] = make_uint2(h0, h1);
    ((uint2*)(xlo + (size_t)row*DD))[t] = make_uint2(l0, l1);
}

__global__ void __launch_bounds__(128)
add_ln2_kernel(__nv_bfloat16* __restrict__ xhi, __nv_bfloat16* __restrict__ xlo,
               const float* __restrict__ sub, const float* __restrict__ ca,
               const float* __restrict__ g1, const float* __restrict__ b1,
               const float* __restrict__ g2, const float* __restrict__ b2) {
    int row = blockIdx.x;
    const float* sp = sub + (size_t)row*DD;
    const float* cp = ca + (size_t)(row >> 8)*DD;
    int t = threadIdx.x;
    __shared__ float red[8];

    uint2 hp = ((const uint2*)(xhi + (size_t)row*DD))[t];
    uint2 lp = ((const uint2*)(xlo + (size_t)row*DD))[t];
    float v[4];
    join2(hp.x, lp.x, v[0], v[1]);
    join2(hp.y, lp.y, v[2], v[3]);
    float4 sv = ((const float4*)sp)[t];
    v[0] += sv.x; v[1] += sv.y; v[2] += sv.z; v[3] += sv.w;

    float y1[4];
    ln_block(v, ((const float4*)g1)[t], ((const float4*)b1)[t], t, red, y1);
    __syncthreads();

    float4 cv = ((const float4*)cp)[t];
    float v2[4] = {y1[0]+cv.x, y1[1]+cv.y, y1[2]+cv.z, y1[3]+cv.w};
    float o[4];
    ln_block(v2, ((const float4*)g2)[t], ((const float4*)b2)[t], t, red, o);
    uint32_t h0, l0, h1, l1;
    split2(o[0], o[1], h0, l0);
    split2(o[2], o[3], h1, l1);
    ((uint2*)(xhi + (size_t)row*DD))[t] = make_uint2(h0, h1);
    ((uint2*)(xlo + (size_t)row*DD))[t] = make_uint2(l0, l1);
}

// ---------------------------------------------------------------------------
// Launch
// ---------------------------------------------------------------------------
extern "C" void kernel_launch(void* const* d_in, const int* in_sizes, int n_in,
                              void* d_out, int out_size) {
    const float* z      = (const float*)d_in[0];
    const int*   tgt    = (const int*)  d_in[1];
    const float* emb    = (const float*)d_in[2];
    const float* pos    = (const float*)d_in[3];
    const float* proj_w = (const float*)d_in[4];
    const float* proj_b = (const float*)d_in[5];
    const float* sa_w   = (const float*)d_in[6];
    const float* sa_b   = (const float*)d_in[7];
    const float* sa_ow  = (const float*)d_in[8];
    const float* sa_ob  = (const float*)d_in[9];
    const float* ca_w   = (const float*)d_in[10];
    const float* ca_b   = (const float*)d_in[11];
    const float* ca_ow  = (const float*)d_in[12];
    const float* ca_ob  = (const float*)d_in[13];
    const float* ln1_s  = (const float*)d_in[14];
    const float* ln1_b  = (const float*)d_in[15];
    const float* ln2_s  = (const float*)d_in[16];
    const float* ln2_b  = (const float*)d_in[17];
    const float* ln3_s  = (const float*)d_in[18];
    const float* ln3_b  = (const float*)d_in[19];
    const float* ff1_w  = (const float*)d_in[20];
    const float* ff1_b  = (const float*)d_in[21];
    const float* ff2_w  = (const float*)d_in[22];
    const float* ff2_b  = (const float*)d_in[23];
    const float* fc_w   = (const float*)d_in[24];
    const float* fc_b   = (const float*)d_in[25];
    float* out = (float*)d_out;

    float *sub, *mem, *cav, *ca;
    __nv_bfloat16 *ahi, *alo, *qhi, *qlo, *fhi, *flo, *whi, *wlo;
    cudaGetSymbolAddress((void**)&sub, g_sub);
    cudaGetSymbolAddress((void**)&mem, g_mem);
    cudaGetSymbolAddress((void**)&cav, g_cav);
    cudaGetSymbolAddress((void**)&ca,  g_ca);
    cudaGetSymbolAddress((void**)&ahi, g_ahi);
    cudaGetSymbolAddress((void**)&alo, g_alo);
    cudaGetSymbolAddress((void**)&qhi, g_qhi);
    cudaGetSymbolAddress((void**)&qlo, g_qlo);
    cudaGetSymbolAddress((void**)&fhi, g_fhi);
    cudaGetSymbolAddress((void**)&flo, g_flo);
    cudaGetSymbolAddress((void**)&whi, g_whi);
    cudaGetSymbolAddress((void**)&wlo, g_wlo);

    cudaFuncSetAttribute(gemm_hmma,
                         cudaFuncAttributeMaxDynamicSharedMemorySize, HSMEM);
    cudaFuncSetAttribute(attn_hmma,
                         cudaFuncAttributeMaxDynamicSharedMemorySize, ATT_SMEM);

    // (1) merged weight conversion
    conv_all<<<CB_TOT, 256>>>(sa_w, sa_ow, ff1_w, ff2_w, fc_w, whi, wlo);

    // (2) embedding
    embed_kernel<<<M_TOK, 128>>>(tgt, emb, pos, ahi, alo);

    // (3-5) memory projection + batched cross-attn vectors (warp-dot GEMMs)
    gemm_dot<<<dim3(BB*DD/8, 1, 1), 256>>>(z, 0, proj_w, 0, proj_b, 0,
                                           mem, 0, DD, DD);
    gemm_dot<<<dim3(BB*DD/8, 1, LL), 256>>>(
        mem, 0,
        ca_w + (size_t)2*DD*DD, (size_t)3*DD*DD,
        ca_b + 2*DD, (size_t)3*DD,
        cav, (size_t)BB*DD, DD, DD);
    gemm_dot<<<dim3(BB*DD/8, 1, LL), 256>>>(
        cav, (size_t)BB*DD,
        ca_ow, (size_t)DD*DD,
        ca_ob, (size_t)DD,
        ca, (size_t)BB*DD, DD, DD);

    const int PGRID = 148;

    for (int l = 0; l < LL; l++) {
        const float* sabl  = sa_b  + (size_t)l*3*DD;
        const float* saobl = sa_ob + (size_t)l*DD;
        size_t o_qkv = O_SAW  + (size_t)l*3*DD*DD;
        size_t o_ow  = O_SAOW + (size_t)l*DD*DD;
        size_t o_ff1 = O_FF1  + (size_t)l*DFF*DD;
        size_t o_ff2 = O_FF2  + (size_t)l*DD*DFF;

        // self-attention
        gemm_hmma<<<PGRID, 256, HSMEM>>>(ahi, alo, whi + o_qkv, wlo + o_qkv,
                                         sabl, nullptr, qhi, qlo,
                                         3*DD, DD, 0, 1, 12, 12*128);
        attn_hmma<<<BB*HH*4, 256, ATT_SMEM>>>(qhi, qlo, fhi, flo);
        gemm_hmma<<<PGRID, 256, HSMEM>>>(fhi, flo, whi + o_ow, wlo + o_ow,
                                         saobl, sub, nullptr, nullptr,
                                         DD, DD, 0, 0, 4, 4*128);
        add_ln2_kernel<<<M_TOK, 128>>>(ahi, alo, sub, ca + (size_t)l*BB*DD,
                                       ln1_s + l*DD, ln1_b + l*DD,
                                       ln2_s + l*DD, ln2_b + l*DD);

        // feed-forward
        gemm_hmma<<<PGRID, 256, HSMEM>>>(ahi, alo, whi + o_ff1, wlo + o_ff1,
                                         ff1_b + l*DFF, nullptr, fhi, flo,
                                         DFF, DD, 1, 1, 16, 16*128);
        gemm_hmma<<<PGRID, 256, HSMEM>>>(fhi, flo, whi + o_ff2, wlo + o_ff2,
                                         ff2_b + l*DD, sub, nullptr, nullptr,
                                         DD, DFF, 0, 0, 4, 4*128);
        add_ln_kernel<<<M_TOK, 128>>>(ahi, alo, sub,
                                      ln3_s + l*DD, ln3_b + l*DD);
    }

    // final classifier
    gemm_hmma<<<128, 256, HSMEM>>>(ahi, alo, whi + O_FC, wlo + O_FC,
                                   fc_b, out, nullptr, nullptr,
                                   VV, DD, 0, 0, 1, 128);
}

// round 15
// speedup vs baseline: 1.6577x; 1.0070x over previous
#include <cuda_runtime.h>
#include <cuda_bf16.h>
#include <math.h>
#include <stdint.h>

#define BB 64
#define SS 256
#define DD 512
#define HH 8
#define DH 64
#define DFF 2048
#define VV 128
#define LL 6
#define M_TOK (BB*SS)

// ---------------------------------------------------------------------------
// Scratch
// ---------------------------------------------------------------------------
__device__ float g_sub[M_TOK*DD];
__device__ float g_mem[BB*DD];
__device__ float g_cav[LL*BB*DD];
__device__ float g_ca [LL*BB*DD];

__device__ __nv_bfloat16 g_ahi[(size_t)M_TOK*DD];
__device__ __nv_bfloat16 g_alo[(size_t)M_TOK*DD];
__device__ __nv_bfloat16 g_qhi[(size_t)M_TOK*3*DD];
__device__ __nv_bfloat16 g_qlo[(size_t)M_TOK*3*DD];
__device__ __nv_bfloat16 g_fhi[(size_t)M_TOK*DFF];
__device__ __nv_bfloat16 g_flo[(size_t)M_TOK*DFF];

#define O_SAW  0u
#define O_SAOW 4718592u
#define O_FF1  6291456u
#define O_FF2  12582912u
#define O_FC   18874368u
#define WPOOL_E 18940032u
__device__ __nv_bfloat16 g_whi[WPOOL_E];
__device__ __nv_bfloat16 g_wlo[WPOOL_E];

// ---------------------------------------------------------------------------
// Helpers
// ---------------------------------------------------------------------------
__device__ __forceinline__ uint32_t smem_u32(const void* p) {
    uint32_t a;
    asm("{ .reg .u64 t; cvta.to.shared.u64 t, %1; cvt.u32.u64 %0, t; }"
        : "=r"(a) : "l"(p));
    return a;
}
__device__ __forceinline__ void cp_async16(uint32_t dst, const void* src) {
    asm volatile("cp.async.cg.shared.global [%0], [%1], 16;"
                 :: "r"(dst), "l"(src));
}
#define CP_COMMIT() asm volatile("cp.async.commit_group;" ::: "memory")
#define CP_WAIT1()  asm volatile("cp.async.wait_group 1;" ::: "memory")
#define CP_WAIT0()  asm volatile("cp.async.wait_group 0;" ::: "memory")

__device__ __forceinline__ void ldm_x4(uint32_t* r, uint32_t addr) {
    asm volatile("ldmatrix.sync.aligned.m8n8.x4.shared.b16 {%0,%1,%2,%3}, [%4];"
                 : "=r"(r[0]), "=r"(r[1]), "=r"(r[2]), "=r"(r[3]) : "r"(addr));
}
__device__ __forceinline__ void ldm_x4t(uint32_t* r, uint32_t addr) {
    asm volatile("ldmatrix.sync.aligned.m8n8.x4.trans.shared.b16 {%0,%1,%2,%3}, [%4];"
                 : "=r"(r[0]), "=r"(r[1]), "=r"(r[2]), "=r"(r[3]) : "r"(addr));
}
__device__ __forceinline__ void mma_bf16(float* c, const uint32_t* a,
                                         const uint32_t* b) {
    asm volatile(
        "mma.sync.aligned.m16n8k16.row.col.f32.bf16.bf16.f32 "
        "{%0,%1,%2,%3}, {%4,%5,%6,%7}, {%8,%9}, {%0,%1,%2,%3};"
        : "+f"(c[0]), "+f"(c[1]), "+f"(c[2]), "+f"(c[3])
        : "r"(a[0]), "r"(a[1]), "r"(a[2]), "r"(a[3]), "r"(b[0]), "r"(b[1]));
}
__device__ __forceinline__ uint32_t pack2bf(float a, float b) {
    __nv_bfloat162 t = __floats2bfloat162_rn(a, b);
    return *(uint32_t*)&t;
}
__device__ __forceinline__ void split2(float a, float b, uint32_t& hi, uint32_t& lo) {
    __nv_bfloat16 ha = __float2bfloat16_rn(a);
    __nv_bfloat16 hb = __float2bfloat16_rn(b);
    hi = pack2bf(__bfloat162float(ha), __bfloat162float(hb));
    lo = pack2bf(a - __bfloat162float(ha), b - __bfloat162float(hb));
}
__device__ __forceinline__ void join2(uint32_t hi, uint32_t lo, float& a, float& b) {
    __nv_bfloat162 h = *(__nv_bfloat162*)&hi;
    __nv_bfloat162 l = *(__nv_bfloat162*)&lo;
    a = __bfloat162float(h.x) + __bfloat162float(l.x);
    b = __bfloat162float(h.y) + __bfloat162float(l.y);
}

// ---------------------------------------------------------------------------
// Embedding -> hi/lo residual stream only
// ---------------------------------------------------------------------------
__global__ void embed_kernel(const int* __restrict__ tgt,
                             const float* __restrict__ emb,
                             const float* __restrict__ pos,
                             __nv_bfloat16* __restrict__ xhi,
                             __nv_bfloat16* __restrict__ xlo) {
    int row = blockIdx.x;
    int d4  = threadIdx.x;
    int tok = tgt[row];
    int s   = row & (SS - 1);
    float4 e = ((const float4*)(emb + (size_t)tok*DD))[d4];
    float4 p = ((const float4*)(pos + (size_t)s*DD))[d4];
    float4 v = make_float4(e.x+p.x, e.y+p.y, e.z+p.z, e.w+p.w);
    uint32_t h0, l0, h1, l1;
    split2(v.x, v.y, h0, l0);
    split2(v.z, v.w, h1, l1);
    ((uint2*)(xhi + (size_t)row*DD))[d4] = make_uint2(h0, h1);
    ((uint2*)(xlo + (size_t)row*DD))[d4] = make_uint2(l0, l1);
}

// ---------------------------------------------------------------------------
// Merged weight conversion: all 5 pools in ONE launch
// ---------------------------------------------------------------------------
#define CB_SAW  4608
#define CB_SAOW 1536
#define CB_FF1  6144
#define CB_FF2  6144
#define CB_FC   64
#define CB_TOT  (CB_SAW + CB_SAOW + CB_FF1 + CB_FF2 + CB_FC)

__global__ void __launch_bounds__(256)
conv_all(const float* __restrict__ sa_w, const float* __restrict__ sa_ow,
         const float* __restrict__ ff1_w, const float* __restrict__ ff2_w,
         const float* __restrict__ fc_w,
         __nv_bfloat16* __restrict__ whi, __nv_bfloat16* __restrict__ wlo) {
    int bid = blockIdx.x;
    const float* src;
    size_t dst;
    if (bid < CB_SAW)                       { src = sa_w;  dst = O_SAW;  }
    else if ((bid -= CB_SAW)  < CB_SAOW)    { src = sa_ow; dst = O_SAOW; }
    else if ((bid -= CB_SAOW) < CB_FF1)     { src = ff1_w; dst = O_FF1;  }
    else if ((bid -= CB_FF1)  < CB_FF2)     { src = ff2_w; dst = O_FF2;  }
    else    { bid -= CB_FF2;                  src = fc_w;  dst = O_FC;   }

    size_t i = (size_t)bid * 256 + threadIdx.x;
    float4 v = ((const float4*)src)[i];
    uint32_t h0, l0, h1, l1;
    split2(v.x, v.y, h0, l0);
    split2(v.z, v.w, h1, l1);
    ((uint2*)(whi + dst))[i] = make_uint2(h0, h1);
    ((uint2*)(wlo + dst))[i] = make_uint2(l0, l1);
}

// ---------------------------------------------------------------------------
// Warp-per-8-outputs dot GEMM for tiny M=64 shapes (z-batched).
// Warp owns (b, n0..n0+7): C[b,n0+j] = sum_k A[b,k]*W[n0+j,k] + bias.
// grid: (BB*(N/8)/8, 1, z) = 512 blocks, block 256 (8 warps).
// ---------------------------------------------------------------------------
__global__ void __launch_bounds__(256)
gemm_dot(const float* __restrict__ A, size_t astr,
         const float* __restrict__ W, size_t wstr,
         const float* __restrict__ bias, size_t bistr,
         float* __restrict__ C, size_t cstr, int N, int K) {
    const int zz = blockIdx.z;
    A += zz*astr; W += zz*wstr; bias += zz*bistr; C += zz*cstr;

    const int ng = N >> 3;                       // n-groups of 8
    int gw = blockIdx.x*8 + (threadIdx.x >> 5);  // 0 .. BB*ng-1
    int lane = threadIdx.x & 31;
    int b = gw / ng, n0 = (gw - b*ng) * 8;
    const float* ap = A + (size_t)b*K;
    const float* wp = W + (size_t)n0*K;

    float acc[8];
    #pragma unroll
    for (int j = 0; j < 8; j++) acc[j] = 0.f;

    for (int k = lane*4; k < K; k += 128) {
        float4 av = *(const float4*)(ap + k);
        #pragma unroll
        for (int j = 0; j < 8; j++) {
            float4 wv = *(const float4*)(wp + (size_t)j*K + k);
            acc[j] = fmaf(av.x, wv.x, acc[j]);
            acc[j] = fmaf(av.y, wv.y, acc[j]);
            acc[j] = fmaf(av.z, wv.z, acc[j]);
            acc[j] = fmaf(av.w, wv.w, acc[j]);
        }
    }
    #pragma unroll
    for (int j = 0; j < 8; j++) {
        #pragma unroll
        for (int o = 16; o; o >>= 1)
            acc[j] += __shfl_xor_sync(~0u, acc[j], o);
    }
    if (lane < 8)
        C[(size_t)b*N + n0 + lane] = acc[lane] + bias[n0 + lane];
}

// ---------------------------------------------------------------------------
// PERSISTENT HMMA bf16x3 GEMM (unchanged)
// ---------------------------------------------------------------------------
#define HSTAGE 65536
#define HSMEM  (3*HSTAGE)

__global__ void __launch_bounds__(256, 1)
gemm_hmma(const __nv_bfloat16* __restrict__ Ahi,
          const __nv_bfloat16* __restrict__ Alo,
          const __nv_bfloat16* __restrict__ Bhi,
          const __nv_bfloat16* __restrict__ Blo,
          const float* __restrict__ bias, float* __restrict__ C,
          __nv_bfloat16* __restrict__ Chi, __nv_bfloat16* __restrict__ Clo,
          int N, int K, int relu, int mode, int ntx, int ntiles) {
    extern __shared__ char smg[];
    const uint32_t sa = smem_u32(smg);
    const int tid = threadIdx.x;
    const int wid = tid >> 5, lane = tid & 31;
    const int wM = wid >> 2, wN = wid & 3;
    const int kc = K >> 6;

    const int laneA_row = lane & 15;
    const int laneA_b   = (lane >> 4) << 4;
    const int laneB_row = ((lane >> 4) << 3) + (lane & 7);
    const int laneB_b   = ((lane >> 3) & 1) << 4;
    const int gid = lane >> 2, tig = lane & 3;

    int dec_pool[8], dec_r[8];
    uint32_t offA[8], offB[8];
    #pragma unroll
    for (int it = 0; it < 8; it++) {
        int i = tid + it*256;
        int pool = i >> 10, r = (i >> 3) & 127, c = i & 7;
        dec_pool[it] = pool; dec_r[it] = r;
        uint32_t sw = (uint32_t)((c*16) ^ ((r & 7) << 4));
        offA[it] = pool*16384 + r*128 + sw;
        offB[it] = 32768 + pool*16384 + r*128 + sw;
    }

    for (int tile = blockIdx.x; tile < ntiles; tile += gridDim.x) {
        const int bm = (tile / ntx) * 128;
        const int bn = (tile % ntx) * 128;

        const char* srcA[8];
        const char* srcB[8];
        #pragma unroll
        for (int it = 0; it < 8; it++) {
            int i = tid + it*256;
            int c = i & 7;
            srcA[it] = (const char*)((dec_pool[it] ? Alo : Ahi) +
                                     (size_t)(bm + dec_r[it])*K + c*8);
            srcB[it] = (const char*)((dec_pool[it] ? Blo : Bhi) +
                                     (size_t)(bn + dec_r[it])*K + c*8);
        }

        __syncthreads();

        float acc[4][4][4];
        #pragma unroll
        for (int i = 0; i < 4; i++)
            #pragma unroll
            for (int j = 0; j < 4; j++)
                #pragma unroll
                for (int e = 0; e < 4; e++) acc[i][j][e] = 0.f;

        auto load_stage = [&](int s, int kk) {
            uint32_t stg = sa + s*HSTAGE;
            int kb = kk << 7;
            #pragma unroll
            for (int it = 0; it < 8; it++)
                cp_async16(stg + offA[it], srcA[it] + kb);
            #pragma unroll
            for (int it = 0; it < 8; it++)
                cp_async16(stg + offB[it], srcB[it] + kb);
        };

        load_stage(0, 0); CP_COMMIT();
        load_stage(1, 1); CP_COMMIT();

        int sidx = 0;
        for (int ch = 0; ch < kc; ch++) {
            CP_WAIT1();
            __syncthreads();

            if (ch + 2 < kc) {
                int st2 = sidx + 2; if (st2 >= 3) st2 -= 3;
                load_stage(st2, ch + 2);
            }
            CP_COMMIT();

            uint32_t stg = sa + sidx*HSTAGE;
            #pragma unroll
            for (int ks = 0; ks < 4; ks++) {
                uint32_t ah[4][4], al[4][4], bh[2][4], bl[2][4];
                #pragma unroll
                for (int mf = 0; mf < 4; mf++) {
                    int r = wM*64 + mf*16 + laneA_row;
                    uint32_t off = r*128 + (((uint32_t)(ks*32 + laneA_b)) ^ ((r & 7) << 4));
                    ldm_x4(ah[mf], stg + off);
                    ldm_x4(al[mf], stg + 16384 + off);
                }
                #pragma unroll
                for (int nf2 = 0; nf2 < 2; nf2++) {
                    int r = wN*32 + nf2*16 + laneB_row;
                    uint32_t off = r*128 + (((uint32_t)(ks*32 + laneB_b)) ^ ((r & 7) << 4));
                    ldm_x4(bh[nf2], stg + 32768 + off);
                    ldm_x4(bl[nf2], stg + 49152 + off);
                }
                #pragma unroll
                for (int mf = 0; mf < 4; mf++)
                    #pragma unroll
                    for (int nf = 0; nf < 4; nf++) {
                        const uint32_t* bhf = &bh[nf >> 1][(nf & 1)*2];
                        const uint32_t* blf = &bl[nf >> 1][(nf & 1)*2];
                        mma_bf16(acc[mf][nf], ah[mf], bhf);
                        mma_bf16(acc[mf][nf], ah[mf], blf);
                        mma_bf16(acc[mf][nf], al[mf], bhf);
                    }
            }
            sidx = (sidx == 2) ? 0 : sidx + 1;
        }

        #pragma unroll
        for (int mf = 0; mf < 4; mf++) {
            int r0 = bm + wM*64 + mf*16 + gid;
            #pragma unroll
            for (int nf = 0; nf < 4; nf++) {
                int col = bn + wN*32 + nf*8 + tig*2;
                float bx = __ldg(bias + col), by = __ldg(bias + col + 1);
                float v0x = acc[mf][nf][0] + bx, v0y = acc[mf][nf][1] + by;
                float v1x = acc[mf][nf][2] + bx, v1y = acc[mf][nf][3] + by;
                if (relu) {
                    v0x = fmaxf(v0x, 0.f); v0y = fmaxf(v0y, 0.f);
                    v1x = fmaxf(v1x, 0.f); v1y = fmaxf(v1y, 0.f);
                }
                if (mode == 0) {
                    *(float2*)(C + (size_t)r0*N + col)       = make_float2(v0x, v0y);
                    *(float2*)(C + (size_t)(r0 + 8)*N + col) = make_float2(v1x, v1y);
                } else {
                    uint32_t h, l;
                    size_t i0 = (size_t)r0*N + col, i1 = (size_t)(r0 + 8)*N + col;
                    split2(v0x, v0y, h, l);
                    *(uint32_t*)(Chi + i0) = h; *(uint32_t*)(Clo + i0) = l;
                    split2(v1x, v1y, h, l);
                    *(uint32_t*)(Chi + i1) = h; *(uint32_t*)(Clo + i1) = l;
                }
            }
        }
    }
}

// ---------------------------------------------------------------------------
// HMMA causal attention (unchanged)
// ---------------------------------------------------------------------------
#define OQH 0
#define OQL 8192
#define OKH 16384
#define OKL 49152
#define OVH 81920
#define OVL 114688
#define OPH 147456
#define OPL 180224
#define ORED 212992
#define ATT_SMEM (ORED + 1024)

__global__ void __launch_bounds__(256, 1)
attn_hmma(const __nv_bfloat16* __restrict__ qhi,
          const __nv_bfloat16* __restrict__ qlo,
          __nv_bfloat16* __restrict__ ohi,
          __nv_bfloat16* __restrict__ olo) {
    extern __shared__ char smg[];
    const uint32_t sa = smem_u32(smg);
    const int tid = threadIdx.x;
    const int wid = tid >> 5, lane = tid & 31;
    const int wM = wid >> 1, wN = wid & 1;
    const int gid = lane >> 2, tig = lane & 3;

    const int bid = blockIdx.x;
    const int qb = 3 - (bid & 3);
    const int h  = (bid >> 2) & 7;
    const int b  = bid >> 5;
    const int krows = (qb + 1) * 64;

    auto load_tile = [&](const __nv_bfloat16* g, uint32_t sbase, int rows) {
        for (int i = tid; i < rows*8; i += 256) {
            int r = i >> 3, c = i & 7;
            cp_async16(sa + sbase + r*128 + ((c*16) ^ ((r & 7) << 4)),
                       g + (size_t)r*1536 + c*8);
        }
    };
    const size_t qbase = (size_t)(b*SS + qb*64)*1536 + h*DH;
    const size_t kbase = (size_t)(b*SS)*1536 + DD + h*DH;
    const size_t vbase = (size_t)(b*SS)*1536 + 2*DD + h*DH;
    load_tile(qhi + qbase, OQH, 64);
    load_tile(qlo + qbase, OQL, 64);
    load_tile(qhi + kbase, OKH, krows);
    load_tile(qlo + kbase, OKL, krows);
    CP_COMMIT();
    load_tile(qhi + vbase, OVH, krows);
    load_tile(qlo + vbase, OVL, krows);
    CP_COMMIT();
    CP_WAIT1();
    __syncthreads();

    const int laneA_row = lane & 15;
    const int laneA_b   = (lane >> 4) << 4;
    const int laneB_row = ((lane >> 4) << 3) + (lane & 7);
    const int laneB_b   = ((lane >> 3) & 1) << 4;

    float s[16][4];
    #pragma unroll
    for (int nt = 0; nt < 16; nt++)
        #pragma unroll
        for (int e = 0; e < 4; e++) s[nt][e] = 0.f;

    #pragma unroll
    for (int ks = 0; ks < 4; ks++) {
        uint32_t ah[4], al[4];
        {
            int r = wM*16 + laneA_row;
            uint32_t off = r*128 + (((uint32_t)(ks*32 + laneA_b)) ^ ((r & 7) << 4));
            ldm_x4(ah, sa + OQH + off);
            ldm_x4(al, sa + OQL + off);
        }
        #pragma unroll
        for (int ng = 0; ng < 8; ng++) {
            uint32_t bh4[4], bl4[4];
            int r = wN*128 + ng*16 + laneB_row;
            uint32_t off = r*128 + (((uint32_t)(ks*32 + laneB_b)) ^ ((r & 7) << 4));
            ldm_x4(bh4, sa + OKH + off);
            ldm_x4(bl4, sa + OKL + off);
            #pragma unroll
            for (int j = 0; j < 2; j++) {
                float* a = s[ng*2 + j];
                mma_bf16(a, ah, &bh4[j*2]);
                mma_bf16(a, ah, &bl4[j*2]);
                mma_bf16(a, al, &bh4[j*2]);
            }
        }
    }

    const int qrow0 = qb*64 + wM*16 + gid;
    const int qrow1 = qrow0 + 8;
    float m0 = -1e30f, m1 = -1e30f;
    #pragma unroll
    for (int nt = 0; nt < 16; nt++) {
        int c0 = wN*128 + nt*8 + tig*2;
        s[nt][0] = (c0     <= qrow0) ? s[nt][0]*0.125f : -1e30f;
        s[nt][1] = (c0 + 1 <= qrow0) ? s[nt][1]*0.125f : -1e30f;
        s[nt][2] = (c0     <= qrow1) ? s[nt][2]*0.125f : -1e30f;
        s[nt][3] = (c0 + 1 <= qrow1) ? s[nt][3]*0.125f : -1e30f;
        m0 = fmaxf(m0, fmaxf(s[nt][0], s[nt][1]));
        m1 = fmaxf(m1, fmaxf(s[nt][2], s[nt][3]));
    }
    #pragma unroll
    for (int o = 1; o <= 2; o <<= 1) {
        m0 = fmaxf(m0, __shfl_xor_sync(~0u, m0, o));
        m1 = fmaxf(m1, __shfl_xor_sync(~0u, m1, o));
    }
    float* redm = (float*)(smg + ORED);
    float* reds = (float*)(smg + ORED + 512);
    int r0l = wM*16 + gid;
    if (tig == 0) { redm[wN*64 + r0l] = m0; redm[wN*64 + r0l + 8] = m1; }
    __syncthreads();
    m0 = fmaxf(redm[r0l],     redm[64 + r0l]);
    m1 = fmaxf(redm[r0l + 8], redm[64 + r0l + 8]);

    float sum0 = 0.f, sum1 = 0.f;
    #pragma unroll
    for (int nt = 0; nt < 16; nt++) {
        s[nt][0] = __expf(s[nt][0] - m0);
        s[nt][1] = __expf(s[nt][1] - m0);
        s[nt][2] = __expf(s[nt][2] - m1);
        s[nt][3] = __expf(s[nt][3] - m1);
        sum0 += s[nt][0] + s[nt][1];
        sum1 += s[nt][2] + s[nt][3];
    }
    #pragma unroll
    for (int o = 1; o <= 2; o <<= 1) {
        sum0 += __shfl_xor_sync(~0u, sum0, o);
        sum1 += __shfl_xor_sync(~0u, sum1, o);
    }
    if (tig == 0) { reds[wN*64 + r0l] = sum0; reds[wN*64 + r0l + 8] = sum1; }
    __syncthreads();
    float inv0 = 1.f / (reds[r0l]     + reds[64 + r0l]);
    float inv1 = 1.f / (reds[r0l + 8] + reds[64 + r0l + 8]);

    #pragma unroll
    for (int nt = 0; nt < 16; nt++) {
        int c0 = wN*128 + nt*8 + tig*2;
        int kb = c0 >> 6, cb = c0 & 63;
        uint32_t sw0 = (uint32_t)(cb*2) ^ ((r0l & 7) << 4);
        uint32_t sw1 = (uint32_t)(cb*2) ^ (((r0l + 8) & 7) << 4);
        uint32_t off0 = kb*8192 + r0l*128 + sw0;
        uint32_t off1 = kb*8192 + (r0l + 8)*128 + sw1;
        uint32_t h, l;
        split2(s[nt][0]*inv0, s[nt][1]*inv0, h, l);
        *(uint32_t*)(smg + OPH + off0) = h;
        *(uint32_t*)(smg + OPL + off0) = l;
        split2(s[nt][2]*inv1, s[nt][3]*inv1, h, l);
        *(uint32_t*)(smg + OPH + off1) = h;
        *(uint32_t*)(smg + OPL + off1) = l;
    }
    CP_WAIT0();
    __syncthreads();

    float o[4][4];
    #pragma unroll
    for (int nt = 0; nt < 4; nt++)
        #pragma unroll
        for (int e = 0; e < 4; e++) o[nt][e] = 0.f;

    const int vlrow = lane & 15;
    const uint32_t cbyte0 = (uint32_t)(wN*64 + ((lane >> 4) << 4));
    for (int kb = 0; kb <= qb; kb++) {
        #pragma unroll
        for (int ks = 0; ks < 4; ks++) {
            uint32_t ph4[4], pl4[4];
            {
                int r = wM*16 + laneA_row;
                uint32_t off = kb*8192 + r*128 +
                               (((uint32_t)(ks*32 + laneA_b)) ^ ((r & 7) << 4));
                ldm_x4(ph4, sa + OPH + off);
                ldm_x4(pl4, sa + OPL + off);
            }
            int vr = kb*64 + ks*16 + vlrow;
            #pragma unroll
            for (int chh = 0; chh < 2; chh++) {
                uint32_t vh4[4], vl4[4];
                uint32_t voff = vr*128 + ((cbyte0 + chh*32) ^ ((vr & 7) << 4));
                ldm_x4t(vh4, sa + OVH + voff);
                ldm_x4t(vl4, sa + OVL + voff);
                #pragma unroll
                for (int j = 0; j < 2; j++) {
                    float* a = o[chh*2 + j];
                    mma_bf16(a, ph4, &vh4[j*2]);
                    mma_bf16(a, ph4, &vl4[j*2]);
                    mma_bf16(a, pl4, &vh4[j*2]);
                }
            }
        }
    }

    const int gr0 = b*SS + qb*64 + wM*16 + gid;
    #pragma unroll
    for (int nt = 0; nt < 4; nt++) {
        int col = h*DH + wN*32 + nt*8 + tig*2;
        uint32_t h0, l0, h1, l1;
        split2(o[nt][0], o[nt][1], h0, l0);
        split2(o[nt][2], o[nt][3], h1, l1);
        size_t i0 = (size_t)gr0*DD + col, i1 = (size_t)(gr0 + 8)*DD + col;
        *(uint32_t*)(ohi + i0) = h0; *(uint32_t*)(olo + i0) = l0;
        *(uint32_t*)(ohi + i1) = h1; *(uint32_t*)(olo + i1) = l1;
    }
}

// ---------------------------------------------------------------------------
// LN body (device helper)
// ---------------------------------------------------------------------------
__device__ __forceinline__ void ln_block(float* v, const float4 gv,
                                         const float4 bv, int t,
                                         float* red, float* o) {
    float sum = v[0] + v[1] + v[2] + v[3];
    #pragma unroll
    for (int oo = 16; oo; oo >>= 1) sum += __shfl_xor_sync(~0u, sum, oo);
    if ((t & 31) == 0) red[t >> 5] = sum;
    __syncthreads();
    float mean = (red[0] + red[1] + red[2] + red[3]) * (1.f/512.f);
    float var = 0.f;
    #pragma unroll
    for (int i = 0; i < 4; i++) {
        float d = v[i] - mean;
        var = fmaf(d, d, var);
    }
    #pragma unroll
    for (int oo = 16; oo; oo >>= 1) var += __shfl_xor_sync(~0u, var, oo);
    if ((t & 31) == 0) red[4 + (t >> 5)] = var;
    __syncthreads();
    float rs = rsqrtf((red[4] + red[5] + red[6] + red[7]) * (1.f/512.f) + 1e-5f);
    o[0] = (v[0] - mean) * rs * gv.x + bv.x;
    o[1] = (v[1] - mean) * rs * gv.y + bv.y;
    o[2] = (v[2] - mean) * rs * gv.z + bv.z;
    o[3] = (v[3] - mean) * rs * gv.w + bv.w;
}

__global__ void __launch_bounds__(128)
add_ln_kernel(__nv_bfloat16* __restrict__ xhi, __nv_bfloat16* __restrict__ xlo,
              const float* __restrict__ r,
              const float* __restrict__ g, const float* __restrict__ bt) {
    int row = blockIdx.x;
    const float* rp = r + (size_t)row*DD;
    int t = threadIdx.x;
    __shared__ float red[8];

    uint2 hp = ((const uint2*)(xhi + (size_t)row*DD))[t];
    uint2 lp = ((const uint2*)(xlo + (size_t)row*DD))[t];
    float v[4];
    join2(hp.x, lp.x, v[0], v[1]);
    join2(hp.y, lp.y, v[2], v[3]);
    float4 rv = ((const float4*)rp)[t];
    v[0] += rv.x; v[1] += rv.y; v[2] += rv.z; v[3] += rv.w;

    float o[4];
    ln_block(v, ((const float4*)g)[t], ((const float4*)bt)[t], t, red, o);
    uint32_t h0, l0, h1, l1;
    split2(o[0], o[1], h0, l0);
    split2(o[2], o[3], h1, l1);
    ((uint2*)(xhi + (size_t)row*DD))[t] = make_uint2(h0, h1);
    ((uint2*)(xlo + (size_t)row*DD))[t] = make_uint2(l0, l1);
}

__global__ void __launch_bounds__(128)
add_ln2_kernel(__nv_bfloat16* __restrict__ xhi, __nv_bfloat16* __restrict__ xlo,
               const float* __restrict__ sub, const float* __restrict__ ca,
               const float* __restrict__ g1, const float* __restrict__ b1,
               const float* __restrict__ g2, const float* __restrict__ b2) {
    int row = blockIdx.x;
    const float* sp = sub + (size_t)row*DD;
    const float* cp = ca + (size_t)(row >> 8)*DD;
    int t = threadIdx.x;
    __shared__ float red[8];

    uint2 hp = ((const uint2*)(xhi + (size_t)row*DD))[t];
    uint2 lp = ((const uint2*)(xlo + (size_t)row*DD))[t];
    float v[4];
    join2(hp.x, lp.x, v[0], v[1]);
    join2(hp.y, lp.y, v[2], v[3]);
    float4 sv = ((const float4*)sp)[t];
    v[0] += sv.x; v[1] += sv.y; v[2] += sv.z; v[3] += sv.w;

    float y1[4];
    ln_block(v, ((const float4*)g1)[t], ((const float4*)b1)[t], t, red, y1);
    __syncthreads();

    float4 cv = ((const float4*)cp)[t];
    float v2[4] = {y1[0]+cv.x, y1[1]+cv.y, y1[2]+cv.z, y1[3]+cv.w};
    float o[4];
    ln_block(v2, ((const float4*)g2)[t], ((const float4*)b2)[t], t, red, o);
    uint32_t h0, l0, h1, l1;
    split2(o[0], o[1], h0, l0);
    split2(o[2], o[3], h1, l1);
    ((uint2*)(xhi + (size_t)row*DD))[t] = make_uint2(h0, h1);
    ((uint2*)(xlo + (size_t)row*DD))[t] = make_uint2(l0, l1);
}

// ---------------------------------------------------------------------------
// Launch
// ---------------------------------------------------------------------------
extern "C" void kernel_launch(void* const* d_in, const int* in_sizes, int n_in,
                              void* d_out, int out_size) {
    const float* z      = (const float*)d_in[0];
    const int*   tgt    = (const int*)  d_in[1];
    const float* emb    = (const float*)d_in[2];
    const float* pos    = (const float*)d_in[3];
    const float* proj_w = (const float*)d_in[4];
    const float* proj_b = (const float*)d_in[5];
    const float* sa_w   = (const float*)d_in[6];
    const float* sa_b   = (const float*)d_in[7];
    const float* sa_ow  = (const float*)d_in[8];
    const float* sa_ob  = (const float*)d_in[9];
    const float* ca_w   = (const float*)d_in[10];
    const float* ca_b   = (const float*)d_in[11];
    const float* ca_ow  = (const float*)d_in[12];
    const float* ca_ob  = (const float*)d_in[13];
    const float* ln1_s  = (const float*)d_in[14];
    const float* ln1_b  = (const float*)d_in[15];
    const float* ln2_s  = (const float*)d_in[16];
    const float* ln2_b  = (const float*)d_in[17];
    const float* ln3_s  = (const float*)d_in[18];
    const float* ln3_b  = (const float*)d_in[19];
    const float* ff1_w  = (const float*)d_in[20];
    const float* ff1_b  = (const float*)d_in[21];
    const float* ff2_w  = (const float*)d_in[22];
    const float* ff2_b  = (const float*)d_in[23];
    const float* fc_w   = (const float*)d_in[24];
    const float* fc_b   = (const float*)d_in[25];
    float* out = (float*)d_out;

    float *sub, *mem, *cav, *ca;
    __nv_bfloat16 *ahi, *alo, *qhi, *qlo, *fhi, *flo, *whi, *wlo;
    cudaGetSymbolAddress((void**)&sub, g_sub);
    cudaGetSymbolAddress((void**)&mem, g_mem);
    cudaGetSymbolAddress((void**)&cav, g_cav);
    cudaGetSymbolAddress((void**)&ca,  g_ca);
    cudaGetSymbolAddress((void**)&ahi, g_ahi);
    cudaGetSymbolAddress((void**)&alo, g_alo);
    cudaGetSymbolAddress((void**)&qhi, g_qhi);
    cudaGetSymbolAddress((void**)&qlo, g_qlo);
    cudaGetSymbolAddress((void**)&fhi, g_fhi);
    cudaGetSymbolAddress((void**)&flo, g_flo);
    cudaGetSymbolAddress((void**)&whi, g_whi);
    cudaGetSymbolAddress((void**)&wlo, g_wlo);

    cudaFuncSetAttribute(gemm_hmma,
                         cudaFuncAttributeMaxDynamicSharedMemorySize, HSMEM);
    cudaFuncSetAttribute(attn_hmma,
                         cudaFuncAttributeMaxDynamicSharedMemorySize, ATT_SMEM);

    // (1) merged weight conversion
    conv_all<<<CB_TOT, 256>>>(sa_w, sa_ow, ff1_w, ff2_w, fc_w, whi, wlo);

    // (2) embedding
    embed_kernel<<<M_TOK, 128>>>(tgt, emb, pos, ahi, alo);

    // (3-5) memory projection + batched cross-attn vectors
    gemm_dot<<<dim3(BB*DD/64, 1, 1), 256>>>(z, 0, proj_w, 0, proj_b, 0,
                                            mem, 0, DD, DD);
    gemm_dot<<<dim3(BB*DD/64, 1, LL), 256>>>(
        mem, 0,
        ca_w + (size_t)2*DD*DD, (size_t)3*DD*DD,
        ca_b + 2*DD, (size_t)3*DD,
        cav, (size_t)BB*DD, DD, DD);
    gemm_dot<<<dim3(BB*DD/64, 1, LL), 256>>>(
        cav, (size_t)BB*DD,
        ca_ow, (size_t)DD*DD,
        ca_ob, (size_t)DD,
        ca, (size_t)BB*DD, DD, DD);

    const int PGRID = 148;

    for (int l = 0; l < LL; l++) {
        const float* sabl  = sa_b  + (size_t)l*3*DD;
        const float* saobl = sa_ob + (size_t)l*DD;
        size_t o_qkv = O_SAW  + (size_t)l*3*DD*DD;
        size_t o_ow  = O_SAOW + (size_t)l*DD*DD;
        size_t o_ff1 = O_FF1  + (size_t)l*DFF*DD;
        size_t o_ff2 = O_FF2  + (size_t)l*DD*DFF;

        // self-attention
        gemm_hmma<<<PGRID, 256, HSMEM>>>(ahi, alo, whi + o_qkv, wlo + o_qkv,
                                         sabl, nullptr, qhi, qlo,
                                         3*DD, DD, 0, 1, 12, 12*128);
        attn_hmma<<<BB*HH*4, 256, ATT_SMEM>>>(qhi, qlo, fhi, flo);
        gemm_hmma<<<PGRID, 256, HSMEM>>>(fhi, flo, whi + o_ow, wlo + o_ow,
                                         saobl, sub, nullptr, nullptr,
                                         DD, DD, 0, 0, 4, 4*128);
        add_ln2_kernel<<<M_TOK, 128>>>(ahi, alo, sub, ca + (size_t)l*BB*DD,
                                       ln1_s + l*DD, ln1_b + l*DD,
                                       ln2_s + l*DD, ln2_b + l*DD);

        // feed-forward
        gemm_hmma<<<PGRID, 256, HSMEM>>>(ahi, alo, whi + o_ff1, wlo + o_ff1,
                                         ff1_b + l*DFF, nullptr, fhi, flo,
                                         DFF, DD, 1, 1, 16, 16*128);
        gemm_hmma<<<PGRID, 256, HSMEM>>>(fhi, flo, whi + o_ff2, wlo + o_ff2,
                                         ff2_b + l*DD, sub, nullptr, nullptr,
                                         DD, DFF, 0, 0, 4, 4*128);
        add_ln_kernel<<<M_TOK, 128>>>(ahi, alo, sub,
                                      ln3_s + l*DD, ln3_b + l*DD);
    }

    // final classifier
    gemm_hmma<<<128, 256, HSMEM>>>(ahi, alo, whi + O_FC, wlo + O_FC,
                                   fc_b, out, nullptr, nullptr,
                                   VV, DD, 0, 0, 1, 128);
}

// round 16
// speedup vs baseline: 1.6668x; 1.0055x over previous
#include <cuda_runtime.h>
#include <cuda_bf16.h>
#include <math.h>
#include <stdint.h>

#define BB 64
#define SS 256
#define DD 512
#define HH 8
#define DH 64
#define DFF 2048
#define VV 128
#define LL 6
#define M_TOK (BB*SS)

// ---------------------------------------------------------------------------
// Scratch
// ---------------------------------------------------------------------------
__device__ float g_sub[M_TOK*DD];
__device__ float g_mem[BB*DD];
__device__ float g_cav[LL*BB*DD];
__device__ float g_ca [LL*BB*DD];

__device__ __nv_bfloat16 g_ahi[(size_t)M_TOK*DD];
__device__ __nv_bfloat16 g_alo[(size_t)M_TOK*DD];
__device__ __nv_bfloat16 g_qhi[(size_t)M_TOK*3*DD];
__device__ __nv_bfloat16 g_qlo[(size_t)M_TOK*3*DD];
__device__ __nv_bfloat16 g_fhi[(size_t)M_TOK*DFF];
__device__ __nv_bfloat16 g_flo[(size_t)M_TOK*DFF];

#define O_SAW  0u
#define O_SAOW 4718592u
#define O_FF1  6291456u
#define O_FF2  12582912u
#define O_FC   18874368u
#define WPOOL_E 18940032u
__device__ __nv_bfloat16 g_whi[WPOOL_E];
__device__ __nv_bfloat16 g_wlo[WPOOL_E];

// ---------------------------------------------------------------------------
// Helpers
// ---------------------------------------------------------------------------
__device__ __forceinline__ uint32_t smem_u32(const void* p) {
    uint32_t a;
    asm("{ .reg .u64 t; cvta.to.shared.u64 t, %1; cvt.u32.u64 %0, t; }"
        : "=r"(a) : "l"(p));
    return a;
}
__device__ __forceinline__ void cp_async16(uint32_t dst, const void* src) {
    asm volatile("cp.async.cg.shared.global [%0], [%1], 16;"
                 :: "r"(dst), "l"(src));
}
#define CP_COMMIT() asm volatile("cp.async.commit_group;" ::: "memory")
#define CP_WAIT1()  asm volatile("cp.async.wait_group 1;" ::: "memory")
#define CP_WAIT0()  asm volatile("cp.async.wait_group 0;" ::: "memory")

__device__ __forceinline__ void ldm_x4(uint32_t* r, uint32_t addr) {
    asm volatile("ldmatrix.sync.aligned.m8n8.x4.shared.b16 {%0,%1,%2,%3}, [%4];"
                 : "=r"(r[0]), "=r"(r[1]), "=r"(r[2]), "=r"(r[3]) : "r"(addr));
}
__device__ __forceinline__ void ldm_x4t(uint32_t* r, uint32_t addr) {
    asm volatile("ldmatrix.sync.aligned.m8n8.x4.trans.shared.b16 {%0,%1,%2,%3}, [%4];"
                 : "=r"(r[0]), "=r"(r[1]), "=r"(r[2]), "=r"(r[3]) : "r"(addr));
}
__device__ __forceinline__ void mma_bf16(float* c, const uint32_t* a,
                                         const uint32_t* b) {
    asm volatile(
        "mma.sync.aligned.m16n8k16.row.col.f32.bf16.bf16.f32 "
        "{%0,%1,%2,%3}, {%4,%5,%6,%7}, {%8,%9}, {%0,%1,%2,%3};"
        : "+f"(c[0]), "+f"(c[1]), "+f"(c[2]), "+f"(c[3])
        : "r"(a[0]), "r"(a[1]), "r"(a[2]), "r"(a[3]), "r"(b[0]), "r"(b[1]));
}
__device__ __forceinline__ uint32_t pack2bf(float a, float b) {
    __nv_bfloat162 t = __floats2bfloat162_rn(a, b);
    return *(uint32_t*)&t;
}
__device__ __forceinline__ void split2(float a, float b, uint32_t& hi, uint32_t& lo) {
    __nv_bfloat16 ha = __float2bfloat16_rn(a);
    __nv_bfloat16 hb = __float2bfloat16_rn(b);
    hi = pack2bf(__bfloat162float(ha), __bfloat162float(hb));
    lo = pack2bf(a - __bfloat162float(ha), b - __bfloat162float(hb));
}
__device__ __forceinline__ void join2(uint32_t hi, uint32_t lo, float& a, float& b) {
    __nv_bfloat162 h = *(__nv_bfloat162*)&hi;
    __nv_bfloat162 l = *(__nv_bfloat162*)&lo;
    a = __bfloat162float(h.x) + __bfloat162float(l.x);
    b = __bfloat162float(h.y) + __bfloat162float(l.y);
}

// ---------------------------------------------------------------------------
// Embedding
// ---------------------------------------------------------------------------
__global__ void embed_kernel(const int* __restrict__ tgt,
                             const float* __restrict__ emb,
                             const float* __restrict__ pos,
                             __nv_bfloat16* __restrict__ xhi,
                             __nv_bfloat16* __restrict__ xlo) {
    int row = blockIdx.x;
    int d4  = threadIdx.x;
    int tok = tgt[row];
    int s   = row & (SS - 1);
    float4 e = ((const float4*)(emb + (size_t)tok*DD))[d4];
    float4 p = ((const float4*)(pos + (size_t)s*DD))[d4];
    float4 v = make_float4(e.x+p.x, e.y+p.y, e.z+p.z, e.w+p.w);
    uint32_t h0, l0, h1, l1;
    split2(v.x, v.y, h0, l0);
    split2(v.z, v.w, h1, l1);
    ((uint2*)(xhi + (size_t)row*DD))[d4] = make_uint2(h0, h1);
    ((uint2*)(xlo + (size_t)row*DD))[d4] = make_uint2(l0, l1);
}

// ---------------------------------------------------------------------------
// Merged weight conversion
// ---------------------------------------------------------------------------
#define CB_SAW  4608
#define CB_SAOW 1536
#define CB_FF1  6144
#define CB_FF2  6144
#define CB_FC   64
#define CB_TOT  (CB_SAW + CB_SAOW + CB_FF1 + CB_FF2 + CB_FC)

__global__ void __launch_bounds__(256)
conv_all(const float* __restrict__ sa_w, const float* __restrict__ sa_ow,
         const float* __restrict__ ff1_w, const float* __restrict__ ff2_w,
         const float* __restrict__ fc_w,
         __nv_bfloat16* __restrict__ whi, __nv_bfloat16* __restrict__ wlo) {
    int bid = blockIdx.x;
    const float* src;
    size_t dst;
    if (bid < CB_SAW)                       { src = sa_w;  dst = O_SAW;  }
    else if ((bid -= CB_SAW)  < CB_SAOW)    { src = sa_ow; dst = O_SAOW; }
    else if ((bid -= CB_SAOW) < CB_FF1)     { src = ff1_w; dst = O_FF1;  }
    else if ((bid -= CB_FF1)  < CB_FF2)     { src = ff2_w; dst = O_FF2;  }
    else    { bid -= CB_FF2;                  src = fc_w;  dst = O_FC;   }

    size_t i = (size_t)bid * 256 + threadIdx.x;
    float4 v = ((const float4*)src)[i];
    uint32_t h0, l0, h1, l1;
    split2(v.x, v.y, h0, l0);
    split2(v.z, v.w, h1, l1);
    ((uint2*)(whi + dst))[i] = make_uint2(h0, h1);
    ((uint2*)(wlo + dst))[i] = make_uint2(l0, l1);
}

// ---------------------------------------------------------------------------
// Warp-per-8-outputs dot GEMM (tiny M=64 shapes, z-batched)
// ---------------------------------------------------------------------------
__global__ void __launch_bounds__(256)
gemm_dot(const float* __restrict__ A, size_t astr,
         const float* __restrict__ W, size_t wstr,
         const float* __restrict__ bias, size_t bistr,
         float* __restrict__ C, size_t cstr, int N, int K) {
    const int zz = blockIdx.z;
    A += zz*astr; W += zz*wstr; bias += zz*bistr; C += zz*cstr;

    const int ng = N >> 3;
    int gw = blockIdx.x*8 + (threadIdx.x >> 5);
    int lane = threadIdx.x & 31;
    int b = gw / ng, n0 = (gw - b*ng) * 8;
    const float* ap = A + (size_t)b*K;
    const float* wp = W + (size_t)n0*K;

    float acc[8];
    #pragma unroll
    for (int j = 0; j < 8; j++) acc[j] = 0.f;

    for (int k = lane*4; k < K; k += 128) {
        float4 av = *(const float4*)(ap + k);
        #pragma unroll
        for (int j = 0; j < 8; j++) {
            float4 wv = *(const float4*)(wp + (size_t)j*K + k);
            acc[j] = fmaf(av.x, wv.x, acc[j]);
            acc[j] = fmaf(av.y, wv.y, acc[j]);
            acc[j] = fmaf(av.z, wv.z, acc[j]);
            acc[j] = fmaf(av.w, wv.w, acc[j]);
        }
    }
    #pragma unroll
    for (int j = 0; j < 8; j++) {
        #pragma unroll
        for (int o = 16; o; o >>= 1)
            acc[j] += __shfl_xor_sync(~0u, acc[j], o);
    }
    if (lane < 8)
        C[(size_t)b*N + n0 + lane] = acc[lane] + bias[n0 + lane];
}

// ---------------------------------------------------------------------------
// PERSISTENT HMMA bf16x3 GEMM (unchanged)
// ---------------------------------------------------------------------------
#define HSTAGE 65536
#define HSMEM  (3*HSTAGE)

__global__ void __launch_bounds__(256, 1)
gemm_hmma(const __nv_bfloat16* __restrict__ Ahi,
          const __nv_bfloat16* __restrict__ Alo,
          const __nv_bfloat16* __restrict__ Bhi,
          const __nv_bfloat16* __restrict__ Blo,
          const float* __restrict__ bias, float* __restrict__ C,
          __nv_bfloat16* __restrict__ Chi, __nv_bfloat16* __restrict__ Clo,
          int N, int K, int relu, int mode, int ntx, int ntiles) {
    extern __shared__ char smg[];
    const uint32_t sa = smem_u32(smg);
    const int tid = threadIdx.x;
    const int wid = tid >> 5, lane = tid & 31;
    const int wM = wid >> 2, wN = wid & 3;
    const int kc = K >> 6;

    const int laneA_row = lane & 15;
    const int laneA_b   = (lane >> 4) << 4;
    const int laneB_row = ((lane >> 4) << 3) + (lane & 7);
    const int laneB_b   = ((lane >> 3) & 1) << 4;
    const int gid = lane >> 2, tig = lane & 3;

    int dec_pool[8], dec_r[8];
    uint32_t offA[8], offB[8];
    #pragma unroll
    for (int it = 0; it < 8; it++) {
        int i = tid + it*256;
        int pool = i >> 10, r = (i >> 3) & 127, c = i & 7;
        dec_pool[it] = pool; dec_r[it] = r;
        uint32_t sw = (uint32_t)((c*16) ^ ((r & 7) << 4));
        offA[it] = pool*16384 + r*128 + sw;
        offB[it] = 32768 + pool*16384 + r*128 + sw;
    }

    for (int tile = blockIdx.x; tile < ntiles; tile += gridDim.x) {
        const int bm = (tile / ntx) * 128;
        const int bn = (tile % ntx) * 128;

        const char* srcA[8];
        const char* srcB[8];
        #pragma unroll
        for (int it = 0; it < 8; it++) {
            int i = tid + it*256;
            int c = i & 7;
            srcA[it] = (const char*)((dec_pool[it] ? Alo : Ahi) +
                                     (size_t)(bm + dec_r[it])*K + c*8);
            srcB[it] = (const char*)((dec_pool[it] ? Blo : Bhi) +
                                     (size_t)(bn + dec_r[it])*K + c*8);
        }

        __syncthreads();

        float acc[4][4][4];
        #pragma unroll
        for (int i = 0; i < 4; i++)
            #pragma unroll
            for (int j = 0; j < 4; j++)
                #pragma unroll
                for (int e = 0; e < 4; e++) acc[i][j][e] = 0.f;

        auto load_stage = [&](int s, int kk) {
            uint32_t stg = sa + s*HSTAGE;
            int kb = kk << 7;
            #pragma unroll
            for (int it = 0; it < 8; it++)
                cp_async16(stg + offA[it], srcA[it] + kb);
            #pragma unroll
            for (int it = 0; it < 8; it++)
                cp_async16(stg + offB[it], srcB[it] + kb);
        };

        load_stage(0, 0); CP_COMMIT();
        load_stage(1, 1); CP_COMMIT();

        int sidx = 0;
        for (int ch = 0; ch < kc; ch++) {
            CP_WAIT1();
            __syncthreads();

            if (ch + 2 < kc) {
                int st2 = sidx + 2; if (st2 >= 3) st2 -= 3;
                load_stage(st2, ch + 2);
            }
            CP_COMMIT();

            uint32_t stg = sa + sidx*HSTAGE;
            #pragma unroll
            for (int ks = 0; ks < 4; ks++) {
                uint32_t ah[4][4], al[4][4], bh[2][4], bl[2][4];
                #pragma unroll
                for (int mf = 0; mf < 4; mf++) {
                    int r = wM*64 + mf*16 + laneA_row;
                    uint32_t off = r*128 + (((uint32_t)(ks*32 + laneA_b)) ^ ((r & 7) << 4));
                    ldm_x4(ah[mf], stg + off);
                    ldm_x4(al[mf], stg + 16384 + off);
                }
                #pragma unroll
                for (int nf2 = 0; nf2 < 2; nf2++) {
                    int r = wN*32 + nf2*16 + laneB_row;
                    uint32_t off = r*128 + (((uint32_t)(ks*32 + laneB_b)) ^ ((r & 7) << 4));
                    ldm_x4(bh[nf2], stg + 32768 + off);
                    ldm_x4(bl[nf2], stg + 49152 + off);
                }
                #pragma unroll
                for (int mf = 0; mf < 4; mf++)
                    #pragma unroll
                    for (int nf = 0; nf < 4; nf++) {
                        const uint32_t* bhf = &bh[nf >> 1][(nf & 1)*2];
                        const uint32_t* blf = &bl[nf >> 1][(nf & 1)*2];
                        mma_bf16(acc[mf][nf], ah[mf], bhf);
                        mma_bf16(acc[mf][nf], ah[mf], blf);
                        mma_bf16(acc[mf][nf], al[mf], bhf);
                    }
            }
            sidx = (sidx == 2) ? 0 : sidx + 1;
        }

        #pragma unroll
        for (int mf = 0; mf < 4; mf++) {
            int r0 = bm + wM*64 + mf*16 + gid;
            #pragma unroll
            for (int nf = 0; nf < 4; nf++) {
                int col = bn + wN*32 + nf*8 + tig*2;
                float bx = __ldg(bias + col), by = __ldg(bias + col + 1);
                float v0x = acc[mf][nf][0] + bx, v0y = acc[mf][nf][1] + by;
                float v1x = acc[mf][nf][2] + bx, v1y = acc[mf][nf][3] + by;
                if (relu) {
                    v0x = fmaxf(v0x, 0.f); v0y = fmaxf(v0y, 0.f);
                    v1x = fmaxf(v1x, 0.f); v1y = fmaxf(v1y, 0.f);
                }
                if (mode == 0) {
                    *(float2*)(C + (size_t)r0*N + col)       = make_float2(v0x, v0y);
                    *(float2*)(C + (size_t)(r0 + 8)*N + col) = make_float2(v1x, v1y);
                } else {
                    uint32_t h, l;
                    size_t i0 = (size_t)r0*N + col, i1 = (size_t)(r0 + 8)*N + col;
                    split2(v0x, v0y, h, l);
                    *(uint32_t*)(Chi + i0) = h; *(uint32_t*)(Clo + i0) = l;
                    split2(v1x, v1y, h, l);
                    *(uint32_t*)(Chi + i1) = h; *(uint32_t*)(Clo + i1) = l;
                }
            }
        }
    }
}

// ---------------------------------------------------------------------------
// HMMA causal attention — PAIRED q-blocks per CTA.
// grid = BB*HH*2. pair 0 -> qb {3,0}, pair 1 -> qb {2,1}; K/V loaded once.
// smem: Q[2] 32K | Khi 32K | Klo 32K | Vhi 32K | Vlo 32K | Phi 32K | Plo 32K
// ---------------------------------------------------------------------------
#define OQH0 0
#define OQL0 16384
#define OKH  32768
#define OKL  65536
#define OVH  98304
#define OVL  131072
#define OPH  163840
#define OPL  196608
#define ORED 229376
#define ATT_SMEM (ORED + 1024)

__global__ void __launch_bounds__(256, 1)
attn_hmma(const __nv_bfloat16* __restrict__ qhi,
          const __nv_bfloat16* __restrict__ qlo,
          __nv_bfloat16* __restrict__ ohi,
          __nv_bfloat16* __restrict__ olo) {
    extern __shared__ char smg[];
    const uint32_t sa = smem_u32(smg);
    const int tid = threadIdx.x;
    const int wid = tid >> 5, lane = tid & 31;
    const int wM = wid >> 1, wN = wid & 1;
    const int gid = lane >> 2, tig = lane & 3;

    const int bid  = blockIdx.x;
    const int pair = bid & 1;
    const int h    = (bid >> 1) & 7;
    const int b    = bid >> 4;
    const int qbA  = pair ? 2 : 3;       // heavy block first
    const int qbB  = pair ? 1 : 0;
    const int krows = (qbA + 1) * 64;    // covers both blocks of the pair

    auto load_tile = [&](const __nv_bfloat16* g, uint32_t sbase, int rows) {
        for (int i = tid; i < rows*8; i += 256) {
            int r = i >> 3, c = i & 7;
            cp_async16(sa + sbase + r*128 + ((c*16) ^ ((r & 7) << 4)),
                       g + (size_t)r*1536 + c*8);
        }
    };
    const size_t kbase = (size_t)(b*SS)*1536 + DD + h*DH;
    const size_t vbase = (size_t)(b*SS)*1536 + 2*DD + h*DH;
    // Q for both blocks
    {
        const size_t qA = (size_t)(b*SS + qbA*64)*1536 + h*DH;
        const size_t qB = (size_t)(b*SS + qbB*64)*1536 + h*DH;
        load_tile(qhi + qA, OQH0,        64);
        load_tile(qlo + qA, OQL0,        64);
        load_tile(qhi + qB, OQH0 + 8192, 64);
        load_tile(qlo + qB, OQL0 + 8192, 64);
    }
    load_tile(qhi + kbase, OKH, krows);
    load_tile(qlo + kbase, OKL, krows);
    CP_COMMIT();
    load_tile(qhi + vbase, OVH, krows);
    load_tile(qlo + vbase, OVL, krows);
    CP_COMMIT();
    CP_WAIT1();                 // Q,K ready
    __syncthreads();

    const int laneA_row = lane & 15;
    const int laneA_b   = (lane >> 4) << 4;
    const int laneB_row = ((lane >> 4) << 3) + (lane & 7);
    const int laneB_b   = ((lane >> 3) & 1) << 4;

    float* redm = (float*)(smg + ORED);
    float* reds = (float*)(smg + ORED + 512);
    const int r0l = wM*16 + gid;

    for (int ii = 0; ii < 2; ii++) {
        const int qb = ii ? qbB : qbA;
        const uint32_t qoff = (uint32_t)(ii * 8192);
        if (ii) __syncthreads();          // P/red reuse barrier

        // ---- QK^T ----
        float s[16][4];
        #pragma unroll
        for (int nt = 0; nt < 16; nt++)
            #pragma unroll
            for (int e = 0; e < 4; e++) s[nt][e] = 0.f;

        #pragma unroll
        for (int ks = 0; ks < 4; ks++) {
            uint32_t ah[4], al[4];
            {
                int r = wM*16 + laneA_row;
                uint32_t off = r*128 + (((uint32_t)(ks*32 + laneA_b)) ^ ((r & 7) << 4));
                ldm_x4(ah, sa + OQH0 + qoff + off);
                ldm_x4(al, sa + OQL0 + qoff + off);
            }
            #pragma unroll
            for (int ng = 0; ng < 8; ng++) {
                uint32_t bh4[4], bl4[4];
                int r = wN*128 + ng*16 + laneB_row;
                uint32_t off = r*128 + (((uint32_t)(ks*32 + laneB_b)) ^ ((r & 7) << 4));
                ldm_x4(bh4, sa + OKH + off);
                ldm_x4(bl4, sa + OKL + off);
                #pragma unroll
                for (int j = 0; j < 2; j++) {
                    float* a = s[ng*2 + j];
                    mma_bf16(a, ah, &bh4[j*2]);
                    mma_bf16(a, ah, &bl4[j*2]);
                    mma_bf16(a, al, &bh4[j*2]);
                }
            }
        }

        // ---- mask + softmax ----
        const int qrow0 = qb*64 + wM*16 + gid;
        const int qrow1 = qrow0 + 8;
        float m0 = -1e30f, m1 = -1e30f;
        #pragma unroll
        for (int nt = 0; nt < 16; nt++) {
            int c0 = wN*128 + nt*8 + tig*2;
            s[nt][0] = (c0     <= qrow0) ? s[nt][0]*0.125f : -1e30f;
            s[nt][1] = (c0 + 1 <= qrow0) ? s[nt][1]*0.125f : -1e30f;
            s[nt][2] = (c0     <= qrow1) ? s[nt][2]*0.125f : -1e30f;
            s[nt][3] = (c0 + 1 <= qrow1) ? s[nt][3]*0.125f : -1e30f;
            m0 = fmaxf(m0, fmaxf(s[nt][0], s[nt][1]));
            m1 = fmaxf(m1, fmaxf(s[nt][2], s[nt][3]));
        }
        #pragma unroll
        for (int o = 1; o <= 2; o <<= 1) {
            m0 = fmaxf(m0, __shfl_xor_sync(~0u, m0, o));
            m1 = fmaxf(m1, __shfl_xor_sync(~0u, m1, o));
        }
        if (tig == 0) { redm[wN*64 + r0l] = m0; redm[wN*64 + r0l + 8] = m1; }
        __syncthreads();
        m0 = fmaxf(redm[r0l],     redm[64 + r0l]);
        m1 = fmaxf(redm[r0l + 8], redm[64 + r0l + 8]);

        float sum0 = 0.f, sum1 = 0.f;
        #pragma unroll
        for (int nt = 0; nt < 16; nt++) {
            s[nt][0] = __expf(s[nt][0] - m0);
            s[nt][1] = __expf(s[nt][1] - m0);
            s[nt][2] = __expf(s[nt][2] - m1);
            s[nt][3] = __expf(s[nt][3] - m1);
            sum0 += s[nt][0] + s[nt][1];
            sum1 += s[nt][2] + s[nt][3];
        }
        #pragma unroll
        for (int o = 1; o <= 2; o <<= 1) {
            sum0 += __shfl_xor_sync(~0u, sum0, o);
            sum1 += __shfl_xor_sync(~0u, sum1, o);
        }
        if (tig == 0) { reds[wN*64 + r0l] = sum0; reds[wN*64 + r0l + 8] = sum1; }
        __syncthreads();
        float inv0 = 1.f / (reds[r0l]     + reds[64 + r0l]);
        float inv1 = 1.f / (reds[r0l + 8] + reds[64 + r0l + 8]);

        // ---- store P hi/lo ----
        #pragma unroll
        for (int nt = 0; nt < 16; nt++) {
            int c0 = wN*128 + nt*8 + tig*2;
            int kb = c0 >> 6, cb = c0 & 63;
            uint32_t sw0 = (uint32_t)(cb*2) ^ ((r0l & 7) << 4);
            uint32_t sw1 = (uint32_t)(cb*2) ^ (((r0l + 8) & 7) << 4);
            uint32_t off0 = kb*8192 + r0l*128 + sw0;
            uint32_t off1 = kb*8192 + (r0l + 8)*128 + sw1;
            uint32_t hh, ll;
            split2(s[nt][0]*inv0, s[nt][1]*inv0, hh, ll);
            *(uint32_t*)(smg + OPH + off0) = hh;
            *(uint32_t*)(smg + OPL + off0) = ll;
            split2(s[nt][2]*inv1, s[nt][3]*inv1, hh, ll);
            *(uint32_t*)(smg + OPH + off1) = hh;
            *(uint32_t*)(smg + OPL + off1) = ll;
        }
        if (ii == 0) { CP_WAIT0(); }      // V resident before first PV
        __syncthreads();

        // ---- PV ----
        float o[4][4];
        #pragma unroll
        for (int nt = 0; nt < 4; nt++)
            #pragma unroll
            for (int e = 0; e < 4; e++) o[nt][e] = 0.f;

        const int vlrow = lane & 15;
        const uint32_t cbyte0 = (uint32_t)(wN*64 + ((lane >> 4) << 4));
        for (int kb = 0; kb <= qb; kb++) {
            #pragma unroll
            for (int ks = 0; ks < 4; ks++) {
                uint32_t ph4[4], pl4[4];
                {
                    int r = wM*16 + laneA_row;
                    uint32_t off = kb*8192 + r*128 +
                                   (((uint32_t)(ks*32 + laneA_b)) ^ ((r & 7) << 4));
                    ldm_x4(ph4, sa + OPH + off);
                    ldm_x4(pl4, sa + OPL + off);
                }
                int vr = kb*64 + ks*16 + vlrow;
                #pragma unroll
                for (int chh = 0; chh < 2; chh++) {
                    uint32_t vh4[4], vl4[4];
                    uint32_t voff = vr*128 + ((cbyte0 + chh*32) ^ ((vr & 7) << 4));
                    ldm_x4t(vh4, sa + OVH + voff);
                    ldm_x4t(vl4, sa + OVL + voff);
                    #pragma unroll
                    for (int j = 0; j < 2; j++) {
                        float* a = o[chh*2 + j];
                        mma_bf16(a, ph4, &vh4[j*2]);
                        mma_bf16(a, ph4, &vl4[j*2]);
                        mma_bf16(a, pl4, &vh4[j*2]);
                    }
                }
            }
        }

        // ---- write output hi/lo ----
        const int gr0 = b*SS + qb*64 + wM*16 + gid;
        #pragma unroll
        for (int nt = 0; nt < 4; nt++) {
            int col = h*DH + wN*32 + nt*8 + tig*2;
            uint32_t h0, l0, h1, l1;
            split2(o[nt][0], o[nt][1], h0, l0);
            split2(o[nt][2], o[nt][3], h1, l1);
            size_t i0 = (size_t)gr0*DD + col, i1 = (size_t)(gr0 + 8)*DD + col;
            *(uint32_t*)(ohi + i0) = h0; *(uint32_t*)(olo + i0) = l0;
            *(uint32_t*)(ohi + i1) = h1; *(uint32_t*)(olo + i1) = l1;
        }
    }
}

// ---------------------------------------------------------------------------
// LN body (device helper)
// ---------------------------------------------------------------------------
__device__ __forceinline__ void ln_block(float* v, const float4 gv,
                                         const float4 bv, int t,
                                         float* red, float* o) {
    float sum = v[0] + v[1] + v[2] + v[3];
    #pragma unroll
    for (int oo = 16; oo; oo >>= 1) sum += __shfl_xor_sync(~0u, sum, oo);
    if ((t & 31) == 0) red[t >> 5] = sum;
    __syncthreads();
    float mean = (red[0] + red[1] + red[2] + red[3]) * (1.f/512.f);
    float var = 0.f;
    #pragma unroll
    for (int i = 0; i < 4; i++) {
        float d = v[i] - mean;
        var = fmaf(d, d, var);
    }
    #pragma unroll
    for (int oo = 16; oo; oo >>= 1) var += __shfl_xor_sync(~0u, var, oo);
    if ((t & 31) == 0) red[4 + (t >> 5)] = var;
    __syncthreads();
    float rs = rsqrtf((red[4] + red[5] + red[6] + red[7]) * (1.f/512.f) + 1e-5f);
    o[0] = (v[0] - mean) * rs * gv.x + bv.x;
    o[1] = (v[1] - mean) * rs * gv.y + bv.y;
    o[2] = (v[2] - mean) * rs * gv.z + bv.z;
    o[3] = (v[3] - mean) * rs * gv.w + bv.w;
}

__global__ void __launch_bounds__(128)
add_ln_kernel(__nv_bfloat16* __restrict__ xhi, __nv_bfloat16* __restrict__ xlo,
              const float* __restrict__ r,
              const float* __restrict__ g, const float* __restrict__ bt) {
    int row = blockIdx.x;
    const float* rp = r + (size_t)row*DD;
    int t = threadIdx.x;
    __shared__ float red[8];

    uint2 hp = ((const uint2*)(xhi + (size_t)row*DD))[t];
    uint2 lp = ((const uint2*)(xlo + (size_t)row*DD))[t];
    float v[4];
    join2(hp.x, lp.x, v[0], v[1]);
    join2(hp.y, lp.y, v[2], v[3]);
    float4 rv = ((const float4*)rp)[t];
    v[0] += rv.x; v[1] += rv.y; v[2] += rv.z; v[3] += rv.w;

    float o[4];
    ln_block(v, ((const float4*)g)[t], ((const float4*)bt)[t], t, red, o);
    uint32_t h0, l0, h1, l1;
    split2(o[0], o[1], h0, l0);
    split2(o[2], o[3], h1, l1);
    ((uint2*)(xhi + (size_t)row*DD))[t] = make_uint2(h0, h1);
    ((uint2*)(xlo + (size_t)row*DD))[t] = make_uint2(l0, l1);
}

__global__ void __launch_bounds__(128)
add_ln2_kernel(__nv_bfloat16* __restrict__ xhi, __nv_bfloat16* __restrict__ xlo,
               const float* __restrict__ sub, const float* __restrict__ ca,
               const float* __restrict__ g1, const float* __restrict__ b1,
               const float* __restrict__ g2, const float* __restrict__ b2) {
    int row = blockIdx.x;
    const float* sp = sub + (size_t)row*DD;
    const float* cp = ca + (size_t)(row >> 8)*DD;
    int t = threadIdx.x;
    __shared__ float red[8];

    uint2 hp = ((const uint2*)(xhi + (size_t)row*DD))[t];
    uint2 lp = ((const uint2*)(xlo + (size_t)row*DD))[t];
    float v[4];
    join2(hp.x, lp.x, v[0], v[1]);
    join2(hp.y, lp.y, v[2], v[3]);
    float4 sv = ((const float4*)sp)[t];
    v[0] += sv.x; v[1] += sv.y; v[2] += sv.z; v[3] += sv.w;

    float y1[4];
    ln_block(v, ((const float4*)g1)[t], ((const float4*)b1)[t], t, red, y1);
    __syncthreads();

    float4 cv = ((const float4*)cp)[t];
    float v2[4] = {y1[0]+cv.x, y1[1]+cv.y, y1[2]+cv.z, y1[3]+cv.w};
    float o[4];
    ln_block(v2, ((const float4*)g2)[t], ((const float4*)b2)[t], t, red, o);
    uint32_t h0, l0, h1, l1;
    split2(o[0], o[1], h0, l0);
    split2(o[2], o[3], h1, l1);
    ((uint2*)(xhi + (size_t)row*DD))[t] = make_uint2(h0, h1);
    ((uint2*)(xlo + (size_t)row*DD))[t] = make_uint2(l0, l1);
}

// ---------------------------------------------------------------------------
// Launch
// ---------------------------------------------------------------------------
extern "C" void kernel_launch(void* const* d_in, const int* in_sizes, int n_in,
                              void* d_out, int out_size) {
    const float* z      = (const float*)d_in[0];
    const int*   tgt    = (const int*)  d_in[1];
    const float* emb    = (const float*)d_in[2];
    const float* pos    = (const float*)d_in[3];
    const float* proj_w = (const float*)d_in[4];
    const float* proj_b = (const float*)d_in[5];
    const float* sa_w   = (const float*)d_in[6];
    const float* sa_b   = (const float*)d_in[7];
    const float* sa_ow  = (const float*)d_in[8];
    const float* sa_ob  = (const float*)d_in[9];
    const float* ca_w   = (const float*)d_in[10];
    const float* ca_b   = (const float*)d_in[11];
    const float* ca_ow  = (const float*)d_in[12];
    const float* ca_ob  = (const float*)d_in[13];
    const float* ln1_s  = (const float*)d_in[14];
    const float* ln1_b  = (const float*)d_in[15];
    const float* ln2_s  = (const float*)d_in[16];
    const float* ln2_b  = (const float*)d_in[17];
    const float* ln3_s  = (const float*)d_in[18];
    const float* ln3_b  = (const float*)d_in[19];
    const float* ff1_w  = (const float*)d_in[20];
    const float* ff1_b  = (const float*)d_in[21];
    const float* ff2_w  = (const float*)d_in[22];
    const float* ff2_b  = (const float*)d_in[23];
    const float* fc_w   = (const float*)d_in[24];
    const float* fc_b   = (const float*)d_in[25];
    float* out = (float*)d_out;

    float *sub, *mem, *cav, *ca;
    __nv_bfloat16 *ahi, *alo, *qhi, *qlo, *fhi, *flo, *whi, *wlo;
    cudaGetSymbolAddress((void**)&sub, g_sub);
    cudaGetSymbolAddress((void**)&mem, g_mem);
    cudaGetSymbolAddress((void**)&cav, g_cav);
    cudaGetSymbolAddress((void**)&ca,  g_ca);
    cudaGetSymbolAddress((void**)&ahi, g_ahi);
    cudaGetSymbolAddress((void**)&alo, g_alo);
    cudaGetSymbolAddress((void**)&qhi, g_qhi);
    cudaGetSymbolAddress((void**)&qlo, g_qlo);
    cudaGetSymbolAddress((void**)&fhi, g_fhi);
    cudaGetSymbolAddress((void**)&flo, g_flo);
    cudaGetSymbolAddress((void**)&whi, g_whi);
    cudaGetSymbolAddress((void**)&wlo, g_wlo);

    cudaFuncSetAttribute(gemm_hmma,
                         cudaFuncAttributeMaxDynamicSharedMemorySize, HSMEM);
    cudaFuncSetAttribute(attn_hmma,
                         cudaFuncAttributeMaxDynamicSharedMemorySize, ATT_SMEM);

    // (1) merged weight conversion
    conv_all<<<CB_TOT, 256>>>(sa_w, sa_ow, ff1_w, ff2_w, fc_w, whi, wlo);

    // (2) embedding
    embed_kernel<<<M_TOK, 128>>>(tgt, emb, pos, ahi, alo);

    // (3-5) memory projection + batched cross-attn vectors
    gemm_dot<<<dim3(BB*DD/64, 1, 1), 256>>>(z, 0, proj_w, 0, proj_b, 0,
                                            mem, 0, DD, DD);
    gemm_dot<<<dim3(BB*DD/64, 1, LL), 256>>>(
        mem, 0,
        ca_w + (size_t)2*DD*DD, (size_t)3*DD*DD,
        ca_b + 2*DD, (size_t)3*DD,
        cav, (size_t)BB*DD, DD, DD);
    gemm_dot<<<dim3(BB*DD/64, 1, LL), 256>>>(
        cav, (size_t)BB*DD,
        ca_ow, (size_t)DD*DD,
        ca_ob, (size_t)DD,
        ca, (size_t)BB*DD, DD, DD);

    const int PGRID = 148;

    for (int l = 0; l < LL; l++) {
        const float* sabl  = sa_b  + (size_t)l*3*DD;
        const float* saobl = sa_ob + (size_t)l*DD;
        size_t o_qkv = O_SAW  + (size_t)l*3*DD*DD;
        size_t o_ow  = O_SAOW + (size_t)l*DD*DD;
        size_t o_ff1 = O_FF1  + (size_t)l*DFF*DD;
        size_t o_ff2 = O_FF2  + (size_t)l*DD*DFF;

        // self-attention
        gemm_hmma<<<PGRID, 256, HSMEM>>>(ahi, alo, whi + o_qkv, wlo + o_qkv,
                                         sabl, nullptr, qhi, qlo,
                                         3*DD, DD, 0, 1, 12, 12*128);
        attn_hmma<<<BB*HH*2, 256, ATT_SMEM>>>(qhi, qlo, fhi, flo);
        gemm_hmma<<<PGRID, 256, HSMEM>>>(fhi, flo, whi + o_ow, wlo + o_ow,
                                         saobl, sub, nullptr, nullptr,
                                         DD, DD, 0, 0, 4, 4*128);
        add_ln2_kernel<<<M_TOK, 128>>>(ahi, alo, sub, ca + (size_t)l*BB*DD,
                                       ln1_s + l*DD, ln1_b + l*DD,
                                       ln2_s + l*DD, ln2_b + l*DD);

        // feed-forward
        gemm_hmma<<<PGRID, 256, HSMEM>>>(ahi, alo, whi + o_ff1, wlo + o_ff1,
                                         ff1_b + l*DFF, nullptr, fhi, flo,
                                         DFF, DD, 1, 1, 16, 16*128);
        gemm_hmma<<<PGRID, 256, HSMEM>>>(fhi, flo, whi + o_ff2, wlo + o_ff2,
                                         ff2_b + l*DD, sub, nullptr, nullptr,
                                         DD, DFF, 0, 0, 4, 4*128);
        add_ln_kernel<<<M_TOK, 128>>>(ahi, alo, sub,
                                      ln3_s + l*DD, ln3_b + l*DD);
    }

    // final classifier
    gemm_hmma<<<128, 256, HSMEM>>>(ahi, alo, whi + O_FC, wlo + O_FC,
                                   fc_b, out, nullptr, nullptr,
                                   VV, DD, 0, 0, 1, 128);
}